// round 8
// baseline (speedup 1.0000x reference)
#include <cuda_runtime.h>
#include <cuda_bf16.h>
#include <cstdint>

// ---------------- problem constants ----------------
#define BATCH    4096
#define N_COL    100
#define N_COND   64
#define TOTAL    6400
#define N_RODT   1600
#define N_EST    160
#define N_FOREST 100
#define N_HID    128
#define N_CLASS  10
#define EPSV     1e-5f
#define SDIM     136

// ---------------- device scratch ----------------
__device__ float g_xT [N_COL * BATCH];
__device__ float g_wT [N_RODT * BATCH];
__device__ float g_Etf[N_RODT * N_HID];
__device__ float g_W1p[N_HID * N_HID];
__device__ float g_wc2[N_HID * 12];
__device__ float g_s1[N_HID], g_d1[N_HID];
__device__ float g_s2[16],    g_d2[16];
__device__ float g_Y  [(size_t)N_FOREST * BATCH * N_CLASS];

__device__ __forceinline__ float to_tf32(float x) {
    uint32_t u;
    asm("cvt.rna.tf32.f32 %0, %1;" : "=r"(u) : "f"(x));
    return __uint_as_float(u);
}
__device__ __forceinline__ void cpasync16(uint32_t dst, const void* src) {
    asm volatile("cp.async.cg.shared.global [%0], [%1], 16;" :: "r"(dst), "l"(src));
}
#define CP_COMMIT asm volatile("cp.async.commit_group;")
#define CP_WAIT0  asm volatile("cp.async.wait_group 0;")

// =====================================================================
__global__ void k0_transpose(const float* __restrict__ x) {
    int i = blockIdx.x * 256 + threadIdx.x;
    int c = i >> 12;
    int b = i & 4095;
    g_xT[i] = x[b * N_COL + c];
}

// =====================================================================
__global__ void k_pre(const float* __restrict__ E, const float* __restrict__ fc1w,
                      const float* __restrict__ ln1w, const float* __restrict__ fc2w,
                      const float* __restrict__ ln2w) {
    int i = blockIdx.x * 256 + threadIdx.x;
    if (i < N_RODT * N_HID) g_Etf[i] = to_tf32(E[i]);
    if (i < N_HID * N_HID) {
        int d = i >> 7;
        g_W1p[i] = to_tf32(fc1w[i] * ln1w[d]);
    }
    if (i < N_HID * 12) {
        int o = i / 12, c = i % 12;
        g_wc2[i] = (c < 10) ? to_tf32(fc2w[o * 10 + c] * ln2w[o]) : 0.f;
    }
}
__global__ void k_pre2(const float* __restrict__ fc1w, const float* __restrict__ fc1b,
                       const float* __restrict__ ln1b, const float* __restrict__ fc2w,
                       const float* __restrict__ fc2b, const float* __restrict__ ln2b) {
    int o = threadIdx.x;
    float s = 0.f, d = 0.f;
    for (int k = 0; k < 128; k++) {
        s += g_W1p[k * 128 + o];
        d += fc1w[k * 128 + o] * ln1b[k];
    }
    g_s1[o] = s;
    g_d1[o] = d + fc1b[o];
    if (o < 10) {
        float s2 = 0.f, d2 = 0.f;
        for (int k = 0; k < 128; k++) {
            s2 += g_wc2[k * 12 + o];
            d2 += ln2b[k] * fc2w[k * 10 + o];
        }
        g_s2[o] = s2;
        g_d2[o] = d2 + fc2b[o];
    } else if (o < 16) {
        g_s2[o] = 0.f; g_d2[o] = 0.f;
    }
}

// =====================================================================
// Kernel 1: condition gen + rODT scoring — 4 b's per thread, occ-capped regs
// =====================================================================
__global__ void __launch_bounds__(256, 4)
k1_rodt(const float* __restrict__ w1, const float* __restrict__ b1,
        const int*   __restrict__ perm,
        const float* __restrict__ gn1w, const float* __restrict__ gn1b,
        const float* __restrict__ c2w,  const float* __restrict__ c2b,
        const float* __restrict__ gn2w, const float* __restrict__ gn2b,
        const float* __restrict__ c3w,  const float* __restrict__ c3b) {
    int g   = blockIdx.x;
    int tid = threadIdx.x;
    __shared__ int   sc[4];
    __shared__ float sw1[4], sb1[4], sg1w[4], sg1b[4];
    __shared__ float sw2[16], sb2[4], sg2w[4], sg2b[4], sw3[4], sb3;
    if (tid < 4) {
        int t = 4 * g + tid;
        int p = perm[t];
        int c = p % N_COL;
        int j = p / N_COL;
        sc [tid] = c;
        sw1[tid] = w1[c * N_COND + j];
        sb1[tid] = b1[c * N_COND + j];
        sg1w[tid] = gn1w[t];  sg1b[tid] = gn1b[t];
        sb2 [tid] = c2b[t];
        sg2w[tid] = gn2w[t];  sg2b[tid] = gn2b[t];
        sw3 [tid] = c3w[g * 4 + tid];
    }
    if (tid < 16) sw2[tid] = c2w[g * 16 + tid];
    if (tid == 31) sb3 = c3b[g];
    __syncthreads();

    const int b = blockIdx.y * 1024 + tid * 4;
    float4 xv[4];
#pragma unroll
    for (int k = 0; k < 4; k++)
        xv[k] = *(const float4*)&g_xT[sc[k] * BATCH + b];

    float out[4];
#pragma unroll
    for (int j = 0; j < 4; j++) {
        float v[4];
#pragma unroll
        for (int k = 0; k < 4; k++) {
            float xval = (&xv[k].x)[j];
            float z = fmaf(xval, sw1[k], sb1[k]);
            v[k] = 1.f / (1.f + __expf(-z));
        }
        float mu = 0.25f * (v[0] + v[1] + v[2] + v[3]);
        float var = 0.f;
#pragma unroll
        for (int k = 0; k < 4; k++) { float d = v[k] - mu; var += d * d; }
        var *= 0.25f;
        float rs = rsqrtf(var + EPSV);
        float n[4];
#pragma unroll
        for (int k = 0; k < 4; k++) n[k] = fmaf((v[k] - mu) * rs, sg1w[k], sg1b[k]);
        float h[4];
#pragma unroll
        for (int o = 0; o < 4; o++) {
            float a = sb2[o];
#pragma unroll
            for (int k = 0; k < 4; k++) a = fmaf(n[k], sw2[k * 4 + o], a);
            h[o] = fmaxf(a, 0.f);
        }
        float mu2 = 0.25f * (h[0] + h[1] + h[2] + h[3]);
        float var2 = 0.f;
#pragma unroll
        for (int k = 0; k < 4; k++) { float d = h[k] - mu2; var2 += d * d; }
        var2 *= 0.25f;
        float rs2 = rsqrtf(var2 + EPSV);
        float wo = sb3;
#pragma unroll
        for (int k = 0; k < 4; k++)
            wo = fmaf(fmaf((h[k] - mu2) * rs2, sg2w[k], sg2b[k]), sw3[k], wo);
        out[j] = wo;
    }
    *(float4*)&g_wT[(size_t)g * BATCH + b] = make_float4(out[0], out[1], out[2], out[3]);
}

// =====================================================================
__device__ __forceinline__ void mma_tf32(float* c, const uint32_t* a, const uint32_t* b) {
    asm volatile("mma.sync.aligned.m16n8k8.row.col.f32.tf32.tf32.f32 "
                 "{%0,%1,%2,%3}, {%4,%5,%6,%7}, {%8,%9}, {%0,%1,%2,%3};"
                 : "+f"(c[0]), "+f"(c[1]), "+f"(c[2]), "+f"(c[3])
                 : "r"(a[0]), "r"(a[1]), "r"(a[2]), "r"(a[3]), "r"(b[0]), "r"(b[1]));
}

template<int KSTEPS>
__device__ __forceinline__ void gemm512(const float* __restrict__ Asm,
                                        const float* __restrict__ Bsm,
                                        int warp, int lane, float acc[2][4][4]) {
    const int M0 = (warp & 3) * 32, N0 = (warp >> 2) * 32;
    const int g = lane >> 2, t = lane & 3;
#pragma unroll
    for (int ks = 0; ks < KSTEPS; ks++) {
        const int k0 = ks * 8;
        const float* ab = Asm + (k0 + t) * SDIM + M0 + g;
        uint32_t a[2][4];
        a[0][0] = __float_as_uint(ab[0]);
        a[0][1] = __float_as_uint(ab[8]);
        a[0][2] = __float_as_uint(ab[4 * SDIM]);
        a[0][3] = __float_as_uint(ab[4 * SDIM + 8]);
        a[1][0] = __float_as_uint(ab[16]);
        a[1][1] = __float_as_uint(ab[24]);
        a[1][2] = __float_as_uint(ab[4 * SDIM + 16]);
        a[1][3] = __float_as_uint(ab[4 * SDIM + 24]);
        const float* bb = Bsm + (k0 + t) * SDIM + N0 + g;
        uint32_t bf[4][2];
#pragma unroll
        for (int nt = 0; nt < 4; nt++) {
            bf[nt][0] = __float_as_uint(bb[nt * 8]);
            bf[nt][1] = __float_as_uint(bb[nt * 8 + 4 * SDIM]);
        }
#pragma unroll
        for (int mt = 0; mt < 2; mt++)
#pragma unroll
            for (int nt = 0; nt < 4; nt++) mma_tf32(acc[mt][nt], a[mt], bf[nt]);
    }
}

// =====================================================================
// k23: fused forest GEMM + MLP; LN stats fused into GEMM epilogues.
// =====================================================================
#define K23_SMEM ((160 * SDIM + 80 * SDIM + 80 * SDIM) * 4)   // 174080
__global__ void __launch_bounds__(512, 1) k23_forest_mlp(const int* __restrict__ swr) {
    extern __shared__ char sh[];
    float* Pf  = (float*)sh;
    float* Wb0 = (float*)(sh + 160 * SDIM * 4);
    float* Wb1 = (float*)(sh + (160 + 80) * SDIM * 4);

    __shared__ int   s_idx[160];
    __shared__ float s_invS[128];
    __shared__ float s_redA[512], s_redB[512];
    __shared__ float s_mu[128], s_rs[128];
    __shared__ float s_s1[128], s_d1[128];
    __shared__ __align__(16) float s_wc2[128 * 12];
    __shared__ float s_s2[16], s_d2[16];

    const int tid = threadIdx.x, lane = tid & 31, warp = tid >> 5;
    const int f = blockIdx.y;
    const int b0 = blockIdx.x * 128;

    if (tid < 160) s_idx[tid] = swr[f * N_EST + tid];
    __syncthreads();

    // ---- issue E half0 via cp.async ----
    {
        uint32_t wb0 = (uint32_t)__cvta_generic_to_shared(Wb0);
#pragma unroll
        for (int i = tid; i < 80 * 32; i += 512) {
            int e = i >> 5, q = i & 31;
            cpasync16(wb0 + (e * SDIM + q * 4) * 4, g_Etf + (size_t)s_idx[e] * N_HID + q * 4);
        }
        CP_COMMIT;
    }

    // ---- stage P = tf32(exp(w)); load params ----
#pragma unroll
    for (int i = tid; i < 160 * 32; i += 512) {
        int e = i >> 5, b4 = i & 31;
        float4 v = *(const float4*)(g_wT + (size_t)s_idx[e] * BATCH + b0 + b4 * 4);
        float* dst = Pf + e * SDIM + b4 * 4;
        dst[0] = to_tf32(__expf(v.x));
        dst[1] = to_tf32(__expf(v.y));
        dst[2] = to_tf32(__expf(v.z));
        dst[3] = to_tf32(__expf(v.w));
    }
    if (tid < 128) { s_s1[tid] = g_s1[tid]; s_d1[tid] = g_d1[tid]; }
    for (int i = tid; i < 1536; i += 512) s_wc2[i] = g_wc2[i];
    if (tid < 16) { s_s2[tid] = g_s2[tid]; s_d2[tid] = g_d2[tid]; }
    CP_WAIT0;
    __syncthreads();

    // ---- issue E half1 -> Wb1 ----
    {
        uint32_t wb1 = (uint32_t)__cvta_generic_to_shared(Wb1);
#pragma unroll
        for (int i = tid; i < 80 * 32; i += 512) {
            int e = i >> 5, q = i & 31;
            cpasync16(wb1 + (e * SDIM + q * 4) * 4, g_Etf + (size_t)s_idx[80 + e] * N_HID + q * 4);
        }
        CP_COMMIT;
    }

    // ---- invS: column sums of P (160 rows) ----
    {
        const int col = tid & 127, q = tid >> 7;
        float s = 0.f;
        for (int r = 0; r < 40; r++) s += Pf[(q * 40 + r) * SDIM + col];
        s_redA[q * 128 + col] = s;
    }
    __syncthreads();
    if (tid < 128)
        s_invS[tid] = 1.f / (s_redA[tid] + s_redA[128 + tid] + s_redA[256 + tid] + s_redA[384 + tid]);

    // ---- GEMM A: K=160, two halves ----
    float acc[2][4][4];
#pragma unroll
    for (int mt = 0; mt < 2; mt++)
#pragma unroll
        for (int nt = 0; nt < 4; nt++)
#pragma unroll
            for (int r = 0; r < 4; r++) acc[mt][nt][r] = 0.f;
    gemm512<10>(Wb0, Pf, warp, lane, acc);
    CP_WAIT0;
    __syncthreads();
    // prefetch W1' half0 into Wb0
    {
        uint32_t wb0 = (uint32_t)__cvta_generic_to_shared(Wb0);
#pragma unroll
        for (int i = tid; i < 64 * 32; i += 512) {
            int k = i >> 5, q = i & 31;
            cpasync16(wb0 + (k * SDIM + q * 4) * 4, g_W1p + k * N_HID + q * 4);
        }
        CP_COMMIT;
    }
    gemm512<10>(Wb1, Pf + 80 * SDIM, warp, lane, acc);
    __syncthreads();   // all P reads done before overwrite
    // prefetch W1' half1 into Wb1
    {
        uint32_t wb1 = (uint32_t)__cvta_generic_to_shared(Wb1);
#pragma unroll
        for (int i = tid; i < 64 * 32; i += 512) {
            int k = i >> 5, q = i & 31;
            cpasync16(wb1 + (k * SDIM + q * 4) * 4, g_W1p + (64 + k) * N_HID + q * 4);
        }
        CP_COMMIT;
    }

    // epilogue A: C~ -> Pf rows 0..127, with fused stats1 partials
    {
        const int wm = warp & 3;
        const int M0 = wm * 32, N0 = (warp >> 2) * 32;
        const int g = lane >> 2, q2 = (lane & 3) * 2;
#pragma unroll
        for (int nt = 0; nt < 4; nt++) {
            int col = N0 + nt * 8 + q2;
            float i0 = s_invS[col], i1 = s_invS[col + 1];
            float s0 = 0.f, s1v = 0.f, qq0 = 0.f, qq1 = 0.f;
#pragma unroll
            for (int mt = 0; mt < 2; mt++) {
                int row = M0 + mt * 16 + g;
                float v00 = to_tf32(acc[mt][nt][0] * i0);
                float v01 = to_tf32(acc[mt][nt][1] * i1);
                float v10 = to_tf32(acc[mt][nt][2] * i0);
                float v11 = to_tf32(acc[mt][nt][3] * i1);
                Pf[row * SDIM + col]           = v00;
                Pf[row * SDIM + col + 1]       = v01;
                Pf[(row + 8) * SDIM + col]     = v10;
                Pf[(row + 8) * SDIM + col + 1] = v11;
                s0 += v00 + v10;  s1v += v01 + v11;
                qq0 = fmaf(v00, v00, fmaf(v10, v10, qq0));
                qq1 = fmaf(v01, v01, fmaf(v11, v11, qq1));
            }
#pragma unroll
            for (int off = 4; off < 32; off <<= 1) {
                s0  += __shfl_xor_sync(0xffffffff, s0,  off);
                s1v += __shfl_xor_sync(0xffffffff, s1v, off);
                qq0 += __shfl_xor_sync(0xffffffff, qq0, off);
                qq1 += __shfl_xor_sync(0xffffffff, qq1, off);
            }
            if (lane < 4) {
                s_redA[wm * 128 + col]     = s0;
                s_redA[wm * 128 + col + 1] = s1v;
                s_redB[wm * 128 + col]     = qq0;
                s_redB[wm * 128 + col + 1] = qq1;
            }
        }
    }
    CP_WAIT0;
    __syncthreads();

    // stats1 finalize (no smem pass)
    if (tid < 128) {
        float s  = s_redA[tid] + s_redA[128 + tid] + s_redA[256 + tid] + s_redA[384 + tid];
        float s2 = s_redB[tid] + s_redB[128 + tid] + s_redB[256 + tid] + s_redB[384 + tid];
        float mu = s * (1.f / 128.f);
        float var = fmaxf(s2 * (1.f / 128.f) - mu * mu, 0.f);
        s_mu[tid] = mu;
        s_rs[tid] = rsqrtf(var + EPSV);
    }

    // ---- GEMM B: K=128, two halves (no barrier needed between) ----
#pragma unroll
    for (int mt = 0; mt < 2; mt++)
#pragma unroll
        for (int nt = 0; nt < 4; nt++)
#pragma unroll
            for (int r = 0; r < 4; r++) acc[mt][nt][r] = 0.f;
    gemm512<8>(Wb0, Pf, warp, lane, acc);
    gemm512<8>(Wb1, Pf + 64 * SDIM, warp, lane, acc);
    __syncthreads();   // all C~ reads done before overwrite; also orders s_mu/s_rs

    // epilogue B: H -> Pf rows 0..127, with fused stats2 partials
    {
        const int wm = warp & 3;
        const int M0 = wm * 32, N0 = (warp >> 2) * 32;
        const int g = lane >> 2, q2 = (lane & 3) * 2;
#pragma unroll
        for (int nt = 0; nt < 4; nt++) {
            int col = N0 + nt * 8 + q2;
            float mu0 = s_mu[col], rs0 = s_rs[col];
            float mu1 = s_mu[col + 1], rs1 = s_rs[col + 1];
            float s0 = 0.f, s1v = 0.f, qq0 = 0.f, qq1 = 0.f;
#pragma unroll
            for (int mt = 0; mt < 2; mt++) {
                int row = M0 + mt * 16 + g;
                float s1a = s_s1[row], d1a = s_d1[row];
                float s1b = s_s1[row + 8], d1b = s_d1[row + 8];
                float v00 = fmaxf(fmaf(rs0, acc[mt][nt][0] - mu0 * s1a, d1a), 0.f);
                float v01 = fmaxf(fmaf(rs1, acc[mt][nt][1] - mu1 * s1a, d1a), 0.f);
                float v10 = fmaxf(fmaf(rs0, acc[mt][nt][2] - mu0 * s1b, d1b), 0.f);
                float v11 = fmaxf(fmaf(rs1, acc[mt][nt][3] - mu1 * s1b, d1b), 0.f);
                Pf[row * SDIM + col]           = v00;
                Pf[row * SDIM + col + 1]       = v01;
                Pf[(row + 8) * SDIM + col]     = v10;
                Pf[(row + 8) * SDIM + col + 1] = v11;
                s0 += v00 + v10;  s1v += v01 + v11;
                qq0 = fmaf(v00, v00, fmaf(v10, v10, qq0));
                qq1 = fmaf(v01, v01, fmaf(v11, v11, qq1));
            }
#pragma unroll
            for (int off = 4; off < 32; off <<= 1) {
                s0  += __shfl_xor_sync(0xffffffff, s0,  off);
                s1v += __shfl_xor_sync(0xffffffff, s1v, off);
                qq0 += __shfl_xor_sync(0xffffffff, qq0, off);
                qq1 += __shfl_xor_sync(0xffffffff, qq1, off);
            }
            if (lane < 4) {
                s_redA[wm * 128 + col]     = s0;
                s_redA[wm * 128 + col + 1] = s1v;
                s_redB[wm * 128 + col]     = qq0;
                s_redB[wm * 128 + col + 1] = qq1;
            }
        }
    }
    __syncthreads();

    // stats2 finalize
    if (tid < 128) {
        float s  = s_redA[tid] + s_redA[128 + tid] + s_redA[256 + tid] + s_redA[384 + tid];
        float s2 = s_redB[tid] + s_redB[128 + tid] + s_redB[256 + tid] + s_redB[384 + tid];
        float mu = s * (1.f / 128.f);
        float var = fmaxf(s2 * (1.f / 128.f) - mu * mu, 0.f);
        s_mu[tid] = mu;
        s_rs[tid] = rsqrtf(var + EPSV);
    }
    __syncthreads();

    // ---- fc2 (fused LN2) ----
    {
        const int b = tid >> 2, q = tid & 3;
        float a10[10];
#pragma unroll
        for (int c = 0; c < 10; c++) a10[c] = 0.f;
#pragma unroll 4
        for (int i = 0; i < 32; i++) {
            int o = 4 * i + q;
            float h = Pf[o * SDIM + b];
            const float* wr = s_wc2 + o * 12;
            float4 w0 = *(const float4*)wr;
            float4 w1 = *(const float4*)(wr + 4);
            float2 w2 = *(const float2*)(wr + 8);
            a10[0] = fmaf(h, w0.x, a10[0]);
            a10[1] = fmaf(h, w0.y, a10[1]);
            a10[2] = fmaf(h, w0.z, a10[2]);
            a10[3] = fmaf(h, w0.w, a10[3]);
            a10[4] = fmaf(h, w1.x, a10[4]);
            a10[5] = fmaf(h, w1.y, a10[5]);
            a10[6] = fmaf(h, w1.z, a10[6]);
            a10[7] = fmaf(h, w1.w, a10[7]);
            a10[8] = fmaf(h, w2.x, a10[8]);
            a10[9] = fmaf(h, w2.y, a10[9]);
        }
#pragma unroll
        for (int c = 0; c < 10; c++) {
            a10[c] += __shfl_xor_sync(0xffffffff, a10[c], 1);
            a10[c] += __shfl_xor_sync(0xffffffff, a10[c], 2);
        }
        if (q < 2) {
            const int c0 = q * 5;
            float mu2 = s_mu[b], rs2 = s_rs[b];
            size_t R = ((size_t)f * BATCH + b0 + b) * N_CLASS;
#pragma unroll
            for (int j = 0; j < 5; j++) {
                int c = c0 + j;
                g_Y[R + c] = fmaf(rs2, a10[c] - mu2 * s_s2[c], s_d2[c]);
            }
        }
    }
}

// =====================================================================
__global__ void k4_reduce(float* __restrict__ out) {
    int i = blockIdx.x * 256 + threadIdx.x;
    if (i < BATCH * N_CLASS / 4) {
        float4 s = make_float4(0.f, 0.f, 0.f, 0.f);
        for (int f = 0; f < N_FOREST; f++) {
            float4 v = *((const float4*)(g_Y + (size_t)f * (BATCH * N_CLASS)) + i);
            s.x += v.x; s.y += v.y; s.z += v.z; s.w += v.w;
        }
        out[i * 4 + 0] = s.x * (1.f / N_FOREST);
        out[i * 4 + 1] = s.y * (1.f / N_FOREST);
        out[i * 4 + 2] = s.z * (1.f / N_FOREST);
        out[i * 4 + 3] = s.w * (1.f / N_FOREST);
    }
}

// =====================================================================
extern "C" void kernel_launch(void* const* d_in, const int* in_sizes, int n_in,
                              void* d_out, int out_size) {
    const float* x     = (const float*)d_in[0];
    const float* w1    = (const float*)d_in[1];
    const float* b1    = (const float*)d_in[2];
    const int*   perm  = (const int*)  d_in[3];
    const float* gn1w  = (const float*)d_in[4];
    const float* gn1b  = (const float*)d_in[5];
    const float* c2w   = (const float*)d_in[6];
    const float* c2b   = (const float*)d_in[7];
    const float* gn2w  = (const float*)d_in[8];
    const float* gn2b  = (const float*)d_in[9];
    const float* c3w   = (const float*)d_in[10];
    const float* c3b   = (const float*)d_in[11];
    const int*   swr   = (const int*)  d_in[12];
    const float* E     = (const float*)d_in[13];
    const float* ln1w  = (const float*)d_in[14];
    const float* ln1b  = (const float*)d_in[15];
    const float* fc1w  = (const float*)d_in[16];
    const float* fc1b  = (const float*)d_in[17];
    const float* ln2w  = (const float*)d_in[18];
    const float* ln2b  = (const float*)d_in[19];
    const float* fc2w  = (const float*)d_in[20];
    const float* fc2b  = (const float*)d_in[21];
    float* out = (float*)d_out;

    cudaFuncSetAttribute(k23_forest_mlp, cudaFuncAttributeMaxDynamicSharedMemorySize, K23_SMEM);

    k0_transpose<<<(N_COL * BATCH) / 256, 256>>>(x);
    k_pre<<<(N_RODT * N_HID + 255) / 256, 256>>>(E, fc1w, ln1w, fc2w, ln2w);
    k_pre2<<<1, 128>>>(fc1w, fc1b, ln1b, fc2w, fc2b, ln2b);
    k1_rodt<<<dim3(N_RODT, BATCH / 1024), 256>>>(w1, b1, perm, gn1w, gn1b,
                                                 c2w, c2b, gn2w, gn2b, c3w, c3b);
    k23_forest_mlp<<<dim3(BATCH / 128, N_FOREST), 512, K23_SMEM>>>(swr);
    k4_reduce<<<(BATCH * N_CLASS / 4 + 255) / 256, 256>>>(out);
}

// round 9
// speedup vs baseline: 1.0047x; 1.0047x over previous
#include <cuda_runtime.h>
#include <cuda_bf16.h>
#include <cstdint>

// ---------------- problem constants ----------------
#define BATCH    4096
#define N_COL    100
#define N_COND   64
#define TOTAL    6400
#define N_RODT   1600
#define N_EST    160
#define N_FOREST 100
#define N_HID    128
#define N_CLASS  10
#define EPSV     1e-5f
#define SDIM     136

// ---------------- device scratch ----------------
__device__ float g_xT [N_COL * BATCH];
__device__ float g_wT [N_RODT * BATCH];
__device__ float g_Etf[N_RODT * N_HID];     // tf32(E), ROW-PERMUTED to frag order
__device__ float g_W1p[N_HID * N_HID];      // tf32(fc1w*ln1w), ROW-PERMUTED
__device__ float g_wc2[N_HID * 12];
__device__ float g_s1[N_HID], g_d1[N_HID];
__device__ float g_s2[16],    g_d2[16];
__device__ float g_Y  [(size_t)N_FOREST * BATCH * N_CLASS];

__device__ __forceinline__ float to_tf32(float x) {
    uint32_t u;
    asm("cvt.rna.tf32.f32 %0, %1;" : "=r"(u) : "f"(x));
    return __uint_as_float(u);
}
__device__ __forceinline__ void cpasync16(uint32_t dst, const void* src) {
    asm volatile("cp.async.cg.shared.global [%0], [%1], 16;" :: "r"(dst), "l"(src));
}
#define CP_COMMIT asm volatile("cp.async.commit_group;")
#define CP_WAIT0  asm volatile("cp.async.wait_group 0;")

// frag-order within-row permutation: output col p <- source col
__device__ __forceinline__ int frag_src_col(int p) {
    int j = p >> 2, v = p & 3;                 // float4 index, component
    return ((j >> 3) << 5) + (j & 7) + v * 8;  // wm*32 + g + v*8
}

// =====================================================================
__global__ void k0_transpose(const float* __restrict__ x) {
    int i = blockIdx.x * 256 + threadIdx.x;
    int c = i >> 12;
    int b = i & 4095;
    g_xT[i] = x[b * N_COL + c];
}

// =====================================================================
__global__ void k_pre(const float* __restrict__ E, const float* __restrict__ fc1w,
                      const float* __restrict__ ln1w, const float* __restrict__ fc2w,
                      const float* __restrict__ ln2w) {
    int i = blockIdx.x * 256 + threadIdx.x;
    if (i < N_RODT * N_HID) {
        int e = i >> 7, p = i & 127;
        g_Etf[i] = to_tf32(E[e * N_HID + frag_src_col(p)]);
    }
    if (i < N_HID * N_HID) {
        int d = i >> 7, p = i & 127;
        int s = frag_src_col(p);
        g_W1p[i] = to_tf32(fc1w[d * N_HID + s] * ln1w[d]);
    }
    if (i < N_HID * 12) {
        int o = i / 12, c = i % 12;
        g_wc2[i] = (c < 10) ? to_tf32(fc2w[o * 10 + c] * ln2w[o]) : 0.f;
    }
}
__global__ void k_pre2(const float* __restrict__ fc1w, const float* __restrict__ fc1b,
                       const float* __restrict__ ln1b, const float* __restrict__ fc2w,
                       const float* __restrict__ fc2b, const float* __restrict__ ln2b) {
    int o = threadIdx.x;
    float s = 0.f, d = 0.f;
    for (int k = 0; k < 128; k++) {
        s += to_tf32(fc1w[k * 128 + o] * ln1b[k] * 0.f + fc1w[k * 128 + o] * __ldg(&ln2b[0]) * 0.f
                     + fc1w[k * 128 + o]);   // placeholder avoided below
        d += 0.f;
    }
    // recompute properly (the loop above is dead; kept simple below)
    s = 0.f; d = 0.f;
    extern __shared__ float dummy[];
    for (int k = 0; k < 128; k++) {
        float w1l;
        asm("cvt.rna.tf32.f32 %0, %1;" : "=f"(w1l) : "f"(fc1w[k * 128 + o] * __ldg(&((const float*)ln1b)[k] ) * 0.f + fc1w[k*128+o] ));
        (void)w1l;
    }
    // --- clean implementation ---
    float s1v = 0.f, d1v = 0.f;
    for (int k = 0; k < 128; k++) {
        float w = fc1w[k * 128 + o];
        uint32_t u;
        float lw;
        // tf32(fc1w*ln1w) must match k_pre's value: need ln1w... passed via d_in? Not here.
        // NOTE: s1 uses tf32(fc1w*ln1w); ln1w not passed -> use g_W1p inverse-permuted read instead.
        lw = g_W1p[k * 128 + 0];
        (void)lw; (void)u; (void)w;
    }
    // read permuted g_W1p: natural col o lives at permuted position p where frag_src_col(p)=o.
    // inverse: o = wm*32+g+v*8 with g=o&7? o%32: g = o&7, v = (o>>3)&3, wm = o>>5; p = (wm*8+g)*4+v.
    {
        int g = o & 7, v = (o >> 3) & 3, wm = o >> 5;
        int p = ((wm << 3) + g) * 4 + v;
        float ssum = 0.f, dsum = 0.f;
        for (int k = 0; k < 128; k++) {
            ssum += g_W1p[k * 128 + p];
            dsum += fc1w[k * 128 + o] * ln1b[k];
        }
        g_s1[o] = ssum;
        g_d1[o] = dsum + fc1b[o];
    }
    if (o < 10) {
        float s2 = 0.f, d2 = 0.f;
        for (int k = 0; k < 128; k++) {
            s2 += g_wc2[k * 12 + o];
            d2 += ln2b[k] * fc2w[k * 10 + o];
        }
        g_s2[o] = s2;
        g_d2[o] = d2 + fc2b[o];
    } else if (o < 16) {
        g_s2[o] = 0.f; g_d2[o] = 0.f;
    }
}

// =====================================================================
// Kernel 1: condition gen + rODT scoring — 4 b's per thread
// =====================================================================
__global__ void __launch_bounds__(256, 4)
k1_rodt(const float* __restrict__ w1, const float* __restrict__ b1,
        const int*   __restrict__ perm,
        const float* __restrict__ gn1w, const float* __restrict__ gn1b,
        const float* __restrict__ c2w,  const float* __restrict__ c2b,
        const float* __restrict__ gn2w, const float* __restrict__ gn2b,
        const float* __restrict__ c3w,  const float* __restrict__ c3b) {
    int g   = blockIdx.x;
    int tid = threadIdx.x;
    __shared__ int   sc[4];
    __shared__ float sw1[4], sb1[4], sg1w[4], sg1b[4];
    __shared__ float sw2[16], sb2[4], sg2w[4], sg2b[4], sw3[4], sb3;
    if (tid < 4) {
        int t = 4 * g + tid;
        int p = perm[t];
        int c = p % N_COL;
        int j = p / N_COL;
        sc [tid] = c;
        sw1[tid] = w1[c * N_COND + j];
        sb1[tid] = b1[c * N_COND + j];
        sg1w[tid] = gn1w[t];  sg1b[tid] = gn1b[t];
        sb2 [tid] = c2b[t];
        sg2w[tid] = gn2w[t];  sg2b[tid] = gn2b[t];
        sw3 [tid] = c3w[g * 4 + tid];
    }
    if (tid < 16) sw2[tid] = c2w[g * 16 + tid];
    if (tid == 31) sb3 = c3b[g];
    __syncthreads();

    const int b = blockIdx.y * 1024 + tid * 4;
    float4 xv[4];
#pragma unroll
    for (int k = 0; k < 4; k++)
        xv[k] = *(const float4*)&g_xT[sc[k] * BATCH + b];

    float out[4];
#pragma unroll
    for (int j = 0; j < 4; j++) {
        float v[4];
#pragma unroll
        for (int k = 0; k < 4; k++) {
            float xval = (&xv[k].x)[j];
            float z = fmaf(xval, sw1[k], sb1[k]);
            v[k] = 1.f / (1.f + __expf(-z));
        }
        float mu = 0.25f * (v[0] + v[1] + v[2] + v[3]);
        float var = 0.f;
#pragma unroll
        for (int k = 0; k < 4; k++) { float d = v[k] - mu; var += d * d; }
        var *= 0.25f;
        float rs = rsqrtf(var + EPSV);
        float n[4];
#pragma unroll
        for (int k = 0; k < 4; k++) n[k] = fmaf((v[k] - mu) * rs, sg1w[k], sg1b[k]);
        float h[4];
#pragma unroll
        for (int o = 0; o < 4; o++) {
            float a = sb2[o];
#pragma unroll
            for (int k = 0; k < 4; k++) a = fmaf(n[k], sw2[k * 4 + o], a);
            h[o] = fmaxf(a, 0.f);
        }
        float mu2 = 0.25f * (h[0] + h[1] + h[2] + h[3]);
        float var2 = 0.f;
#pragma unroll
        for (int k = 0; k < 4; k++) { float d = h[k] - mu2; var2 += d * d; }
        var2 *= 0.25f;
        float rs2 = rsqrtf(var2 + EPSV);
        float wo = sb3;
#pragma unroll
        for (int k = 0; k < 4; k++)
            wo = fmaf(fmaf((h[k] - mu2) * rs2, sg2w[k], sg2b[k]), sw3[k], wo);
        out[j] = wo;
    }
    *(float4*)&g_wT[(size_t)g * BATCH + b] = make_float4(out[0], out[1], out[2], out[3]);
}

// =====================================================================
__device__ __forceinline__ void mma_tf32(float* c, const uint32_t* a, const uint32_t* b) {
    asm volatile("mma.sync.aligned.m16n8k8.row.col.f32.tf32.tf32.f32 "
                 "{%0,%1,%2,%3}, {%4,%5,%6,%7}, {%8,%9}, {%0,%1,%2,%3};"
                 : "+f"(c[0]), "+f"(c[1]), "+f"(c[2]), "+f"(c[3])
                 : "r"(a[0]), "r"(a[1]), "r"(a[2]), "r"(a[3]), "r"(b[0]), "r"(b[1]));
}

// A operand in smem is row-frag-permuted: A-frag = 2x LDS.128.
template<int KSTEPS>
__device__ __forceinline__ void gemm512(const float* __restrict__ Asm,
                                        const float* __restrict__ Bsm,
                                        int warp, int lane, float acc[2][4][4]) {
    const int wm = warp & 3, N0 = (warp >> 2) * 32;
    const int g = lane >> 2, t = lane & 3;
    const int fj = wm * 8 + g;                 // float4 index within permuted row
#pragma unroll
    for (int ks = 0; ks < KSTEPS; ks++) {
        const int k0 = ks * 8;
        float4 f0 = *(const float4*)(Asm + (k0 + t) * SDIM + fj * 4);
        float4 f1 = *(const float4*)(Asm + (k0 + t + 4) * SDIM + fj * 4);
        uint32_t a[2][4];
        a[0][0] = __float_as_uint(f0.x);
        a[0][1] = __float_as_uint(f0.y);
        a[0][2] = __float_as_uint(f1.x);
        a[0][3] = __float_as_uint(f1.y);
        a[1][0] = __float_as_uint(f0.z);
        a[1][1] = __float_as_uint(f0.w);
        a[1][2] = __float_as_uint(f1.z);
        a[1][3] = __float_as_uint(f1.w);
        const float* bb = Bsm + (k0 + t) * SDIM + N0 + g;
        uint32_t bf[4][2];
#pragma unroll
        for (int nt = 0; nt < 4; nt++) {
            bf[nt][0] = __float_as_uint(bb[nt * 8]);
            bf[nt][1] = __float_as_uint(bb[nt * 8 + 4 * SDIM]);
        }
#pragma unroll
        for (int mt = 0; mt < 2; mt++)
#pragma unroll
            for (int nt = 0; nt < 4; nt++) mma_tf32(acc[mt][nt], a[mt], bf[nt]);
    }
}

// =====================================================================
// k23: fused forest GEMM + MLP; frag-permuted A operands; invS fused into stage-P.
// =====================================================================
#define K23_SMEM ((160 * SDIM + 80 * SDIM + 80 * SDIM) * 4)   // 174080
__global__ void __launch_bounds__(512, 1) k23_forest_mlp(const int* __restrict__ swr) {
    extern __shared__ char sh[];
    float* Pf  = (float*)sh;
    float* Wb0 = (float*)(sh + 160 * SDIM * 4);
    float* Wb1 = (float*)(sh + (160 + 80) * SDIM * 4);

    __shared__ int   s_idx[160];
    __shared__ float s_invS[128];
    __shared__ float s_part[16 * 128];
    __shared__ float s_redA[512], s_redB[512];
    __shared__ float s_mu[128], s_rs[128];
    __shared__ float s_s1[128], s_d1[128];
    __shared__ __align__(16) float s_wc2[128 * 12];
    __shared__ float s_s2[16], s_d2[16];

    const int tid = threadIdx.x, lane = tid & 31, warp = tid >> 5;
    const int f = blockIdx.y;
    const int b0 = blockIdx.x * 128;

    if (tid < 160) s_idx[tid] = swr[f * N_EST + tid];
    __syncthreads();

    // ---- issue E half0 via cp.async (rows are frag-permuted, copy is layout-agnostic) ----
    {
        uint32_t wb0 = (uint32_t)__cvta_generic_to_shared(Wb0);
#pragma unroll
        for (int i = tid; i < 80 * 32; i += 512) {
            int e = i >> 5, q = i & 31;
            cpasync16(wb0 + (e * SDIM + q * 4) * 4, g_Etf + (size_t)s_idx[e] * N_HID + q * 4);
        }
        CP_COMMIT;
    }

    // ---- stage P = tf32(exp(w)) with fused invS partials ----
    {
        float p0 = 0.f, p1 = 0.f, p2 = 0.f, p3 = 0.f;
        const int b4 = tid & 31;
#pragma unroll
        for (int j = 0; j < 10; j++) {
            int e = (tid >> 5) + 16 * j;
            float4 v = *(const float4*)(g_wT + (size_t)s_idx[e] * BATCH + b0 + b4 * 4);
            float* dst = Pf + e * SDIM + b4 * 4;
            float e0 = to_tf32(__expf(v.x));
            float e1 = to_tf32(__expf(v.y));
            float e2 = to_tf32(__expf(v.z));
            float e3 = to_tf32(__expf(v.w));
            dst[0] = e0; dst[1] = e1; dst[2] = e2; dst[3] = e3;
            p0 += e0; p1 += e1; p2 += e2; p3 += e3;
        }
        float* pp = s_part + warp * 128 + b4 * 4;
        pp[0] = p0; pp[1] = p1; pp[2] = p2; pp[3] = p3;
    }
    if (tid < 128) { s_s1[tid] = g_s1[tid]; s_d1[tid] = g_d1[tid]; }
    for (int i = tid; i < 1536; i += 512) s_wc2[i] = g_wc2[i];
    if (tid < 16) { s_s2[tid] = g_s2[tid]; s_d2[tid] = g_d2[tid]; }
    CP_WAIT0;
    __syncthreads();

    // ---- issue E half1 -> Wb1 ----
    {
        uint32_t wb1 = (uint32_t)__cvta_generic_to_shared(Wb1);
#pragma unroll
        for (int i = tid; i < 80 * 32; i += 512) {
            int e = i >> 5, q = i & 31;
            cpasync16(wb1 + (e * SDIM + q * 4) * 4, g_Etf + (size_t)s_idx[80 + e] * N_HID + q * 4);
        }
        CP_COMMIT;
    }

    // ---- invS finalize from partials ----
    if (tid < 128) {
        float s = 0.f;
#pragma unroll
        for (int w = 0; w < 16; w++) s += s_part[w * 128 + tid];
        s_invS[tid] = 1.f / s;
    }

    // ---- GEMM A: K=160, two halves ----
    float acc[2][4][4];
#pragma unroll
    for (int mt = 0; mt < 2; mt++)
#pragma unroll
        for (int nt = 0; nt < 4; nt++)
#pragma unroll
            for (int r = 0; r < 4; r++) acc[mt][nt][r] = 0.f;
    gemm512<10>(Wb0, Pf, warp, lane, acc);
    CP_WAIT0;
    __syncthreads();
    // prefetch W1' half0 into Wb0
    {
        uint32_t wb0 = (uint32_t)__cvta_generic_to_shared(Wb0);
#pragma unroll
        for (int i = tid; i < 64 * 32; i += 512) {
            int k = i >> 5, q = i & 31;
            cpasync16(wb0 + (k * SDIM + q * 4) * 4, g_W1p + k * N_HID + q * 4);
        }
        CP_COMMIT;
    }
    gemm512<10>(Wb1, Pf + 80 * SDIM, warp, lane, acc);
    __syncthreads();   // all P reads done before overwrite
    // prefetch W1' half1 into Wb1
    {
        uint32_t wb1 = (uint32_t)__cvta_generic_to_shared(Wb1);
#pragma unroll
        for (int i = tid; i < 64 * 32; i += 512) {
            int k = i >> 5, q = i & 31;
            cpasync16(wb1 + (k * SDIM + q * 4) * 4, g_W1p + (64 + k) * N_HID + q * 4);
        }
        CP_COMMIT;
    }
    // epilogue A: C~ = tf32(acc * invS) -> Pf rows 0..127
    {
        const int M0 = (warp & 3) * 32, N0 = (warp >> 2) * 32;
        const int g = lane >> 2, q2 = (lane & 3) * 2;
#pragma unroll
        for (int mt = 0; mt < 2; mt++)
#pragma unroll
            for (int nt = 0; nt < 4; nt++) {
                int row = M0 + mt * 16 + g, col = N0 + nt * 8 + q2;
                float i0 = s_invS[col], i1 = s_invS[col + 1];
                Pf[row * SDIM + col]           = to_tf32(acc[mt][nt][0] * i0);
                Pf[row * SDIM + col + 1]       = to_tf32(acc[mt][nt][1] * i1);
                Pf[(row + 8) * SDIM + col]     = to_tf32(acc[mt][nt][2] * i0);
                Pf[(row + 8) * SDIM + col + 1] = to_tf32(acc[mt][nt][3] * i1);
            }
    }
    CP_WAIT0;
    __syncthreads();

    // ---- stats1: per-column mean/rstd of C~ (R7-style pass) ----
    {
        const int col = tid & 127, q = tid >> 7;
        float s = 0.f, s2 = 0.f;
        for (int r = 0; r < 32; r++) {
            float v = Pf[(q * 32 + r) * SDIM + col];
            s += v; s2 += v * v;
        }
        s_redA[q * 128 + col] = s;
        s_redB[q * 128 + col] = s2;
    }
    __syncthreads();
    if (tid < 128) {
        float s  = s_redA[tid] + s_redA[128 + tid] + s_redA[256 + tid] + s_redA[384 + tid];
        float s2 = s_redB[tid] + s_redB[128 + tid] + s_redB[256 + tid] + s_redB[384 + tid];
        float mu = s * (1.f / 128.f);
        float var = fmaxf(s2 * (1.f / 128.f) - mu * mu, 0.f);
        s_mu[tid] = mu;
        s_rs[tid] = rsqrtf(var + EPSV);
    }
    __syncthreads();

    // ---- GEMM B: K=128, two halves ----
#pragma unroll
    for (int mt = 0; mt < 2; mt++)
#pragma unroll
        for (int nt = 0; nt < 4; nt++)
#pragma unroll
            for (int r = 0; r < 4; r++) acc[mt][nt][r] = 0.f;
    gemm512<8>(Wb0, Pf, warp, lane, acc);
    gemm512<8>(Wb1, Pf + 64 * SDIM, warp, lane, acc);
    __syncthreads();   // all C~ reads done before overwrite

    // epilogue B: H = relu(rs*(G - mu*s1) + d1) -> Pf rows 0..127
    {
        const int M0 = (warp & 3) * 32, N0 = (warp >> 2) * 32;
        const int g = lane >> 2, q2 = (lane & 3) * 2;
#pragma unroll
        for (int mt = 0; mt < 2; mt++)
#pragma unroll
            for (int nt = 0; nt < 4; nt++) {
                int row = M0 + mt * 16 + g, col = N0 + nt * 8 + q2;
                float s1a = s_s1[row], d1a = s_d1[row];
                float s1b = s_s1[row + 8], d1b = s_d1[row + 8];
                float mu0 = s_mu[col], rs0 = s_rs[col];
                float mu1 = s_mu[col + 1], rs1 = s_rs[col + 1];
                Pf[row * SDIM + col]           = fmaxf(fmaf(rs0, acc[mt][nt][0] - mu0 * s1a, d1a), 0.f);
                Pf[row * SDIM + col + 1]       = fmaxf(fmaf(rs1, acc[mt][nt][1] - mu1 * s1a, d1a), 0.f);
                Pf[(row + 8) * SDIM + col]     = fmaxf(fmaf(rs0, acc[mt][nt][2] - mu0 * s1b, d1b), 0.f);
                Pf[(row + 8) * SDIM + col + 1] = fmaxf(fmaf(rs1, acc[mt][nt][3] - mu1 * s1b, d1b), 0.f);
            }
    }
    __syncthreads();

    // ---- stats2 ----
    {
        const int col = tid & 127, q = tid >> 7;
        float s = 0.f, s2 = 0.f;
        for (int r = 0; r < 32; r++) {
            float v = Pf[(q * 32 + r) * SDIM + col];
            s += v; s2 += v * v;
        }
        s_redA[q * 128 + col] = s;
        s_redB[q * 128 + col] = s2;
    }
    __syncthreads();
    if (tid < 128) {
        float s  = s_redA[tid] + s_redA[128 + tid] + s_redA[256 + tid] + s_redA[384 + tid];
        float s2 = s_redB[tid] + s_redB[128 + tid] + s_redB[256 + tid] + s_redB[384 + tid];
        float mu = s * (1.f / 128.f);
        float var = fmaxf(s2 * (1.f / 128.f) - mu * mu, 0.f);
        s_mu[tid] = mu;
        s_rs[tid] = rsqrtf(var + EPSV);
    }
    __syncthreads();

    // ---- fc2 (fused LN2) ----
    {
        const int b = tid >> 2, q = tid & 3;
        float a10[10];
#pragma unroll
        for (int c = 0; c < 10; c++) a10[c] = 0.f;
#pragma unroll 4
        for (int i = 0; i < 32; i++) {
            int o = 4 * i + q;
            float h = Pf[o * SDIM + b];
            const float* wr = s_wc2 + o * 12;
            float4 w0 = *(const float4*)wr;
            float4 w1 = *(const float4*)(wr + 4);
            float2 w2 = *(const float2*)(wr + 8);
            a10[0] = fmaf(h, w0.x, a10[0]);
            a10[1] = fmaf(h, w0.y, a10[1]);
            a10[2] = fmaf(h, w0.z, a10[2]);
            a10[3] = fmaf(h, w0.w, a10[3]);
            a10[4] = fmaf(h, w1.x, a10[4]);
            a10[5] = fmaf(h, w1.y, a10[5]);
            a10[6] = fmaf(h, w1.z, a10[6]);
            a10[7] = fmaf(h, w1.w, a10[7]);
            a10[8] = fmaf(h, w2.x, a10[8]);
            a10[9] = fmaf(h, w2.y, a10[9]);
        }
#pragma unroll
        for (int c = 0; c < 10; c++) {
            a10[c] += __shfl_xor_sync(0xffffffff, a10[c], 1);
            a10[c] += __shfl_xor_sync(0xffffffff, a10[c], 2);
        }
        if (q < 2) {
            const int c0 = q * 5;
            float mu2 = s_mu[b], rs2 = s_rs[b];
            size_t R = ((size_t)f * BATCH + b0 + b) * N_CLASS;
#pragma unroll
            for (int j = 0; j < 5; j++) {
                int c = c0 + j;
                g_Y[R + c] = fmaf(rs2, a10[c] - mu2 * s_s2[c], s_d2[c]);
            }
        }
    }
}

// =====================================================================
__global__ void k4_reduce(float* __restrict__ out) {
    int i = blockIdx.x * 256 + threadIdx.x;
    if (i < BATCH * N_CLASS / 4) {
        float4 s = make_float4(0.f, 0.f, 0.f, 0.f);
        for (int f = 0; f < N_FOREST; f++) {
            float4 v = *((const float4*)(g_Y + (size_t)f * (BATCH * N_CLASS)) + i);
            s.x += v.x; s.y += v.y; s.z += v.z; s.w += v.w;
        }
        out[i * 4 + 0] = s.x * (1.f / N_FOREST);
        out[i * 4 + 1] = s.y * (1.f / N_FOREST);
        out[i * 4 + 2] = s.z * (1.f / N_FOREST);
        out[i * 4 + 3] = s.w * (1.f / N_FOREST);
    }
}

// =====================================================================
extern "C" void kernel_launch(void* const* d_in, const int* in_sizes, int n_in,
                              void* d_out, int out_size) {
    const float* x     = (const float*)d_in[0];
    const float* w1    = (const float*)d_in[1];
    const float* b1    = (const float*)d_in[2];
    const int*   perm  = (const int*)  d_in[3];
    const float* gn1w  = (const float*)d_in[4];
    const float* gn1b  = (const float*)d_in[5];
    const float* c2w   = (const float*)d_in[6];
    const float* c2b   = (const float*)d_in[7];
    const float* gn2w  = (const float*)d_in[8];
    const float* gn2b  = (const float*)d_in[9];
    const float* c3w   = (const float*)d_in[10];
    const float* c3b   = (const float*)d_in[11];
    const int*   swr   = (const int*)  d_in[12];
    const float* E     = (const float*)d_in[13];
    const float* ln1w  = (const float*)d_in[14];
    const float* ln1b  = (const float*)d_in[15];
    const float* fc1w  = (const float*)d_in[16];
    const float* fc1b  = (const float*)d_in[17];
    const float* ln2w  = (const float*)d_in[18];
    const float* ln2b  = (const float*)d_in[19];
    const float* fc2w  = (const float*)d_in[20];
    const float* fc2b  = (const float*)d_in[21];
    float* out = (float*)d_out;

    cudaFuncSetAttribute(k23_forest_mlp, cudaFuncAttributeMaxDynamicSharedMemorySize, K23_SMEM);

    k0_transpose<<<(N_COL * BATCH) / 256, 256>>>(x);
    k_pre<<<(N_RODT * N_HID + 255) / 256, 256>>>(E, fc1w, ln1w, fc2w, ln2w);
    k_pre2<<<1, 128>>>(fc1w, fc1b, ln1b, fc2w, fc2b, ln2b);
    k1_rodt<<<dim3(N_RODT, BATCH / 1024), 256>>>(w1, b1, perm, gn1w, gn1b,
                                                 c2w, c2b, gn2w, gn2b, c3w, c3b);
    k23_forest_mlp<<<dim3(BATCH / 128, N_FOREST), 512, K23_SMEM>>>(swr);
    k4_reduce<<<(BATCH * N_CLASS / 4 + 255) / 256, 256>>>(out);
}

// round 10
// speedup vs baseline: 1.2457x; 1.2398x over previous
#include <cuda_runtime.h>
#include <cuda_fp16.h>
#include <cstdint>

// ---------------- problem constants ----------------
#define BATCH    4096
#define N_COL    100
#define N_COND   64
#define TOTAL    6400
#define N_RODT   1600
#define N_EST    160
#define N_FOREST 100
#define N_HID    128
#define N_CLASS  10
#define EPSV     1e-5f
#define SDH      136      // half stride per row (272B, 16B-aligned)

// ---------------- device scratch ----------------
__device__ float  g_xT  [N_COL * BATCH];
__device__ float  g_wT  [N_RODT * BATCH];
__device__ __half g_Ehf [N_RODT * N_HID];     // fp16(E)
__device__ __half g_W1hf[N_HID * N_HID];      // fp16(fc1w * ln1w) [d][o]
__device__ float  g_wc2[N_HID * 12];
__device__ float  g_s1[N_HID], g_d1[N_HID];
__device__ float  g_s2[16],    g_d2[16];
__device__ float  g_Y  [(size_t)N_FOREST * BATCH * N_CLASS];

__device__ __forceinline__ float to_tf32(float x) {
    uint32_t u;
    asm("cvt.rna.tf32.f32 %0, %1;" : "=r"(u) : "f"(x));
    return __uint_as_float(u);
}
__device__ __forceinline__ void cpasync16(uint32_t dst, const void* src) {
    asm volatile("cp.async.cg.shared.global [%0], [%1], 16;" :: "r"(dst), "l"(src));
}
#define CP_COMMIT asm volatile("cp.async.commit_group;")
#define CP_WAIT0  asm volatile("cp.async.wait_group 0;")

// =====================================================================
__global__ void k0_transpose(const float* __restrict__ x) {
    int i = blockIdx.x * 256 + threadIdx.x;
    int c = i >> 12;
    int b = i & 4095;
    g_xT[i] = x[b * N_COL + c];
}

// =====================================================================
__global__ void k_pre(const float* __restrict__ E, const float* __restrict__ fc1w,
                      const float* __restrict__ ln1w, const float* __restrict__ fc2w,
                      const float* __restrict__ ln2w) {
    int i = blockIdx.x * 256 + threadIdx.x;
    if (i < N_RODT * N_HID) g_Ehf[i] = __float2half_rn(E[i]);
    if (i < N_HID * N_HID) {
        int d = i >> 7;
        g_W1hf[i] = __float2half_rn(fc1w[i] * ln1w[d]);
    }
    if (i < N_HID * 12) {
        int o = i / 12, c = i % 12;
        g_wc2[i] = (c < 10) ? to_tf32(fc2w[o * 10 + c] * ln2w[o]) : 0.f;
    }
}
__global__ void k_pre2(const float* __restrict__ fc1w, const float* __restrict__ fc1b,
                       const float* __restrict__ ln1b, const float* __restrict__ fc2w,
                       const float* __restrict__ fc2b, const float* __restrict__ ln2b) {
    int o = threadIdx.x;
    float ssum = 0.f, dsum = 0.f;
    for (int k = 0; k < 128; k++) {
        ssum += __half2float(g_W1hf[k * 128 + o]);
        dsum += fc1w[k * 128 + o] * ln1b[k];
    }
    g_s1[o] = ssum;
    g_d1[o] = dsum + fc1b[o];
    if (o < 10) {
        float s2 = 0.f, d2 = 0.f;
        for (int k = 0; k < 128; k++) {
            s2 += g_wc2[k * 12 + o];
            d2 += ln2b[k] * fc2w[k * 10 + o];
        }
        g_s2[o] = s2;
        g_d2[o] = d2 + fc2b[o];
    } else if (o < 16) {
        g_s2[o] = 0.f; g_d2[o] = 0.f;
    }
}

// =====================================================================
// Kernel 1: condition gen + rODT scoring — 4 b's per thread
// =====================================================================
__global__ void __launch_bounds__(256, 4)
k1_rodt(const float* __restrict__ w1, const float* __restrict__ b1,
        const int*   __restrict__ perm,
        const float* __restrict__ gn1w, const float* __restrict__ gn1b,
        const float* __restrict__ c2w,  const float* __restrict__ c2b,
        const float* __restrict__ gn2w, const float* __restrict__ gn2b,
        const float* __restrict__ c3w,  const float* __restrict__ c3b) {
    int g   = blockIdx.x;
    int tid = threadIdx.x;
    __shared__ int   sc[4];
    __shared__ float sw1[4], sb1[4], sg1w[4], sg1b[4];
    __shared__ float sw2[16], sb2[4], sg2w[4], sg2b[4], sw3[4], sb3;
    if (tid < 4) {
        int t = 4 * g + tid;
        int p = perm[t];
        int c = p % N_COL;
        int j = p / N_COL;
        sc [tid] = c;
        sw1[tid] = w1[c * N_COND + j];
        sb1[tid] = b1[c * N_COND + j];
        sg1w[tid] = gn1w[t];  sg1b[tid] = gn1b[t];
        sb2 [tid] = c2b[t];
        sg2w[tid] = gn2w[t];  sg2b[tid] = gn2b[t];
        sw3 [tid] = c3w[g * 4 + tid];
    }
    if (tid < 16) sw2[tid] = c2w[g * 16 + tid];
    if (tid == 31) sb3 = c3b[g];
    __syncthreads();

    const int b = blockIdx.y * 1024 + tid * 4;
    float4 xv[4];
#pragma unroll
    for (int k = 0; k < 4; k++)
        xv[k] = *(const float4*)&g_xT[sc[k] * BATCH + b];

    float out[4];
#pragma unroll
    for (int j = 0; j < 4; j++) {
        float v[4];
#pragma unroll
        for (int k = 0; k < 4; k++) {
            float xval = (&xv[k].x)[j];
            float z = fmaf(xval, sw1[k], sb1[k]);
            v[k] = 1.f / (1.f + __expf(-z));
        }
        float mu = 0.25f * (v[0] + v[1] + v[2] + v[3]);
        float var = 0.f;
#pragma unroll
        for (int k = 0; k < 4; k++) { float d = v[k] - mu; var += d * d; }
        var *= 0.25f;
        float rs = rsqrtf(var + EPSV);
        float n[4];
#pragma unroll
        for (int k = 0; k < 4; k++) n[k] = fmaf((v[k] - mu) * rs, sg1w[k], sg1b[k]);
        float h[4];
#pragma unroll
        for (int o = 0; o < 4; o++) {
            float a = sb2[o];
#pragma unroll
            for (int k = 0; k < 4; k++) a = fmaf(n[k], sw2[k * 4 + o], a);
            h[o] = fmaxf(a, 0.f);
        }
        float mu2 = 0.25f * (h[0] + h[1] + h[2] + h[3]);
        float var2 = 0.f;
#pragma unroll
        for (int k = 0; k < 4; k++) { float d = h[k] - mu2; var2 += d * d; }
        var2 *= 0.25f;
        float rs2 = rsqrtf(var2 + EPSV);
        float wo = sb3;
#pragma unroll
        for (int k = 0; k < 4; k++)
            wo = fmaf(fmaf((h[k] - mu2) * rs2, sg2w[k], sg2b[k]), sw3[k], wo);
        out[j] = wo;
    }
    *(float4*)&g_wT[(size_t)g * BATCH + b] = make_float4(out[0], out[1], out[2], out[3]);
}

// =====================================================================
// fp16 m16n8k16 mma + ldmatrix (structure validated in R2)
// =====================================================================
__device__ __forceinline__ uint32_t smaddr(const void* p) {
    return (uint32_t)__cvta_generic_to_shared(p);
}
__device__ __forceinline__ void ldsm4t(uint32_t& r0, uint32_t& r1, uint32_t& r2, uint32_t& r3,
                                       uint32_t addr) {
    asm volatile("ldmatrix.sync.aligned.m8n8.x4.trans.shared.b16 {%0,%1,%2,%3}, [%4];"
                 : "=r"(r0), "=r"(r1), "=r"(r2), "=r"(r3) : "r"(addr));
}
__device__ __forceinline__ void mma_f16(float* c, const uint32_t* a, const uint32_t* b) {
    asm volatile("mma.sync.aligned.m16n8k16.row.col.f32.f16.f16.f32 "
                 "{%0,%1,%2,%3}, {%4,%5,%6,%7}, {%8,%9}, {%0,%1,%2,%3};"
                 : "+f"(c[0]), "+f"(c[1]), "+f"(c[2]), "+f"(c[3])
                 : "r"(a[0]), "r"(a[1]), "r"(a[2]), "r"(a[3]), "r"(b[0]), "r"(b[1]));
}

// C^T[m][n] += A^T B. Asm[k][SDH] halves (cols=m), Bsm[k][SDH] halves (cols=n).
// 16 warps: wm = warp&3 (M=32), wn = warp>>2 (N=32). K steps of 16.
template<int KSTEPS>
__device__ __forceinline__ void gemm_h(const __half* __restrict__ Asm,
                                       const __half* __restrict__ Bsm,
                                       int warp, int lane, float acc[2][4][4]) {
    const int M0 = (warp & 3) * 32, N0 = (warp >> 2) * 32;
    const int a_k = ((lane >> 4) << 3) + (lane & 7);
    const int a_m = ((lane >> 3) & 1) << 3;
    const int b_k = (((lane >> 3) & 1) << 3) + (lane & 7);
    const int b_n = (lane >> 4) << 3;
#pragma unroll
    for (int ks = 0; ks < KSTEPS; ks++) {
        const int K0 = ks * 16;
        uint32_t afr[2][4];
#pragma unroll
        for (int mt = 0; mt < 2; mt++) {
            uint32_t addr = smaddr(Asm + (K0 + a_k) * SDH + (M0 + mt * 16 + a_m));
            ldsm4t(afr[mt][0], afr[mt][1], afr[mt][2], afr[mt][3], addr);
        }
        uint32_t bfr[4][2];
#pragma unroll
        for (int np = 0; np < 2; np++) {
            uint32_t addr = smaddr(Bsm + (K0 + b_k) * SDH + (N0 + np * 16 + b_n));
            uint32_t r0, r1, r2, r3;
            ldsm4t(r0, r1, r2, r3, addr);
            bfr[np * 2][0] = r0;     bfr[np * 2][1] = r1;
            bfr[np * 2 + 1][0] = r2; bfr[np * 2 + 1][1] = r3;
        }
#pragma unroll
        for (int mt = 0; mt < 2; mt++)
#pragma unroll
            for (int nt = 0; nt < 4; nt++) mma_f16(acc[mt][nt], afr[mt], bfr[nt]);
    }
}

// =====================================================================
// k23: fused forest GEMM + MLP, fp16 operands.
// dynamic smem: Ph half[160][136] (P -> C~), Wh0/Wh1 half[80][136], Hf float[128][132]
// =====================================================================
#define OFF_WH0 (160 * SDH * 2)            // 43520
#define OFF_WH1 (OFF_WH0 + 80 * SDH * 2)   // 65280
#define OFF_HF  (OFF_WH1 + 80 * SDH * 2)   // 87040
#define K23_SMEM (OFF_HF + 128 * 132 * 4)  // 154624
__global__ void __launch_bounds__(512, 1) k23_forest_mlp(const int* __restrict__ swr) {
    extern __shared__ char sh[];
    __half* Ph  = (__half*)sh;
    __half* Wh0 = (__half*)(sh + OFF_WH0);
    __half* Wh1 = (__half*)(sh + OFF_WH1);
    float*  Hf  = (float*)(sh + OFF_HF);

    __shared__ int   s_idx[160];
    __shared__ float s_invS[128];
    __shared__ float s_part[16 * 128];
    __shared__ float s_redA[512], s_redB[512];
    __shared__ float s_mu[128], s_rs[128];
    __shared__ float s_s1[128], s_d1[128];
    __shared__ __align__(16) float s_wc2[128 * 12];
    __shared__ float s_s2[16], s_d2[16];

    const int tid = threadIdx.x, lane = tid & 31, warp = tid >> 5;
    const int f = blockIdx.y;
    const int b0 = blockIdx.x * 128;

    if (tid < 160) s_idx[tid] = swr[f * N_EST + tid];
    __syncthreads();

    // ---- issue E half0 via cp.async (rows: 128 halves = 16 x 16B) ----
    {
        uint32_t wb0 = (uint32_t)__cvta_generic_to_shared(Wh0);
#pragma unroll
        for (int i = tid; i < 80 * 16; i += 512) {
            int e = i >> 4, q = i & 15;
            cpasync16(wb0 + e * (SDH * 2) + q * 16, g_Ehf + (size_t)s_idx[e] * N_HID + q * 8);
        }
        CP_COMMIT;
    }

    // ---- stage P = fp16(exp(w)) with fused invS partials ----
    {
        float p0 = 0.f, p1 = 0.f, p2 = 0.f, p3 = 0.f;
        const int b4 = tid & 31;
#pragma unroll
        for (int j = 0; j < 10; j++) {
            int e = (tid >> 5) + 16 * j;
            float4 v = *(const float4*)(g_wT + (size_t)s_idx[e] * BATCH + b0 + b4 * 4);
            __half2 h01 = __floats2half2_rn(__expf(v.x), __expf(v.y));
            __half2 h23 = __floats2half2_rn(__expf(v.z), __expf(v.w));
            __half2* dst = (__half2*)(Ph + e * SDH + b4 * 4);
            dst[0] = h01; dst[1] = h23;
            float2 f01 = __half22float2(h01), f23 = __half22float2(h23);
            p0 += f01.x; p1 += f01.y; p2 += f23.x; p3 += f23.y;
        }
        float* pp = s_part + warp * 128 + b4 * 4;
        pp[0] = p0; pp[1] = p1; pp[2] = p2; pp[3] = p3;
    }
    if (tid < 128) { s_s1[tid] = g_s1[tid]; s_d1[tid] = g_d1[tid]; }
    for (int i = tid; i < 1536; i += 512) s_wc2[i] = g_wc2[i];
    if (tid < 16) { s_s2[tid] = g_s2[tid]; s_d2[tid] = g_d2[tid]; }
    CP_WAIT0;
    __syncthreads();

    // ---- issue E half1 -> Wh1 ----
    {
        uint32_t wb1 = (uint32_t)__cvta_generic_to_shared(Wh1);
#pragma unroll
        for (int i = tid; i < 80 * 16; i += 512) {
            int e = i >> 4, q = i & 15;
            cpasync16(wb1 + e * (SDH * 2) + q * 16, g_Ehf + (size_t)s_idx[80 + e] * N_HID + q * 8);
        }
        CP_COMMIT;
    }

    // ---- invS finalize ----
    if (tid < 128) {
        float s = 0.f;
#pragma unroll
        for (int w = 0; w < 16; w++) s += s_part[w * 128 + tid];
        s_invS[tid] = 1.f / s;
    }

    // ---- GEMM A: C^T[d][b] = sum_e E[e][d] P[e][b], K=160, two halves ----
    float acc[2][4][4];
#pragma unroll
    for (int mt = 0; mt < 2; mt++)
#pragma unroll
        for (int nt = 0; nt < 4; nt++)
#pragma unroll
            for (int r = 0; r < 4; r++) acc[mt][nt][r] = 0.f;
    gemm_h<5>(Wh0, Ph, warp, lane, acc);
    CP_WAIT0;
    __syncthreads();
    // prefetch W1' half0 (64 rows) into Wh0
    {
        uint32_t wb0 = (uint32_t)__cvta_generic_to_shared(Wh0);
#pragma unroll
        for (int i = tid; i < 64 * 16; i += 512) {
            int k = i >> 4, q = i & 15;
            cpasync16(wb0 + k * (SDH * 2) + q * 16, g_W1hf + k * N_HID + q * 8);
        }
        CP_COMMIT;
    }
    gemm_h<5>(Wh1, Ph + 80 * SDH, warp, lane, acc);
    __syncthreads();   // all P reads done before overwrite
    // prefetch W1' half1 into Wh1
    {
        uint32_t wb1 = (uint32_t)__cvta_generic_to_shared(Wh1);
#pragma unroll
        for (int i = tid; i < 64 * 16; i += 512) {
            int k = i >> 4, q = i & 15;
            cpasync16(wb1 + k * (SDH * 2) + q * 16, g_W1hf + (64 + k) * N_HID + q * 8);
        }
        CP_COMMIT;
    }
    // epilogue A: C~ = fp16(acc * invS) -> Ph rows 0..127
    {
        const int M0 = (warp & 3) * 32, N0 = (warp >> 2) * 32;
        const int g = lane >> 2, q2 = (lane & 3) * 2;
#pragma unroll
        for (int mt = 0; mt < 2; mt++)
#pragma unroll
            for (int nt = 0; nt < 4; nt++) {
                int row = M0 + mt * 16 + g, col = N0 + nt * 8 + q2;
                float i0 = s_invS[col], i1 = s_invS[col + 1];
                *(__half2*)(Ph + row * SDH + col) =
                    __floats2half2_rn(acc[mt][nt][0] * i0, acc[mt][nt][1] * i1);
                *(__half2*)(Ph + (row + 8) * SDH + col) =
                    __floats2half2_rn(acc[mt][nt][2] * i0, acc[mt][nt][3] * i1);
            }
    }
    CP_WAIT0;
    __syncthreads();

    // ---- stats1: per-column mean/rstd of C~ ----
    {
        const int col = tid & 127, q = tid >> 7;
        float s = 0.f, s2 = 0.f;
        for (int r = 0; r < 32; r++) {
            float v = __half2float(Ph[(q * 32 + r) * SDH + col]);
            s += v; s2 += v * v;
        }
        s_redA[q * 128 + col] = s;
        s_redB[q * 128 + col] = s2;
    }
    __syncthreads();
    if (tid < 128) {
        float s  = s_redA[tid] + s_redA[128 + tid] + s_redA[256 + tid] + s_redA[384 + tid];
        float s2 = s_redB[tid] + s_redB[128 + tid] + s_redB[256 + tid] + s_redB[384 + tid];
        float mu = s * (1.f / 128.f);
        float var = fmaxf(s2 * (1.f / 128.f) - mu * mu, 0.f);
        s_mu[tid] = mu;
        s_rs[tid] = rsqrtf(var + EPSV);
    }
    __syncthreads();

    // ---- GEMM B: G[o][b] = sum_d W1'[d][o] C~[d][b], K=128, two halves ----
#pragma unroll
    for (int mt = 0; mt < 2; mt++)
#pragma unroll
        for (int nt = 0; nt < 4; nt++)
#pragma unroll
            for (int r = 0; r < 4; r++) acc[mt][nt][r] = 0.f;
    gemm_h<4>(Wh0, Ph, warp, lane, acc);
    gemm_h<4>(Wh1, Ph + 64 * SDH, warp, lane, acc);
    __syncthreads();

    // epilogue B: H = relu(rs*(G - mu*s1) + d1) -> Hf (float)
    {
        const int M0 = (warp & 3) * 32, N0 = (warp >> 2) * 32;
        const int g = lane >> 2, q2 = (lane & 3) * 2;
#pragma unroll
        for (int mt = 0; mt < 2; mt++)
#pragma unroll
            for (int nt = 0; nt < 4; nt++) {
                int row = M0 + mt * 16 + g, col = N0 + nt * 8 + q2;
                float s1a = s_s1[row], d1a = s_d1[row];
                float s1b = s_s1[row + 8], d1b = s_d1[row + 8];
                float mu0 = s_mu[col], rs0 = s_rs[col];
                float mu1 = s_mu[col + 1], rs1 = s_rs[col + 1];
                Hf[row * 132 + col]           = fmaxf(fmaf(rs0, acc[mt][nt][0] - mu0 * s1a, d1a), 0.f);
                Hf[row * 132 + col + 1]       = fmaxf(fmaf(rs1, acc[mt][nt][1] - mu1 * s1a, d1a), 0.f);
                Hf[(row + 8) * 132 + col]     = fmaxf(fmaf(rs0, acc[mt][nt][2] - mu0 * s1b, d1b), 0.f);
                Hf[(row + 8) * 132 + col + 1] = fmaxf(fmaf(rs1, acc[mt][nt][3] - mu1 * s1b, d1b), 0.f);
            }
    }
    __syncthreads();

    // ---- stats2 ----
    {
        const int col = tid & 127, q = tid >> 7;
        float s = 0.f, s2 = 0.f;
        for (int r = 0; r < 32; r++) {
            float v = Hf[(q * 32 + r) * 132 + col];
            s += v; s2 += v * v;
        }
        s_redA[q * 128 + col] = s;
        s_redB[q * 128 + col] = s2;
    }
    __syncthreads();
    if (tid < 128) {
        float s  = s_redA[tid] + s_redA[128 + tid] + s_redA[256 + tid] + s_redA[384 + tid];
        float s2 = s_redB[tid] + s_redB[128 + tid] + s_redB[256 + tid] + s_redB[384 + tid];
        float mu = s * (1.f / 128.f);
        float var = fmaxf(s2 * (1.f / 128.f) - mu * mu, 0.f);
        s_mu[tid] = mu;
        s_rs[tid] = rsqrtf(var + EPSV);
    }
    __syncthreads();

    // ---- fc2 (fused LN2) ----
    {
        const int b = tid >> 2, q = tid & 3;
        float a10[10];
#pragma unroll
        for (int c = 0; c < 10; c++) a10[c] = 0.f;
#pragma unroll 4
        for (int i = 0; i < 32; i++) {
            int o = 4 * i + q;
            float h = Hf[o * 132 + b];
            const float* wr = s_wc2 + o * 12;
            float4 w0 = *(const float4*)wr;
            float4 w1 = *(const float4*)(wr + 4);
            float2 w2 = *(const float2*)(wr + 8);
            a10[0] = fmaf(h, w0.x, a10[0]);
            a10[1] = fmaf(h, w0.y, a10[1]);
            a10[2] = fmaf(h, w0.z, a10[2]);
            a10[3] = fmaf(h, w0.w, a10[3]);
            a10[4] = fmaf(h, w1.x, a10[4]);
            a10[5] = fmaf(h, w1.y, a10[5]);
            a10[6] = fmaf(h, w1.z, a10[6]);
            a10[7] = fmaf(h, w1.w, a10[7]);
            a10[8] = fmaf(h, w2.x, a10[8]);
            a10[9] = fmaf(h, w2.y, a10[9]);
        }
#pragma unroll
        for (int c = 0; c < 10; c++) {
            a10[c] += __shfl_xor_sync(0xffffffff, a10[c], 1);
            a10[c] += __shfl_xor_sync(0xffffffff, a10[c], 2);
        }
        if (q < 2) {
            const int c0 = q * 5;
            float mu2 = s_mu[b], rs2 = s_rs[b];
            size_t R = ((size_t)f * BATCH + b0 + b) * N_CLASS;
#pragma unroll
            for (int j = 0; j < 5; j++) {
                int c = c0 + j;
                g_Y[R + c] = fmaf(rs2, a10[c] - mu2 * s_s2[c], s_d2[c]);
            }
        }
    }
}

// =====================================================================
__global__ void k4_reduce(float* __restrict__ out) {
    int i = blockIdx.x * 256 + threadIdx.x;
    if (i < BATCH * N_CLASS / 4) {
        float4 s = make_float4(0.f, 0.f, 0.f, 0.f);
        for (int f = 0; f < N_FOREST; f++) {
            float4 v = *((const float4*)(g_Y + (size_t)f * (BATCH * N_CLASS)) + i);
            s.x += v.x; s.y += v.y; s.z += v.z; s.w += v.w;
        }
        out[i * 4 + 0] = s.x * (1.f / N_FOREST);
        out[i * 4 + 1] = s.y * (1.f / N_FOREST);
        out[i * 4 + 2] = s.z * (1.f / N_FOREST);
        out[i * 4 + 3] = s.w * (1.f / N_FOREST);
    }
}

// =====================================================================
extern "C" void kernel_launch(void* const* d_in, const int* in_sizes, int n_in,
                              void* d_out, int out_size) {
    const float* x     = (const float*)d_in[0];
    const float* w1    = (const float*)d_in[1];
    const float* b1    = (const float*)d_in[2];
    const int*   perm  = (const int*)  d_in[3];
    const float* gn1w  = (const float*)d_in[4];
    const float* gn1b  = (const float*)d_in[5];
    const float* c2w   = (const float*)d_in[6];
    const float* c2b   = (const float*)d_in[7];
    const float* gn2w  = (const float*)d_in[8];
    const float* gn2b  = (const float*)d_in[9];
    const float* c3w   = (const float*)d_in[10];
    const float* c3b   = (const float*)d_in[11];
    const int*   swr   = (const int*)  d_in[12];
    const float* E     = (const float*)d_in[13];
    const float* ln1w  = (const float*)d_in[14];
    const float* ln1b  = (const float*)d_in[15];
    const float* fc1w  = (const float*)d_in[16];
    const float* fc1b  = (const float*)d_in[17];
    const float* ln2w  = (const float*)d_in[18];
    const float* ln2b  = (const float*)d_in[19];
    const float* fc2w  = (const float*)d_in[20];
    const float* fc2b  = (const float*)d_in[21];
    float* out = (float*)d_out;

    cudaFuncSetAttribute(k23_forest_mlp, cudaFuncAttributeMaxDynamicSharedMemorySize, K23_SMEM);

    k0_transpose<<<(N_COL * BATCH) / 256, 256>>>(x);
    k_pre<<<(N_RODT * N_HID + 255) / 256, 256>>>(E, fc1w, ln1w, fc2w, ln2w);
    k_pre2<<<1, 128>>>(fc1w, fc1b, ln1b, fc2w, fc2b, ln2b);
    k1_rodt<<<dim3(N_RODT, BATCH / 1024), 256>>>(w1, b1, perm, gn1w, gn1b,
                                                 c2w, c2b, gn2w, gn2b, c3w, c3b);
    k23_forest_mlp<<<dim3(BATCH / 128, N_FOREST), 512, K23_SMEM>>>(swr);
    k4_reduce<<<(BATCH * N_CLASS / 4 + 255) / 256, 256>>>(out);
}

// round 11
// speedup vs baseline: 1.5624x; 1.2543x over previous
#include <cuda_runtime.h>
#include <cuda_fp16.h>
#include <cstdint>

// ---------------- problem constants ----------------
#define BATCH    4096
#define N_COL    100
#define N_COND   64
#define TOTAL    6400
#define N_RODT   1600
#define N_EST    160
#define N_FOREST 100
#define N_HID    128
#define N_CLASS  10
#define EPSV     1e-5f
#define SDH      136      // half stride per row (272B, 16B-aligned)

// ---------------- device scratch ----------------
__device__ float  g_xT  [N_COL * BATCH];
__device__ float  g_wT  [N_RODT * BATCH];
__device__ __half g_Ehf [N_RODT * N_HID];     // fp16(E)
__device__ __half g_W1hf[N_HID * N_HID];      // fp16(fc1w * ln1w) [d][o]
__device__ float  g_wc2[N_HID * 12];
__device__ float  g_s1[N_HID], g_d1[N_HID];
__device__ float  g_s2[16],    g_d2[16];
__device__ float  g_Y  [(size_t)N_FOREST * BATCH * N_CLASS];

__device__ __forceinline__ float to_tf32(float x) {
    uint32_t u;
    asm("cvt.rna.tf32.f32 %0, %1;" : "=r"(u) : "f"(x));
    return __uint_as_float(u);
}
__device__ __forceinline__ void cpasync16(uint32_t dst, const void* src) {
    asm volatile("cp.async.cg.shared.global [%0], [%1], 16;" :: "r"(dst), "l"(src));
}
#define CP_COMMIT asm volatile("cp.async.commit_group;")
#define CP_WAIT0  asm volatile("cp.async.wait_group 0;")

// =====================================================================
__global__ void k0_transpose(const float* __restrict__ x) {
    int i = blockIdx.x * 256 + threadIdx.x;
    int c = i >> 12;
    int b = i & 4095;
    g_xT[i] = x[b * N_COL + c];
}

// =====================================================================
__global__ void k_pre(const float* __restrict__ E, const float* __restrict__ fc1w,
                      const float* __restrict__ ln1w, const float* __restrict__ fc2w,
                      const float* __restrict__ ln2w) {
    int i = blockIdx.x * 256 + threadIdx.x;
    if (i < N_RODT * N_HID) g_Ehf[i] = __float2half_rn(E[i]);
    if (i < N_HID * N_HID) {
        int d = i >> 7;
        g_W1hf[i] = __float2half_rn(fc1w[i] * ln1w[d]);
    }
    if (i < N_HID * 12) {
        int o = i / 12, c = i % 12;
        g_wc2[i] = (c < 10) ? to_tf32(fc2w[o * 10 + c] * ln2w[o]) : 0.f;
    }
}
__global__ void k_pre2(const float* __restrict__ fc1w, const float* __restrict__ fc1b,
                       const float* __restrict__ ln1b, const float* __restrict__ fc2w,
                       const float* __restrict__ fc2b, const float* __restrict__ ln2b) {
    int o = threadIdx.x;
    float ssum = 0.f, dsum = 0.f;
    for (int k = 0; k < 128; k++) {
        ssum += __half2float(g_W1hf[k * 128 + o]);
        dsum += fc1w[k * 128 + o] * ln1b[k];
    }
    g_s1[o] = ssum;
    g_d1[o] = dsum + fc1b[o];
    if (o < 10) {
        float s2 = 0.f, d2 = 0.f;
        for (int k = 0; k < 128; k++) {
            s2 += g_wc2[k * 12 + o];
            d2 += ln2b[k] * fc2w[k * 10 + o];
        }
        g_s2[o] = s2;
        g_d2[o] = d2 + fc2b[o];
    } else if (o < 16) {
        g_s2[o] = 0.f; g_d2[o] = 0.f;
    }
}

// =====================================================================
// Kernel 1: condition gen + rODT scoring — 4 b's per thread
// =====================================================================
__global__ void __launch_bounds__(256, 4)
k1_rodt(const float* __restrict__ w1, const float* __restrict__ b1,
        const int*   __restrict__ perm,
        const float* __restrict__ gn1w, const float* __restrict__ gn1b,
        const float* __restrict__ c2w,  const float* __restrict__ c2b,
        const float* __restrict__ gn2w, const float* __restrict__ gn2b,
        const float* __restrict__ c3w,  const float* __restrict__ c3b) {
    int g   = blockIdx.x;
    int tid = threadIdx.x;
    __shared__ int   sc[4];
    __shared__ float sw1[4], sb1[4], sg1w[4], sg1b[4];
    __shared__ float sw2[16], sb2[4], sg2w[4], sg2b[4], sw3[4], sb3;
    if (tid < 4) {
        int t = 4 * g + tid;
        int p = perm[t];
        int c = p % N_COL;
        int j = p / N_COL;
        sc [tid] = c;
        sw1[tid] = w1[c * N_COND + j];
        sb1[tid] = b1[c * N_COND + j];
        sg1w[tid] = gn1w[t];  sg1b[tid] = gn1b[t];
        sb2 [tid] = c2b[t];
        sg2w[tid] = gn2w[t];  sg2b[tid] = gn2b[t];
        sw3 [tid] = c3w[g * 4 + tid];
    }
    if (tid < 16) sw2[tid] = c2w[g * 16 + tid];
    if (tid == 31) sb3 = c3b[g];
    __syncthreads();

    const int b = blockIdx.y * 1024 + tid * 4;
    float4 xv[4];
#pragma unroll
    for (int k = 0; k < 4; k++)
        xv[k] = *(const float4*)&g_xT[sc[k] * BATCH + b];

    float out[4];
#pragma unroll
    for (int j = 0; j < 4; j++) {
        float v[4];
#pragma unroll
        for (int k = 0; k < 4; k++) {
            float xval = (&xv[k].x)[j];
            float z = fmaf(xval, sw1[k], sb1[k]);
            v[k] = 1.f / (1.f + __expf(-z));
        }
        float mu = 0.25f * (v[0] + v[1] + v[2] + v[3]);
        float var = 0.f;
#pragma unroll
        for (int k = 0; k < 4; k++) { float d = v[k] - mu; var += d * d; }
        var *= 0.25f;
        float rs = rsqrtf(var + EPSV);
        float n[4];
#pragma unroll
        for (int k = 0; k < 4; k++) n[k] = fmaf((v[k] - mu) * rs, sg1w[k], sg1b[k]);
        float h[4];
#pragma unroll
        for (int o = 0; o < 4; o++) {
            float a = sb2[o];
#pragma unroll
            for (int k = 0; k < 4; k++) a = fmaf(n[k], sw2[k * 4 + o], a);
            h[o] = fmaxf(a, 0.f);
        }
        float mu2 = 0.25f * (h[0] + h[1] + h[2] + h[3]);
        float var2 = 0.f;
#pragma unroll
        for (int k = 0; k < 4; k++) { float d = h[k] - mu2; var2 += d * d; }
        var2 *= 0.25f;
        float rs2 = rsqrtf(var2 + EPSV);
        float wo = sb3;
#pragma unroll
        for (int k = 0; k < 4; k++)
            wo = fmaf(fmaf((h[k] - mu2) * rs2, sg2w[k], sg2b[k]), sw3[k], wo);
        out[j] = wo;
    }
    *(float4*)&g_wT[(size_t)g * BATCH + b] = make_float4(out[0], out[1], out[2], out[3]);
}

// =====================================================================
// fp16 m16n8k16 mma + ldmatrix
// =====================================================================
__device__ __forceinline__ uint32_t smaddr(const void* p) {
    return (uint32_t)__cvta_generic_to_shared(p);
}
__device__ __forceinline__ void ldsm4t(uint32_t& r0, uint32_t& r1, uint32_t& r2, uint32_t& r3,
                                       uint32_t addr) {
    asm volatile("ldmatrix.sync.aligned.m8n8.x4.trans.shared.b16 {%0,%1,%2,%3}, [%4];"
                 : "=r"(r0), "=r"(r1), "=r"(r2), "=r"(r3) : "r"(addr));
}
__device__ __forceinline__ void mma_f16(float* c, const uint32_t* a, const uint32_t* b) {
    asm volatile("mma.sync.aligned.m16n8k16.row.col.f32.f16.f16.f32 "
                 "{%0,%1,%2,%3}, {%4,%5,%6,%7}, {%8,%9}, {%0,%1,%2,%3};"
                 : "+f"(c[0]), "+f"(c[1]), "+f"(c[2]), "+f"(c[3])
                 : "r"(a[0]), "r"(a[1]), "r"(a[2]), "r"(a[3]), "r"(b[0]), "r"(b[1]));
}

template<int KSTEPS>
__device__ __forceinline__ void gemm_h(const __half* __restrict__ Asm,
                                       const __half* __restrict__ Bsm,
                                       int warp, int lane, float acc[2][4][4]) {
    const int M0 = (warp & 3) * 32, N0 = (warp >> 2) * 32;
    const int a_k = ((lane >> 4) << 3) + (lane & 7);
    const int a_m = ((lane >> 3) & 1) << 3;
    const int b_k = (((lane >> 3) & 1) << 3) + (lane & 7);
    const int b_n = (lane >> 4) << 3;
#pragma unroll
    for (int ks = 0; ks < KSTEPS; ks++) {
        const int K0 = ks * 16;
        uint32_t afr[2][4];
#pragma unroll
        for (int mt = 0; mt < 2; mt++) {
            uint32_t addr = smaddr(Asm + (K0 + a_k) * SDH + (M0 + mt * 16 + a_m));
            ldsm4t(afr[mt][0], afr[mt][1], afr[mt][2], afr[mt][3], addr);
        }
        uint32_t bfr[4][2];
#pragma unroll
        for (int np = 0; np < 2; np++) {
            uint32_t addr = smaddr(Bsm + (K0 + b_k) * SDH + (N0 + np * 16 + b_n));
            uint32_t r0, r1, r2, r3;
            ldsm4t(r0, r1, r2, r3, addr);
            bfr[np * 2][0] = r0;     bfr[np * 2][1] = r1;
            bfr[np * 2 + 1][0] = r2; bfr[np * 2 + 1][1] = r3;
        }
#pragma unroll
        for (int mt = 0; mt < 2; mt++)
#pragma unroll
            for (int nt = 0; nt < 4; nt++) mma_f16(acc[mt][nt], afr[mt], bfr[nt]);
    }
}

// =====================================================================
// k23: fused forest GEMM + MLP, fp16 operands AND fp16 H (all in Ph).
// dynamic smem: Ph half[160][136] (P -> C~ -> H), Wh0/Wh1 half[80][136]
// 2 blocks/SM.
// =====================================================================
#define OFF_WH0 (160 * SDH * 2)            // 43520
#define OFF_WH1 (OFF_WH0 + 80 * SDH * 2)   // 65280
#define K23_SMEM (OFF_WH1 + 80 * SDH * 2)  // 87040
__global__ void __launch_bounds__(512, 2) k23_forest_mlp(const int* __restrict__ swr) {
    extern __shared__ char sh[];
    __half* Ph  = (__half*)sh;
    __half* Wh0 = (__half*)(sh + OFF_WH0);
    __half* Wh1 = (__half*)(sh + OFF_WH1);

    __shared__ int   s_idx[160];
    __shared__ float s_invS[128];
    __shared__ float s_scratch[2048];          // s_part(2048) OR redA(512)+redB(512)
    __shared__ float s_mu[128], s_rs[128];
    __shared__ float s_s1[128], s_d1[128];
    __shared__ __align__(16) float s_wc2[128 * 12];
    __shared__ float s_s2[16], s_d2[16];

    float* s_part = s_scratch;
    float* s_redA = s_scratch;
    float* s_redB = s_scratch + 512;

    const int tid = threadIdx.x, lane = tid & 31, warp = tid >> 5;
    const int f = blockIdx.y;
    const int b0 = blockIdx.x * 128;

    if (tid < 160) s_idx[tid] = swr[f * N_EST + tid];
    __syncthreads();

    // ---- issue E half0 via cp.async ----
    {
        uint32_t wb0 = (uint32_t)__cvta_generic_to_shared(Wh0);
#pragma unroll
        for (int i = tid; i < 80 * 16; i += 512) {
            int e = i >> 4, q = i & 15;
            cpasync16(wb0 + e * (SDH * 2) + q * 16, g_Ehf + (size_t)s_idx[e] * N_HID + q * 8);
        }
        CP_COMMIT;
    }

    // ---- stage P = fp16(exp(w)) with fused invS partials ----
    {
        float p0 = 0.f, p1 = 0.f, p2 = 0.f, p3 = 0.f;
        const int b4 = tid & 31;
#pragma unroll
        for (int j = 0; j < 10; j++) {
            int e = (tid >> 5) + 16 * j;
            float4 v = *(const float4*)(g_wT + (size_t)s_idx[e] * BATCH + b0 + b4 * 4);
            __half2 h01 = __floats2half2_rn(__expf(v.x), __expf(v.y));
            __half2 h23 = __floats2half2_rn(__expf(v.z), __expf(v.w));
            __half2* dst = (__half2*)(Ph + e * SDH + b4 * 4);
            dst[0] = h01; dst[1] = h23;
            float2 f01 = __half22float2(h01), f23 = __half22float2(h23);
            p0 += f01.x; p1 += f01.y; p2 += f23.x; p3 += f23.y;
        }
        float* pp = s_part + warp * 128 + b4 * 4;
        pp[0] = p0; pp[1] = p1; pp[2] = p2; pp[3] = p3;
    }
    if (tid < 128) { s_s1[tid] = g_s1[tid]; s_d1[tid] = g_d1[tid]; }
    for (int i = tid; i < 1536; i += 512) s_wc2[i] = g_wc2[i];
    if (tid < 16) { s_s2[tid] = g_s2[tid]; s_d2[tid] = g_d2[tid]; }
    CP_WAIT0;
    __syncthreads();

    // ---- issue E half1 -> Wh1 ----
    {
        uint32_t wb1 = (uint32_t)__cvta_generic_to_shared(Wh1);
#pragma unroll
        for (int i = tid; i < 80 * 16; i += 512) {
            int e = i >> 4, q = i & 15;
            cpasync16(wb1 + e * (SDH * 2) + q * 16, g_Ehf + (size_t)s_idx[80 + e] * N_HID + q * 8);
        }
        CP_COMMIT;
    }

    // ---- invS finalize ----
    if (tid < 128) {
        float s = 0.f;
#pragma unroll
        for (int w = 0; w < 16; w++) s += s_part[w * 128 + tid];
        s_invS[tid] = 1.f / s;
    }

    // ---- GEMM A: K=160, two halves ----
    float acc[2][4][4];
#pragma unroll
    for (int mt = 0; mt < 2; mt++)
#pragma unroll
        for (int nt = 0; nt < 4; nt++)
#pragma unroll
            for (int r = 0; r < 4; r++) acc[mt][nt][r] = 0.f;
    gemm_h<5>(Wh0, Ph, warp, lane, acc);
    CP_WAIT0;
    __syncthreads();
    // prefetch W1' half0 into Wh0
    {
        uint32_t wb0 = (uint32_t)__cvta_generic_to_shared(Wh0);
#pragma unroll
        for (int i = tid; i < 64 * 16; i += 512) {
            int k = i >> 4, q = i & 15;
            cpasync16(wb0 + k * (SDH * 2) + q * 16, g_W1hf + k * N_HID + q * 8);
        }
        CP_COMMIT;
    }
    gemm_h<5>(Wh1, Ph + 80 * SDH, warp, lane, acc);
    __syncthreads();   // all P reads done before overwrite
    // prefetch W1' half1 into Wh1
    {
        uint32_t wb1 = (uint32_t)__cvta_generic_to_shared(Wh1);
#pragma unroll
        for (int i = tid; i < 64 * 16; i += 512) {
            int k = i >> 4, q = i & 15;
            cpasync16(wb1 + k * (SDH * 2) + q * 16, g_W1hf + (64 + k) * N_HID + q * 8);
        }
        CP_COMMIT;
    }
    // epilogue A: C~ = fp16(acc * invS) -> Ph rows 0..127
    {
        const int M0 = (warp & 3) * 32, N0 = (warp >> 2) * 32;
        const int g = lane >> 2, q2 = (lane & 3) * 2;
#pragma unroll
        for (int mt = 0; mt < 2; mt++)
#pragma unroll
            for (int nt = 0; nt < 4; nt++) {
                int row = M0 + mt * 16 + g, col = N0 + nt * 8 + q2;
                float i0 = s_invS[col], i1 = s_invS[col + 1];
                *(__half2*)(Ph + row * SDH + col) =
                    __floats2half2_rn(acc[mt][nt][0] * i0, acc[mt][nt][1] * i1);
                *(__half2*)(Ph + (row + 8) * SDH + col) =
                    __floats2half2_rn(acc[mt][nt][2] * i0, acc[mt][nt][3] * i1);
            }
    }
    CP_WAIT0;
    __syncthreads();

    // ---- stats1: per-column mean/rstd of C~ ----
    {
        const int col = tid & 127, q = tid >> 7;
        float s = 0.f, s2 = 0.f;
        for (int r = 0; r < 32; r++) {
            float v = __half2float(Ph[(q * 32 + r) * SDH + col]);
            s += v; s2 += v * v;
        }
        s_redA[q * 128 + col] = s;
        s_redB[q * 128 + col] = s2;
    }
    __syncthreads();
    if (tid < 128) {
        float s  = s_redA[tid] + s_redA[128 + tid] + s_redA[256 + tid] + s_redA[384 + tid];
        float s2 = s_redB[tid] + s_redB[128 + tid] + s_redB[256 + tid] + s_redB[384 + tid];
        float mu = s * (1.f / 128.f);
        float var = fmaxf(s2 * (1.f / 128.f) - mu * mu, 0.f);
        s_mu[tid] = mu;
        s_rs[tid] = rsqrtf(var + EPSV);
    }
    __syncthreads();

    // ---- GEMM B: K=128, two halves ----
#pragma unroll
    for (int mt = 0; mt < 2; mt++)
#pragma unroll
        for (int nt = 0; nt < 4; nt++)
#pragma unroll
            for (int r = 0; r < 4; r++) acc[mt][nt][r] = 0.f;
    gemm_h<4>(Wh0, Ph, warp, lane, acc);
    gemm_h<4>(Wh1, Ph + 64 * SDH, warp, lane, acc);
    __syncthreads();   // all C~ reads done before overwrite

    // epilogue B: H = fp16(relu(rs*(G - mu*s1) + d1)) -> Ph rows 0..127
    {
        const int M0 = (warp & 3) * 32, N0 = (warp >> 2) * 32;
        const int g = lane >> 2, q2 = (lane & 3) * 2;
#pragma unroll
        for (int mt = 0; mt < 2; mt++)
#pragma unroll
            for (int nt = 0; nt < 4; nt++) {
                int row = M0 + mt * 16 + g, col = N0 + nt * 8 + q2;
                float s1a = s_s1[row], d1a = s_d1[row];
                float s1b = s_s1[row + 8], d1b = s_d1[row + 8];
                float mu0 = s_mu[col], rs0 = s_rs[col];
                float mu1 = s_mu[col + 1], rs1 = s_rs[col + 1];
                *(__half2*)(Ph + row * SDH + col) = __floats2half2_rn(
                    fmaxf(fmaf(rs0, acc[mt][nt][0] - mu0 * s1a, d1a), 0.f),
                    fmaxf(fmaf(rs1, acc[mt][nt][1] - mu1 * s1a, d1a), 0.f));
                *(__half2*)(Ph + (row + 8) * SDH + col) = __floats2half2_rn(
                    fmaxf(fmaf(rs0, acc[mt][nt][2] - mu0 * s1b, d1b), 0.f),
                    fmaxf(fmaf(rs1, acc[mt][nt][3] - mu1 * s1b, d1b), 0.f));
            }
    }
    __syncthreads();

    // ---- stats2 on fp16 H ----
    {
        const int col = tid & 127, q = tid >> 7;
        float s = 0.f, s2 = 0.f;
        for (int r = 0; r < 32; r++) {
            float v = __half2float(Ph[(q * 32 + r) * SDH + col]);
            s += v; s2 += v * v;
        }
        s_redA[q * 128 + col] = s;
        s_redB[q * 128 + col] = s2;
    }
    __syncthreads();
    if (tid < 128) {
        float s  = s_redA[tid] + s_redA[128 + tid] + s_redA[256 + tid] + s_redA[384 + tid];
        float s2 = s_redB[tid] + s_redB[128 + tid] + s_redB[256 + tid] + s_redB[384 + tid];
        float mu = s * (1.f / 128.f);
        float var = fmaxf(s2 * (1.f / 128.f) - mu * mu, 0.f);
        s_mu[tid] = mu;
        s_rs[tid] = rsqrtf(var + EPSV);
    }
    __syncthreads();

    // ---- fc2 (fused LN2) on fp16 H ----
    {
        const int b = tid >> 2, q = tid & 3;
        float a10[10];
#pragma unroll
        for (int c = 0; c < 10; c++) a10[c] = 0.f;
#pragma unroll 4
        for (int i = 0; i < 32; i++) {
            int o = 4 * i + q;
            float h = __half2float(Ph[o * SDH + b]);
            const float* wr = s_wc2 + o * 12;
            float4 w0 = *(const float4*)wr;
            float4 w1 = *(const float4*)(wr + 4);
            float2 w2 = *(const float2*)(wr + 8);
            a10[0] = fmaf(h, w0.x, a10[0]);
            a10[1] = fmaf(h, w0.y, a10[1]);
            a10[2] = fmaf(h, w0.z, a10[2]);
            a10[3] = fmaf(h, w0.w, a10[3]);
            a10[4] = fmaf(h, w1.x, a10[4]);
            a10[5] = fmaf(h, w1.y, a10[5]);
            a10[6] = fmaf(h, w1.z, a10[6]);
            a10[7] = fmaf(h, w1.w, a10[7]);
            a10[8] = fmaf(h, w2.x, a10[8]);
            a10[9] = fmaf(h, w2.y, a10[9]);
        }
#pragma unroll
        for (int c = 0; c < 10; c++) {
            a10[c] += __shfl_xor_sync(0xffffffff, a10[c], 1);
            a10[c] += __shfl_xor_sync(0xffffffff, a10[c], 2);
        }
        if (q < 2) {
            const int c0 = q * 5;
            float mu2 = s_mu[b], rs2 = s_rs[b];
            size_t R = ((size_t)f * BATCH + b0 + b) * N_CLASS;
#pragma unroll
            for (int j = 0; j < 5; j++) {
                int c = c0 + j;
                g_Y[R + c] = fmaf(rs2, a10[c] - mu2 * s_s2[c], s_d2[c]);
            }
        }
    }
}

// =====================================================================
__global__ void k4_reduce(float* __restrict__ out) {
    int i = blockIdx.x * 256 + threadIdx.x;
    if (i < BATCH * N_CLASS / 4) {
        float4 s = make_float4(0.f, 0.f, 0.f, 0.f);
        for (int f = 0; f < N_FOREST; f++) {
            float4 v = *((const float4*)(g_Y + (size_t)f * (BATCH * N_CLASS)) + i);
            s.x += v.x; s.y += v.y; s.z += v.z; s.w += v.w;
        }
        out[i * 4 + 0] = s.x * (1.f / N_FOREST);
        out[i * 4 + 1] = s.y * (1.f / N_FOREST);
        out[i * 4 + 2] = s.z * (1.f / N_FOREST);
        out[i * 4 + 3] = s.w * (1.f / N_FOREST);
    }
}

// =====================================================================
extern "C" void kernel_launch(void* const* d_in, const int* in_sizes, int n_in,
                              void* d_out, int out_size) {
    const float* x     = (const float*)d_in[0];
    const float* w1    = (const float*)d_in[1];
    const float* b1    = (const float*)d_in[2];
    const int*   perm  = (const int*)  d_in[3];
    const float* gn1w  = (const float*)d_in[4];
    const float* gn1b  = (const float*)d_in[5];
    const float* c2w   = (const float*)d_in[6];
    const float* c2b   = (const float*)d_in[7];
    const float* gn2w  = (const float*)d_in[8];
    const float* gn2b  = (const float*)d_in[9];
    const float* c3w   = (const float*)d_in[10];
    const float* c3b   = (const float*)d_in[11];
    const int*   swr   = (const int*)  d_in[12];
    const float* E     = (const float*)d_in[13];
    const float* ln1w  = (const float*)d_in[14];
    const float* ln1b  = (const float*)d_in[15];
    const float* fc1w  = (const float*)d_in[16];
    const float* fc1b  = (const float*)d_in[17];
    const float* ln2w  = (const float*)d_in[18];
    const float* ln2b  = (const float*)d_in[19];
    const float* fc2w  = (const float*)d_in[20];
    const float* fc2b  = (const float*)d_in[21];
    float* out = (float*)d_out;

    cudaFuncSetAttribute(k23_forest_mlp, cudaFuncAttributeMaxDynamicSharedMemorySize, K23_SMEM);

    k0_transpose<<<(N_COL * BATCH) / 256, 256>>>(x);
    k_pre<<<(N_RODT * N_HID + 255) / 256, 256>>>(E, fc1w, ln1w, fc2w, ln2w);
    k_pre2<<<1, 128>>>(fc1w, fc1b, ln1b, fc2w, fc2b, ln2b);
    k1_rodt<<<dim3(N_RODT, BATCH / 1024), 256>>>(w1, b1, perm, gn1w, gn1b,
                                                 c2w, c2b, gn2w, gn2b, c3w, c3b);
    k23_forest_mlp<<<dim3(BATCH / 128, N_FOREST), 512, K23_SMEM>>>(swr);
    k4_reduce<<<(BATCH * N_CLASS / 4 + 255) / 256, 256>>>(out);
}

// round 12
// speedup vs baseline: 2.0290x; 1.2987x over previous
#include <cuda_runtime.h>
#include <cuda_fp16.h>
#include <cstdint>

// ---------------- problem constants ----------------
#define BATCH    4096
#define N_COL    100
#define N_COND   64
#define TOTAL    6400
#define N_RODT   1600
#define N_EST    160
#define N_FOREST 100
#define N_HID    128
#define N_CLASS  10
#define EPSV     1e-5f
#define SDH      136      // half stride per row (272B, 16B-aligned)

// ---------------- device scratch ----------------
__device__ float  g_xT  [N_COL * BATCH];
__device__ float  g_wT  [N_RODT * BATCH];
__device__ __half g_Ehf [N_RODT * N_HID];     // fp16(E)
__device__ __half g_W1hf[N_HID * N_HID];      // fp16(fc1w * ln1w) [d][o]
__device__ __half g_wc2h[N_HID * 16];         // fp16(fc2w * ln2w) [o][16] (10 used)
__device__ float  g_s1[N_HID], g_d1[N_HID];
__device__ float  g_s2[16],    g_d2[16];
__device__ float  g_Y  [(size_t)N_FOREST * BATCH * N_CLASS];

__device__ __forceinline__ void cpasync16(uint32_t dst, const void* src) {
    asm volatile("cp.async.cg.shared.global [%0], [%1], 16;" :: "r"(dst), "l"(src));
}
#define CP_COMMIT asm volatile("cp.async.commit_group;")
#define CP_WAIT0  asm volatile("cp.async.wait_group 0;")

// =====================================================================
__global__ void k0_transpose(const float* __restrict__ x) {
    int i = blockIdx.x * 256 + threadIdx.x;
    int c = i >> 12;
    int b = i & 4095;
    g_xT[i] = x[b * N_COL + c];
}

// =====================================================================
__global__ void k_pre(const float* __restrict__ E, const float* __restrict__ fc1w,
                      const float* __restrict__ ln1w, const float* __restrict__ fc2w,
                      const float* __restrict__ ln2w) {
    int i = blockIdx.x * 256 + threadIdx.x;
    if (i < N_RODT * N_HID) g_Ehf[i] = __float2half_rn(E[i]);
    if (i < N_HID * N_HID) {
        int d = i >> 7;
        g_W1hf[i] = __float2half_rn(fc1w[i] * ln1w[d]);
    }
    if (i < N_HID * 16) {
        int o = i >> 4, c = i & 15;
        g_wc2h[i] = __float2half_rn((c < 10) ? fc2w[o * 10 + c] * ln2w[o] : 0.f);
    }
}
__global__ void k_pre2(const float* __restrict__ fc1w, const float* __restrict__ fc1b,
                       const float* __restrict__ ln1b, const float* __restrict__ fc2w,
                       const float* __restrict__ fc2b, const float* __restrict__ ln2b) {
    int o = threadIdx.x;
    float ssum = 0.f, dsum = 0.f;
    for (int k = 0; k < 128; k++) {
        ssum += __half2float(g_W1hf[k * 128 + o]);
        dsum += fc1w[k * 128 + o] * ln1b[k];
    }
    g_s1[o] = ssum;
    g_d1[o] = dsum + fc1b[o];
    if (o < 10) {
        float s2 = 0.f, d2 = 0.f;
        for (int k = 0; k < 128; k++) {
            s2 += __half2float(g_wc2h[k * 16 + o]);
            d2 += ln2b[k] * fc2w[k * 10 + o];
        }
        g_s2[o] = s2;
        g_d2[o] = d2 + fc2b[o];
    } else if (o < 16) {
        g_s2[o] = 0.f; g_d2[o] = 0.f;
    }
}

// =====================================================================
// Kernel 1: condition gen + rODT scoring — 4 b's per thread
// =====================================================================
__global__ void __launch_bounds__(256, 4)
k1_rodt(const float* __restrict__ w1, const float* __restrict__ b1,
        const int*   __restrict__ perm,
        const float* __restrict__ gn1w, const float* __restrict__ gn1b,
        const float* __restrict__ c2w,  const float* __restrict__ c2b,
        const float* __restrict__ gn2w, const float* __restrict__ gn2b,
        const float* __restrict__ c3w,  const float* __restrict__ c3b) {
    int g   = blockIdx.x;
    int tid = threadIdx.x;
    __shared__ int   sc[4];
    __shared__ float sw1[4], sb1[4], sg1w[4], sg1b[4];
    __shared__ float sw2[16], sb2[4], sg2w[4], sg2b[4], sw3[4], sb3;
    if (tid < 4) {
        int t = 4 * g + tid;
        int p = perm[t];
        int c = p % N_COL;
        int j = p / N_COL;
        sc [tid] = c;
        sw1[tid] = w1[c * N_COND + j];
        sb1[tid] = b1[c * N_COND + j];
        sg1w[tid] = gn1w[t];  sg1b[tid] = gn1b[t];
        sb2 [tid] = c2b[t];
        sg2w[tid] = gn2w[t];  sg2b[tid] = gn2b[t];
        sw3 [tid] = c3w[g * 4 + tid];
    }
    if (tid < 16) sw2[tid] = c2w[g * 16 + tid];
    if (tid == 31) sb3 = c3b[g];
    __syncthreads();

    const int b = blockIdx.y * 1024 + tid * 4;
    float4 xv[4];
#pragma unroll
    for (int k = 0; k < 4; k++)
        xv[k] = *(const float4*)&g_xT[sc[k] * BATCH + b];

    float out[4];
#pragma unroll
    for (int j = 0; j < 4; j++) {
        float v[4];
#pragma unroll
        for (int k = 0; k < 4; k++) {
            float xval = (&xv[k].x)[j];
            float z = fmaf(xval, sw1[k], sb1[k]);
            v[k] = 1.f / (1.f + __expf(-z));
        }
        float mu = 0.25f * (v[0] + v[1] + v[2] + v[3]);
        float var = 0.f;
#pragma unroll
        for (int k = 0; k < 4; k++) { float d = v[k] - mu; var += d * d; }
        var *= 0.25f;
        float rs = rsqrtf(var + EPSV);
        float n[4];
#pragma unroll
        for (int k = 0; k < 4; k++) n[k] = fmaf((v[k] - mu) * rs, sg1w[k], sg1b[k]);
        float h[4];
#pragma unroll
        for (int o = 0; o < 4; o++) {
            float a = sb2[o];
#pragma unroll
            for (int k = 0; k < 4; k++) a = fmaf(n[k], sw2[k * 4 + o], a);
            h[o] = fmaxf(a, 0.f);
        }
        float mu2 = 0.25f * (h[0] + h[1] + h[2] + h[3]);
        float var2 = 0.f;
#pragma unroll
        for (int k = 0; k < 4; k++) { float d = h[k] - mu2; var2 += d * d; }
        var2 *= 0.25f;
        float rs2 = rsqrtf(var2 + EPSV);
        float wo = sb3;
#pragma unroll
        for (int k = 0; k < 4; k++)
            wo = fmaf(fmaf((h[k] - mu2) * rs2, sg2w[k], sg2b[k]), sw3[k], wo);
        out[j] = wo;
    }
    *(float4*)&g_wT[(size_t)g * BATCH + b] = make_float4(out[0], out[1], out[2], out[3]);
}

// =====================================================================
// fp16 m16n8k16 mma + ldmatrix
// =====================================================================
__device__ __forceinline__ uint32_t smaddr(const void* p) {
    return (uint32_t)__cvta_generic_to_shared(p);
}
__device__ __forceinline__ void ldsm4t(uint32_t& r0, uint32_t& r1, uint32_t& r2, uint32_t& r3,
                                       uint32_t addr) {
    asm volatile("ldmatrix.sync.aligned.m8n8.x4.trans.shared.b16 {%0,%1,%2,%3}, [%4];"
                 : "=r"(r0), "=r"(r1), "=r"(r2), "=r"(r3) : "r"(addr));
}
__device__ __forceinline__ void ldsm2t(uint32_t& r0, uint32_t& r1, uint32_t addr) {
    asm volatile("ldmatrix.sync.aligned.m8n8.x2.trans.shared.b16 {%0,%1}, [%2];"
                 : "=r"(r0), "=r"(r1) : "r"(addr));
}
__device__ __forceinline__ void mma_f16(float* c, const uint32_t* a, const uint32_t* b) {
    asm volatile("mma.sync.aligned.m16n8k16.row.col.f32.f16.f16.f32 "
                 "{%0,%1,%2,%3}, {%4,%5,%6,%7}, {%8,%9}, {%0,%1,%2,%3};"
                 : "+f"(c[0]), "+f"(c[1]), "+f"(c[2]), "+f"(c[3])
                 : "r"(a[0]), "r"(a[1]), "r"(a[2]), "r"(a[3]), "r"(b[0]), "r"(b[1]));
}

template<int KSTEPS>
__device__ __forceinline__ void gemm_h(const __half* __restrict__ Asm,
                                       const __half* __restrict__ Bsm,
                                       int warp, int lane, float acc[2][4][4]) {
    const int M0 = (warp & 3) * 32, N0 = (warp >> 2) * 32;
    const int a_k = ((lane >> 4) << 3) + (lane & 7);
    const int a_m = ((lane >> 3) & 1) << 3;
    const int b_k = (((lane >> 3) & 1) << 3) + (lane & 7);
    const int b_n = (lane >> 4) << 3;
#pragma unroll
    for (int ks = 0; ks < KSTEPS; ks++) {
        const int K0 = ks * 16;
        uint32_t afr[2][4];
#pragma unroll
        for (int mt = 0; mt < 2; mt++) {
            uint32_t addr = smaddr(Asm + (K0 + a_k) * SDH + (M0 + mt * 16 + a_m));
            ldsm4t(afr[mt][0], afr[mt][1], afr[mt][2], afr[mt][3], addr);
        }
        uint32_t bfr[4][2];
#pragma unroll
        for (int np = 0; np < 2; np++) {
            uint32_t addr = smaddr(Bsm + (K0 + b_k) * SDH + (N0 + np * 16 + b_n));
            uint32_t r0, r1, r2, r3;
            ldsm4t(r0, r1, r2, r3, addr);
            bfr[np * 2][0] = r0;     bfr[np * 2][1] = r1;
            bfr[np * 2 + 1][0] = r2; bfr[np * 2 + 1][1] = r3;
        }
#pragma unroll
        for (int mt = 0; mt < 2; mt++)
#pragma unroll
            for (int nt = 0; nt < 4; nt++) mma_f16(acc[mt][nt], afr[mt], bfr[nt]);
    }
}

// =====================================================================
// k23: fused forest GEMM + MLP, fp16 everywhere; fc2 via mma. 2 blocks/SM.
// =====================================================================
#define OFF_WH0 (160 * SDH * 2)            // 43520
#define OFF_WH1 (OFF_WH0 + 80 * SDH * 2)   // 65280
#define K23_SMEM (OFF_WH1 + 80 * SDH * 2)  // 87040
__global__ void __launch_bounds__(512, 2) k23_forest_mlp(const int* __restrict__ swr) {
    extern __shared__ char sh[];
    __half* Ph  = (__half*)sh;
    __half* Wh0 = (__half*)(sh + OFF_WH0);
    __half* Wh1 = (__half*)(sh + OFF_WH1);

    __shared__ int   s_idx[160];
    __shared__ float s_invS[128];
    __shared__ float s_scratch[2048];          // s_part(16x128) OR redA(8x128)+redB(8x128)
    __shared__ float s_mu[128], s_rs[128];
    __shared__ float s_s1[128], s_d1[128];
    __shared__ __align__(16) __half s_wc2h[128 * 16];
    __shared__ float s_s2[16], s_d2[16];

    float* s_part = s_scratch;
    float* s_redA = s_scratch;
    float* s_redB = s_scratch + 1024;

    const int tid = threadIdx.x, lane = tid & 31, warp = tid >> 5;
    const int f = blockIdx.y;
    const int b0 = blockIdx.x * 128;

    if (tid < 160) s_idx[tid] = swr[f * N_EST + tid];
    __syncthreads();

    // ---- issue E half0 via cp.async ----
    {
        uint32_t wb0 = (uint32_t)__cvta_generic_to_shared(Wh0);
#pragma unroll
        for (int i = tid; i < 80 * 16; i += 512) {
            int e = i >> 4, q = i & 15;
            cpasync16(wb0 + e * (SDH * 2) + q * 16, g_Ehf + (size_t)s_idx[e] * N_HID + q * 8);
        }
        CP_COMMIT;
    }

    // ---- stage P = fp16(exp(w)) with fused invS partials ----
    {
        float p0 = 0.f, p1 = 0.f, p2 = 0.f, p3 = 0.f;
        const int b4 = tid & 31;
#pragma unroll
        for (int j = 0; j < 10; j++) {
            int e = (tid >> 5) + 16 * j;
            float4 v = *(const float4*)(g_wT + (size_t)s_idx[e] * BATCH + b0 + b4 * 4);
            __half2 h01 = __floats2half2_rn(__expf(v.x), __expf(v.y));
            __half2 h23 = __floats2half2_rn(__expf(v.z), __expf(v.w));
            __half2* dst = (__half2*)(Ph + e * SDH + b4 * 4);
            dst[0] = h01; dst[1] = h23;
            float2 f01 = __half22float2(h01), f23 = __half22float2(h23);
            p0 += f01.x; p1 += f01.y; p2 += f23.x; p3 += f23.y;
        }
        float* pp = s_part + warp * 128 + b4 * 4;
        pp[0] = p0; pp[1] = p1; pp[2] = p2; pp[3] = p3;
    }
    if (tid < 128) { s_s1[tid] = g_s1[tid]; s_d1[tid] = g_d1[tid]; }
    // stage wc2h (2048 halves = 256 uint4)
    if (tid < 256) ((uint4*)s_wc2h)[tid] = ((const uint4*)g_wc2h)[tid];
    if (tid < 16) { s_s2[tid] = g_s2[tid]; s_d2[tid] = g_d2[tid]; }
    CP_WAIT0;
    __syncthreads();

    // ---- issue E half1 -> Wh1 ----
    {
        uint32_t wb1 = (uint32_t)__cvta_generic_to_shared(Wh1);
#pragma unroll
        for (int i = tid; i < 80 * 16; i += 512) {
            int e = i >> 4, q = i & 15;
            cpasync16(wb1 + e * (SDH * 2) + q * 16, g_Ehf + (size_t)s_idx[80 + e] * N_HID + q * 8);
        }
        CP_COMMIT;
    }

    // ---- invS finalize ----
    if (tid < 128) {
        float s = 0.f;
#pragma unroll
        for (int w = 0; w < 16; w++) s += s_part[w * 128 + tid];
        s_invS[tid] = 1.f / s;
    }

    // ---- GEMM A: K=160, two halves ----
    float acc[2][4][4];
#pragma unroll
    for (int mt = 0; mt < 2; mt++)
#pragma unroll
        for (int nt = 0; nt < 4; nt++)
#pragma unroll
            for (int r = 0; r < 4; r++) acc[mt][nt][r] = 0.f;
    gemm_h<5>(Wh0, Ph, warp, lane, acc);
    CP_WAIT0;
    __syncthreads();
    // prefetch W1' half0 into Wh0
    {
        uint32_t wb0 = (uint32_t)__cvta_generic_to_shared(Wh0);
#pragma unroll
        for (int i = tid; i < 64 * 16; i += 512) {
            int k = i >> 4, q = i & 15;
            cpasync16(wb0 + k * (SDH * 2) + q * 16, g_W1hf + k * N_HID + q * 8);
        }
        CP_COMMIT;
    }
    gemm_h<5>(Wh1, Ph + 80 * SDH, warp, lane, acc);
    __syncthreads();   // all P reads done before overwrite
    // prefetch W1' half1 into Wh1
    {
        uint32_t wb1 = (uint32_t)__cvta_generic_to_shared(Wh1);
#pragma unroll
        for (int i = tid; i < 64 * 16; i += 512) {
            int k = i >> 4, q = i & 15;
            cpasync16(wb1 + k * (SDH * 2) + q * 16, g_W1hf + (64 + k) * N_HID + q * 8);
        }
        CP_COMMIT;
    }
    // epilogue A: C~ = fp16(acc * invS) -> Ph rows 0..127
    {
        const int M0 = (warp & 3) * 32, N0 = (warp >> 2) * 32;
        const int g = lane >> 2, q2 = (lane & 3) * 2;
#pragma unroll
        for (int mt = 0; mt < 2; mt++)
#pragma unroll
            for (int nt = 0; nt < 4; nt++) {
                int row = M0 + mt * 16 + g, col = N0 + nt * 8 + q2;
                float i0 = s_invS[col], i1 = s_invS[col + 1];
                *(__half2*)(Ph + row * SDH + col) =
                    __floats2half2_rn(acc[mt][nt][0] * i0, acc[mt][nt][1] * i1);
                *(__half2*)(Ph + (row + 8) * SDH + col) =
                    __floats2half2_rn(acc[mt][nt][2] * i0, acc[mt][nt][3] * i1);
            }
    }
    CP_WAIT0;
    __syncthreads();

    // ---- stats1: per-column mean/rstd of C~ (half2, 8-way row split) ----
    {
        const int c2 = (tid & 63) * 2, q = tid >> 6;
        float s0 = 0.f, s1v = 0.f, q0 = 0.f, q1 = 0.f;
#pragma unroll 4
        for (int r = 0; r < 16; r++) {
            float2 fv = __half22float2(*(__half2*)(Ph + (q * 16 + r) * SDH + c2));
            s0 += fv.x; s1v += fv.y;
            q0 = fmaf(fv.x, fv.x, q0); q1 = fmaf(fv.y, fv.y, q1);
        }
        s_redA[q * 128 + c2] = s0;  s_redA[q * 128 + c2 + 1] = s1v;
        s_redB[q * 128 + c2] = q0;  s_redB[q * 128 + c2 + 1] = q1;
    }
    __syncthreads();
    if (tid < 128) {
        float s = 0.f, s2 = 0.f;
#pragma unroll
        for (int w = 0; w < 8; w++) { s += s_redA[w * 128 + tid]; s2 += s_redB[w * 128 + tid]; }
        float mu = s * (1.f / 128.f);
        float var = fmaxf(s2 * (1.f / 128.f) - mu * mu, 0.f);
        s_mu[tid] = mu;
        s_rs[tid] = rsqrtf(var + EPSV);
    }
    __syncthreads();

    // ---- GEMM B: K=128, two halves ----
#pragma unroll
    for (int mt = 0; mt < 2; mt++)
#pragma unroll
        for (int nt = 0; nt < 4; nt++)
#pragma unroll
            for (int r = 0; r < 4; r++) acc[mt][nt][r] = 0.f;
    gemm_h<4>(Wh0, Ph, warp, lane, acc);
    gemm_h<4>(Wh1, Ph + 64 * SDH, warp, lane, acc);
    __syncthreads();   // all C~ reads done before overwrite

    // epilogue B: H = fp16(relu(rs*(G - mu*s1) + d1)) -> Ph rows 0..127
    {
        const int M0 = (warp & 3) * 32, N0 = (warp >> 2) * 32;
        const int g = lane >> 2, q2 = (lane & 3) * 2;
#pragma unroll
        for (int mt = 0; mt < 2; mt++)
#pragma unroll
            for (int nt = 0; nt < 4; nt++) {
                int row = M0 + mt * 16 + g, col = N0 + nt * 8 + q2;
                float s1a = s_s1[row], d1a = s_d1[row];
                float s1b = s_s1[row + 8], d1b = s_d1[row + 8];
                float mu0 = s_mu[col], rs0 = s_rs[col];
                float mu1 = s_mu[col + 1], rs1 = s_rs[col + 1];
                *(__half2*)(Ph + row * SDH + col) = __floats2half2_rn(
                    fmaxf(fmaf(rs0, acc[mt][nt][0] - mu0 * s1a, d1a), 0.f),
                    fmaxf(fmaf(rs1, acc[mt][nt][1] - mu1 * s1a, d1a), 0.f));
                *(__half2*)(Ph + (row + 8) * SDH + col) = __floats2half2_rn(
                    fmaxf(fmaf(rs0, acc[mt][nt][2] - mu0 * s1b, d1b), 0.f),
                    fmaxf(fmaf(rs1, acc[mt][nt][3] - mu1 * s1b, d1b), 0.f));
            }
    }
    __syncthreads();

    // ---- stats2 on fp16 H (half2) ----
    {
        const int c2 = (tid & 63) * 2, q = tid >> 6;
        float s0 = 0.f, s1v = 0.f, q0 = 0.f, q1 = 0.f;
#pragma unroll 4
        for (int r = 0; r < 16; r++) {
            float2 fv = __half22float2(*(__half2*)(Ph + (q * 16 + r) * SDH + c2));
            s0 += fv.x; s1v += fv.y;
            q0 = fmaf(fv.x, fv.x, q0); q1 = fmaf(fv.y, fv.y, q1);
        }
        s_redA[q * 128 + c2] = s0;  s_redA[q * 128 + c2 + 1] = s1v;
        s_redB[q * 128 + c2] = q0;  s_redB[q * 128 + c2 + 1] = q1;
    }
    __syncthreads();
    if (tid < 128) {
        float s = 0.f, s2 = 0.f;
#pragma unroll
        for (int w = 0; w < 8; w++) { s += s_redA[w * 128 + tid]; s2 += s_redB[w * 128 + tid]; }
        float mu = s * (1.f / 128.f);
        float var = fmaxf(s2 * (1.f / 128.f) - mu * mu, 0.f);
        s_mu[tid] = mu;
        s_rs[tid] = rsqrtf(var + EPSV);
    }
    __syncthreads();

    // ---- fc2 via mma: S^T[c=16][b=128] = wc2h^T H; LN2 folded epilogue ----
    {
        float a2[4] = {0.f, 0.f, 0.f, 0.f};
        const int N0 = warp * 8;
        const int a_k = ((lane >> 4) << 3) + (lane & 7);
        const int a_m = ((lane >> 3) & 1) << 3;
        const int b_k = lane & 15;
#pragma unroll
        for (int ks = 0; ks < 8; ks++) {
            const int K0 = ks * 16;
            uint32_t af[4];
            ldsm4t(af[0], af[1], af[2], af[3], smaddr(s_wc2h + (K0 + a_k) * 16 + a_m));
            uint32_t bf[2];
            ldsm2t(bf[0], bf[1], smaddr(Ph + (K0 + b_k) * SDH + N0));
            mma_f16(a2, af, bf);
        }
        const int g = lane >> 2, q2 = (lane & 3) * 2;
        const int bb = N0 + q2;
        float rs2a = s_rs[bb],     mu2a = s_mu[bb];
        float rs2b = s_rs[bb + 1], mu2b = s_mu[bb + 1];
        size_t Rb = ((size_t)f * BATCH + b0 + bb) * N_CLASS;
        {
            int c = g;   // 0..7, always valid
            g_Y[Rb + c]           = fmaf(rs2a, a2[0] - mu2a * s_s2[c], s_d2[c]);
            g_Y[Rb + N_CLASS + c] = fmaf(rs2b, a2[1] - mu2b * s_s2[c], s_d2[c]);
        }
        if (g < 2) {
            int c = g + 8;   // 8,9
            g_Y[Rb + c]           = fmaf(rs2a, a2[2] - mu2a * s_s2[c], s_d2[c]);
            g_Y[Rb + N_CLASS + c] = fmaf(rs2b, a2[3] - mu2b * s_s2[c], s_d2[c]);
        }
    }
}

// =====================================================================
__global__ void k4_reduce(float* __restrict__ out) {
    int i = blockIdx.x * 256 + threadIdx.x;
    if (i < BATCH * N_CLASS / 4) {
        float4 s = make_float4(0.f, 0.f, 0.f, 0.f);
        for (int f = 0; f < N_FOREST; f++) {
            float4 v = *((const float4*)(g_Y + (size_t)f * (BATCH * N_CLASS)) + i);
            s.x += v.x; s.y += v.y; s.z += v.z; s.w += v.w;
        }
        out[i * 4 + 0] = s.x * (1.f / N_FOREST);
        out[i * 4 + 1] = s.y * (1.f / N_FOREST);
        out[i * 4 + 2] = s.z * (1.f / N_FOREST);
        out[i * 4 + 3] = s.w * (1.f / N_FOREST);
    }
}

// =====================================================================
extern "C" void kernel_launch(void* const* d_in, const int* in_sizes, int n_in,
                              void* d_out, int out_size) {
    const float* x     = (const float*)d_in[0];
    const float* w1    = (const float*)d_in[1];
    const float* b1    = (const float*)d_in[2];
    const int*   perm  = (const int*)  d_in[3];
    const float* gn1w  = (const float*)d_in[4];
    const float* gn1b  = (const float*)d_in[5];
    const float* c2w   = (const float*)d_in[6];
    const float* c2b   = (const float*)d_in[7];
    const float* gn2w  = (const float*)d_in[8];
    const float* gn2b  = (const float*)d_in[9];
    const float* c3w   = (const float*)d_in[10];
    const float* c3b   = (const float*)d_in[11];
    const int*   swr   = (const int*)  d_in[12];
    const float* E     = (const float*)d_in[13];
    const float* ln1w  = (const float*)d_in[14];
    const float* ln1b  = (const float*)d_in[15];
    const float* fc1w  = (const float*)d_in[16];
    const float* fc1b  = (const float*)d_in[17];
    const float* ln2w  = (const float*)d_in[18];
    const float* ln2b  = (const float*)d_in[19];
    const float* fc2w  = (const float*)d_in[20];
    const float* fc2b  = (const float*)d_in[21];
    float* out = (float*)d_out;

    cudaFuncSetAttribute(k23_forest_mlp, cudaFuncAttributeMaxDynamicSharedMemorySize, K23_SMEM);

    k0_transpose<<<(N_COL * BATCH) / 256, 256>>>(x);
    k_pre<<<(N_RODT * N_HID + 255) / 256, 256>>>(E, fc1w, ln1w, fc2w, ln2w);
    k_pre2<<<1, 128>>>(fc1w, fc1b, ln1b, fc2w, fc2b, ln2b);
    k1_rodt<<<dim3(N_RODT, BATCH / 1024), 256>>>(w1, b1, perm, gn1w, gn1b,
                                                 c2w, c2b, gn2w, gn2b, c3w, c3b);
    k23_forest_mlp<<<dim3(BATCH / 128, N_FOREST), 512, K23_SMEM>>>(swr);
    k4_reduce<<<(BATCH * N_CLASS / 4 + 255) / 256, 256>>>(out);
}

// round 13
// speedup vs baseline: 2.1228x; 1.0462x over previous
#include <cuda_runtime.h>
#include <cuda_fp16.h>
#include <cstdint>

// ---------------- problem constants ----------------
#define BATCH    4096
#define N_COL    100
#define N_COND   64
#define TOTAL    6400
#define N_RODT   1600
#define N_EST    160
#define N_FOREST 100
#define N_HID    128
#define N_CLASS  10
#define EPSV     1e-5f
#define SDH      136      // half stride per row (272B, 16B-aligned)

// ---------------- device scratch ----------------
__device__ float  g_xT  [N_COL * BATCH];
__device__ float  g_wT  [N_RODT * BATCH];
__device__ __half g_Ehf [N_RODT * N_HID];     // fp16(E)
__device__ __half g_W1hf[N_HID * N_HID];      // fp16(fc1w * ln1w) [d][o]
__device__ __half g_wc2h[N_HID * 16];         // fp16(fc2w * ln2w) [o][16] (10 used)
__device__ float  g_s1[N_HID], g_d1[N_HID];
__device__ float  g_s2[16],    g_d2[16];
__device__ __half g_Yh [(size_t)N_FOREST * BATCH * N_CLASS];   // per-forest logits fp16

__device__ __forceinline__ void cpasync16(uint32_t dst, const void* src) {
    asm volatile("cp.async.cg.shared.global [%0], [%1], 16;" :: "r"(dst), "l"(src));
}
#define CP_COMMIT asm volatile("cp.async.commit_group;")
#define CP_WAIT0  asm volatile("cp.async.wait_group 0;")

__device__ __forceinline__ float fast_sigmoid(float z) {
    float t;
    asm("tanh.approx.f32 %0, %1;" : "=f"(t) : "f"(z * 0.5f));
    return fmaf(0.5f, t, 0.5f);
}

// =====================================================================
__global__ void k0_transpose(const float* __restrict__ x) {
    int i = blockIdx.x * 256 + threadIdx.x;
    int c = i >> 12;
    int b = i & 4095;
    g_xT[i] = x[b * N_COL + c];
}

// =====================================================================
__global__ void k_pre(const float* __restrict__ E, const float* __restrict__ fc1w,
                      const float* __restrict__ ln1w, const float* __restrict__ fc2w,
                      const float* __restrict__ ln2w) {
    int i = blockIdx.x * 256 + threadIdx.x;
    if (i < N_RODT * N_HID) g_Ehf[i] = __float2half_rn(E[i]);
    if (i < N_HID * N_HID) {
        int d = i >> 7;
        g_W1hf[i] = __float2half_rn(fc1w[i] * ln1w[d]);
    }
    if (i < N_HID * 16) {
        int o = i >> 4, c = i & 15;
        g_wc2h[i] = __float2half_rn((c < 10) ? fc2w[o * 10 + c] * ln2w[o] : 0.f);
    }
}
__global__ void k_pre2(const float* __restrict__ fc1w, const float* __restrict__ fc1b,
                       const float* __restrict__ ln1b, const float* __restrict__ fc2w,
                       const float* __restrict__ fc2b, const float* __restrict__ ln2b) {
    int o = threadIdx.x;
    float ssum = 0.f, dsum = 0.f;
    for (int k = 0; k < 128; k++) {
        ssum += __half2float(g_W1hf[k * 128 + o]);
        dsum += fc1w[k * 128 + o] * ln1b[k];
    }
    g_s1[o] = ssum;
    g_d1[o] = dsum + fc1b[o];
    if (o < 10) {
        float s2 = 0.f, d2 = 0.f;
        for (int k = 0; k < 128; k++) {
            s2 += __half2float(g_wc2h[k * 16 + o]);
            d2 += ln2b[k] * fc2w[k * 10 + o];
        }
        g_s2[o] = s2;
        g_d2[o] = d2 + fc2b[o];
    } else if (o < 16) {
        g_s2[o] = 0.f; g_d2[o] = 0.f;
    }
}

// =====================================================================
// Kernel 1: condition gen + rODT scoring — 4 b's per thread, tanh sigmoid
// =====================================================================
__global__ void __launch_bounds__(256, 4)
k1_rodt(const float* __restrict__ w1, const float* __restrict__ b1,
        const int*   __restrict__ perm,
        const float* __restrict__ gn1w, const float* __restrict__ gn1b,
        const float* __restrict__ c2w,  const float* __restrict__ c2b,
        const float* __restrict__ gn2w, const float* __restrict__ gn2b,
        const float* __restrict__ c3w,  const float* __restrict__ c3b) {
    int g   = blockIdx.x;
    int tid = threadIdx.x;
    __shared__ int   sc[4];
    __shared__ float sw1[4], sb1[4], sg1w[4], sg1b[4];
    __shared__ float sw2[16], sb2[4], sg2w[4], sg2b[4], sw3[4], sb3;
    if (tid < 4) {
        int t = 4 * g + tid;
        int p = perm[t];
        int c = p % N_COL;
        int j = p / N_COL;
        sc [tid] = c;
        sw1[tid] = w1[c * N_COND + j];
        sb1[tid] = b1[c * N_COND + j];
        sg1w[tid] = gn1w[t];  sg1b[tid] = gn1b[t];
        sb2 [tid] = c2b[t];
        sg2w[tid] = gn2w[t];  sg2b[tid] = gn2b[t];
        sw3 [tid] = c3w[g * 4 + tid];
    }
    if (tid < 16) sw2[tid] = c2w[g * 16 + tid];
    if (tid == 31) sb3 = c3b[g];
    __syncthreads();

    const int b = blockIdx.y * 1024 + tid * 4;
    float4 xv[4];
#pragma unroll
    for (int k = 0; k < 4; k++)
        xv[k] = *(const float4*)&g_xT[sc[k] * BATCH + b];

    float out[4];
#pragma unroll
    for (int j = 0; j < 4; j++) {
        float v[4];
#pragma unroll
        for (int k = 0; k < 4; k++) {
            float xval = (&xv[k].x)[j];
            float z = fmaf(xval, sw1[k], sb1[k]);
            v[k] = fast_sigmoid(z);
        }
        float mu = 0.25f * (v[0] + v[1] + v[2] + v[3]);
        float var = 0.f;
#pragma unroll
        for (int k = 0; k < 4; k++) { float d = v[k] - mu; var += d * d; }
        var *= 0.25f;
        float rs = rsqrtf(var + EPSV);
        float n[4];
#pragma unroll
        for (int k = 0; k < 4; k++) n[k] = fmaf((v[k] - mu) * rs, sg1w[k], sg1b[k]);
        float h[4];
#pragma unroll
        for (int o = 0; o < 4; o++) {
            float a = sb2[o];
#pragma unroll
            for (int k = 0; k < 4; k++) a = fmaf(n[k], sw2[k * 4 + o], a);
            h[o] = fmaxf(a, 0.f);
        }
        float mu2 = 0.25f * (h[0] + h[1] + h[2] + h[3]);
        float var2 = 0.f;
#pragma unroll
        for (int k = 0; k < 4; k++) { float d = h[k] - mu2; var2 += d * d; }
        var2 *= 0.25f;
        float rs2 = rsqrtf(var2 + EPSV);
        float wo = sb3;
#pragma unroll
        for (int k = 0; k < 4; k++)
            wo = fmaf(fmaf((h[k] - mu2) * rs2, sg2w[k], sg2b[k]), sw3[k], wo);
        out[j] = wo;
    }
    *(float4*)&g_wT[(size_t)g * BATCH + b] = make_float4(out[0], out[1], out[2], out[3]);
}

// =====================================================================
// fp16 m16n8k16 mma + ldmatrix
// =====================================================================
__device__ __forceinline__ uint32_t smaddr(const void* p) {
    return (uint32_t)__cvta_generic_to_shared(p);
}
__device__ __forceinline__ void ldsm4t(uint32_t& r0, uint32_t& r1, uint32_t& r2, uint32_t& r3,
                                       uint32_t addr) {
    asm volatile("ldmatrix.sync.aligned.m8n8.x4.trans.shared.b16 {%0,%1,%2,%3}, [%4];"
                 : "=r"(r0), "=r"(r1), "=r"(r2), "=r"(r3) : "r"(addr));
}
__device__ __forceinline__ void ldsm2t(uint32_t& r0, uint32_t& r1, uint32_t addr) {
    asm volatile("ldmatrix.sync.aligned.m8n8.x2.trans.shared.b16 {%0,%1}, [%2];"
                 : "=r"(r0), "=r"(r1) : "r"(addr));
}
__device__ __forceinline__ void mma_f16(float* c, const uint32_t* a, const uint32_t* b) {
    asm volatile("mma.sync.aligned.m16n8k16.row.col.f32.f16.f16.f32 "
                 "{%0,%1,%2,%3}, {%4,%5,%6,%7}, {%8,%9}, {%0,%1,%2,%3};"
                 : "+f"(c[0]), "+f"(c[1]), "+f"(c[2]), "+f"(c[3])
                 : "r"(a[0]), "r"(a[1]), "r"(a[2]), "r"(a[3]), "r"(b[0]), "r"(b[1]));
}

template<int KSTEPS>
__device__ __forceinline__ void gemm_h(const __half* __restrict__ Asm,
                                       const __half* __restrict__ Bsm,
                                       int warp, int lane, float acc[2][4][4]) {
    const int M0 = (warp & 3) * 32, N0 = (warp >> 2) * 32;
    const int a_k = ((lane >> 4) << 3) + (lane & 7);
    const int a_m = ((lane >> 3) & 1) << 3;
    const int b_k = (((lane >> 3) & 1) << 3) + (lane & 7);
    const int b_n = (lane >> 4) << 3;
#pragma unroll
    for (int ks = 0; ks < KSTEPS; ks++) {
        const int K0 = ks * 16;
        uint32_t afr[2][4];
#pragma unroll
        for (int mt = 0; mt < 2; mt++) {
            uint32_t addr = smaddr(Asm + (K0 + a_k) * SDH + (M0 + mt * 16 + a_m));
            ldsm4t(afr[mt][0], afr[mt][1], afr[mt][2], afr[mt][3], addr);
        }
        uint32_t bfr[4][2];
#pragma unroll
        for (int np = 0; np < 2; np++) {
            uint32_t addr = smaddr(Bsm + (K0 + b_k) * SDH + (N0 + np * 16 + b_n));
            uint32_t r0, r1, r2, r3;
            ldsm4t(r0, r1, r2, r3, addr);
            bfr[np * 2][0] = r0;     bfr[np * 2][1] = r1;
            bfr[np * 2 + 1][0] = r2; bfr[np * 2 + 1][1] = r3;
        }
#pragma unroll
        for (int mt = 0; mt < 2; mt++)
#pragma unroll
            for (int nt = 0; nt < 4; nt++) mma_f16(acc[mt][nt], afr[mt], bfr[nt]);
    }
}

// =====================================================================
// k23: fused forest GEMM + MLP, fp16 everywhere; fc2 via mma. 2 blocks/SM.
// =====================================================================
#define OFF_WH0 (160 * SDH * 2)            // 43520
#define OFF_WH1 (OFF_WH0 + 80 * SDH * 2)   // 65280
#define K23_SMEM (OFF_WH1 + 80 * SDH * 2)  // 87040
__global__ void __launch_bounds__(512, 2) k23_forest_mlp(const int* __restrict__ swr) {
    extern __shared__ char sh[];
    __half* Ph  = (__half*)sh;
    __half* Wh0 = (__half*)(sh + OFF_WH0);
    __half* Wh1 = (__half*)(sh + OFF_WH1);

    __shared__ int   s_idx[160];
    __shared__ float s_invS[128];
    __shared__ float s_scratch[2048];          // s_part(16x128) OR redA(8x128)+redB(8x128)
    __shared__ float s_mu[128], s_rs[128];
    __shared__ float s_s1[128], s_d1[128];
    __shared__ __align__(16) __half s_wc2h[128 * 16];
    __shared__ float s_s2[16], s_d2[16];

    float* s_part = s_scratch;
    float* s_redA = s_scratch;
    float* s_redB = s_scratch + 1024;

    const int tid = threadIdx.x, lane = tid & 31, warp = tid >> 5;
    const int f = blockIdx.y;
    const int b0 = blockIdx.x * 128;

    if (tid < 160) s_idx[tid] = swr[f * N_EST + tid];
    __syncthreads();

    // ---- issue E half0 via cp.async ----
    {
        uint32_t wb0 = (uint32_t)__cvta_generic_to_shared(Wh0);
#pragma unroll
        for (int i = tid; i < 80 * 16; i += 512) {
            int e = i >> 4, q = i & 15;
            cpasync16(wb0 + e * (SDH * 2) + q * 16, g_Ehf + (size_t)s_idx[e] * N_HID + q * 8);
        }
        CP_COMMIT;
    }

    // ---- stage P = fp16(exp(w)) with fused invS partials ----
    {
        float p0 = 0.f, p1 = 0.f, p2 = 0.f, p3 = 0.f;
        const int b4 = tid & 31;
#pragma unroll
        for (int j = 0; j < 10; j++) {
            int e = (tid >> 5) + 16 * j;
            float4 v = *(const float4*)(g_wT + (size_t)s_idx[e] * BATCH + b0 + b4 * 4);
            __half2 h01 = __floats2half2_rn(__expf(v.x), __expf(v.y));
            __half2 h23 = __floats2half2_rn(__expf(v.z), __expf(v.w));
            __half2* dst = (__half2*)(Ph + e * SDH + b4 * 4);
            dst[0] = h01; dst[1] = h23;
            float2 f01 = __half22float2(h01), f23 = __half22float2(h23);
            p0 += f01.x; p1 += f01.y; p2 += f23.x; p3 += f23.y;
        }
        float* pp = s_part + warp * 128 + b4 * 4;
        pp[0] = p0; pp[1] = p1; pp[2] = p2; pp[3] = p3;
    }
    if (tid < 128) { s_s1[tid] = g_s1[tid]; s_d1[tid] = g_d1[tid]; }
    if (tid < 256) ((uint4*)s_wc2h)[tid] = ((const uint4*)g_wc2h)[tid];
    if (tid < 16) { s_s2[tid] = g_s2[tid]; s_d2[tid] = g_d2[tid]; }
    CP_WAIT0;
    __syncthreads();

    // ---- issue E half1 -> Wh1 ----
    {
        uint32_t wb1 = (uint32_t)__cvta_generic_to_shared(Wh1);
#pragma unroll
        for (int i = tid; i < 80 * 16; i += 512) {
            int e = i >> 4, q = i & 15;
            cpasync16(wb1 + e * (SDH * 2) + q * 16, g_Ehf + (size_t)s_idx[80 + e] * N_HID + q * 8);
        }
        CP_COMMIT;
    }

    // ---- invS finalize ----
    if (tid < 128) {
        float s = 0.f;
#pragma unroll
        for (int w = 0; w < 16; w++) s += s_part[w * 128 + tid];
        s_invS[tid] = 1.f / s;
    }

    // ---- GEMM A: K=160, two halves ----
    float acc[2][4][4];
#pragma unroll
    for (int mt = 0; mt < 2; mt++)
#pragma unroll
        for (int nt = 0; nt < 4; nt++)
#pragma unroll
            for (int r = 0; r < 4; r++) acc[mt][nt][r] = 0.f;
    gemm_h<5>(Wh0, Ph, warp, lane, acc);
    CP_WAIT0;
    __syncthreads();
    // prefetch W1' half0 into Wh0
    {
        uint32_t wb0 = (uint32_t)__cvta_generic_to_shared(Wh0);
#pragma unroll
        for (int i = tid; i < 64 * 16; i += 512) {
            int k = i >> 4, q = i & 15;
            cpasync16(wb0 + k * (SDH * 2) + q * 16, g_W1hf + k * N_HID + q * 8);
        }
        CP_COMMIT;
    }
    gemm_h<5>(Wh1, Ph + 80 * SDH, warp, lane, acc);
    __syncthreads();   // all P reads done before overwrite
    // prefetch W1' half1 into Wh1
    {
        uint32_t wb1 = (uint32_t)__cvta_generic_to_shared(Wh1);
#pragma unroll
        for (int i = tid; i < 64 * 16; i += 512) {
            int k = i >> 4, q = i & 15;
            cpasync16(wb1 + k * (SDH * 2) + q * 16, g_W1hf + (64 + k) * N_HID + q * 8);
        }
        CP_COMMIT;
    }
    // epilogue A: C~ = fp16(acc * invS) -> Ph rows 0..127
    {
        const int M0 = (warp & 3) * 32, N0 = (warp >> 2) * 32;
        const int g = lane >> 2, q2 = (lane & 3) * 2;
#pragma unroll
        for (int mt = 0; mt < 2; mt++)
#pragma unroll
            for (int nt = 0; nt < 4; nt++) {
                int row = M0 + mt * 16 + g, col = N0 + nt * 8 + q2;
                float i0 = s_invS[col], i1 = s_invS[col + 1];
                *(__half2*)(Ph + row * SDH + col) =
                    __floats2half2_rn(acc[mt][nt][0] * i0, acc[mt][nt][1] * i1);
                *(__half2*)(Ph + (row + 8) * SDH + col) =
                    __floats2half2_rn(acc[mt][nt][2] * i0, acc[mt][nt][3] * i1);
            }
    }
    CP_WAIT0;
    __syncthreads();

    // ---- stats1 (half2, 8-way row split) ----
    {
        const int c2 = (tid & 63) * 2, q = tid >> 6;
        float s0 = 0.f, s1v = 0.f, q0 = 0.f, q1 = 0.f;
#pragma unroll 4
        for (int r = 0; r < 16; r++) {
            float2 fv = __half22float2(*(__half2*)(Ph + (q * 16 + r) * SDH + c2));
            s0 += fv.x; s1v += fv.y;
            q0 = fmaf(fv.x, fv.x, q0); q1 = fmaf(fv.y, fv.y, q1);
        }
        s_redA[q * 128 + c2] = s0;  s_redA[q * 128 + c2 + 1] = s1v;
        s_redB[q * 128 + c2] = q0;  s_redB[q * 128 + c2 + 1] = q1;
    }
    __syncthreads();
    if (tid < 128) {
        float s = 0.f, s2 = 0.f;
#pragma unroll
        for (int w = 0; w < 8; w++) { s += s_redA[w * 128 + tid]; s2 += s_redB[w * 128 + tid]; }
        float mu = s * (1.f / 128.f);
        float var = fmaxf(s2 * (1.f / 128.f) - mu * mu, 0.f);
        s_mu[tid] = mu;
        s_rs[tid] = rsqrtf(var + EPSV);
    }
    __syncthreads();

    // ---- GEMM B: K=128, two halves ----
#pragma unroll
    for (int mt = 0; mt < 2; mt++)
#pragma unroll
        for (int nt = 0; nt < 4; nt++)
#pragma unroll
            for (int r = 0; r < 4; r++) acc[mt][nt][r] = 0.f;
    gemm_h<4>(Wh0, Ph, warp, lane, acc);
    gemm_h<4>(Wh1, Ph + 64 * SDH, warp, lane, acc);
    __syncthreads();   // all C~ reads done before overwrite

    // epilogue B: H = fp16(relu(rs*(G - mu*s1) + d1)) -> Ph rows 0..127
    {
        const int M0 = (warp & 3) * 32, N0 = (warp >> 2) * 32;
        const int g = lane >> 2, q2 = (lane & 3) * 2;
#pragma unroll
        for (int mt = 0; mt < 2; mt++)
#pragma unroll
            for (int nt = 0; nt < 4; nt++) {
                int row = M0 + mt * 16 + g, col = N0 + nt * 8 + q2;
                float s1a = s_s1[row], d1a = s_d1[row];
                float s1b = s_s1[row + 8], d1b = s_d1[row + 8];
                float mu0 = s_mu[col], rs0 = s_rs[col];
                float mu1 = s_mu[col + 1], rs1 = s_rs[col + 1];
                *(__half2*)(Ph + row * SDH + col) = __floats2half2_rn(
                    fmaxf(fmaf(rs0, acc[mt][nt][0] - mu0 * s1a, d1a), 0.f),
                    fmaxf(fmaf(rs1, acc[mt][nt][1] - mu1 * s1a, d1a), 0.f));
                *(__half2*)(Ph + (row + 8) * SDH + col) = __floats2half2_rn(
                    fmaxf(fmaf(rs0, acc[mt][nt][2] - mu0 * s1b, d1b), 0.f),
                    fmaxf(fmaf(rs1, acc[mt][nt][3] - mu1 * s1b, d1b), 0.f));
            }
    }
    __syncthreads();

    // ---- stats2 on fp16 H (half2) ----
    {
        const int c2 = (tid & 63) * 2, q = tid >> 6;
        float s0 = 0.f, s1v = 0.f, q0 = 0.f, q1 = 0.f;
#pragma unroll 4
        for (int r = 0; r < 16; r++) {
            float2 fv = __half22float2(*(__half2*)(Ph + (q * 16 + r) * SDH + c2));
            s0 += fv.x; s1v += fv.y;
            q0 = fmaf(fv.x, fv.x, q0); q1 = fmaf(fv.y, fv.y, q1);
        }
        s_redA[q * 128 + c2] = s0;  s_redA[q * 128 + c2 + 1] = s1v;
        s_redB[q * 128 + c2] = q0;  s_redB[q * 128 + c2 + 1] = q1;
    }
    __syncthreads();
    if (tid < 128) {
        float s = 0.f, s2 = 0.f;
#pragma unroll
        for (int w = 0; w < 8; w++) { s += s_redA[w * 128 + tid]; s2 += s_redB[w * 128 + tid]; }
        float mu = s * (1.f / 128.f);
        float var = fmaxf(s2 * (1.f / 128.f) - mu * mu, 0.f);
        s_mu[tid] = mu;
        s_rs[tid] = rsqrtf(var + EPSV);
    }
    __syncthreads();

    // ---- fc2 via mma: S^T[c=16][b=128] = wc2h^T H; LN2 folded epilogue ----
    {
        float a2[4] = {0.f, 0.f, 0.f, 0.f};
        const int N0 = warp * 8;
        const int a_k = ((lane >> 4) << 3) + (lane & 7);
        const int a_m = ((lane >> 3) & 1) << 3;
        const int b_k = lane & 15;
#pragma unroll
        for (int ks = 0; ks < 8; ks++) {
            const int K0 = ks * 16;
            uint32_t af[4];
            ldsm4t(af[0], af[1], af[2], af[3], smaddr(s_wc2h + (K0 + a_k) * 16 + a_m));
            uint32_t bf[2];
            ldsm2t(bf[0], bf[1], smaddr(Ph + (K0 + b_k) * SDH + N0));
            mma_f16(a2, af, bf);
        }
        const int g = lane >> 2, q2 = (lane & 3) * 2;
        const int bb = N0 + q2;
        float rs2a = s_rs[bb],     mu2a = s_mu[bb];
        float rs2b = s_rs[bb + 1], mu2b = s_mu[bb + 1];
        size_t Rb = ((size_t)f * BATCH + b0 + bb) * N_CLASS;
        {
            int c = g;
            g_Yh[Rb + c]           = __float2half_rn(fmaf(rs2a, a2[0] - mu2a * s_s2[c], s_d2[c]));
            g_Yh[Rb + N_CLASS + c] = __float2half_rn(fmaf(rs2b, a2[1] - mu2b * s_s2[c], s_d2[c]));
        }
        if (g < 2) {
            int c = g + 8;
            g_Yh[Rb + c]           = __float2half_rn(fmaf(rs2a, a2[2] - mu2a * s_s2[c], s_d2[c]));
            g_Yh[Rb + N_CLASS + c] = __float2half_rn(fmaf(rs2b, a2[3] - mu2b * s_s2[c], s_d2[c]));
        }
    }
}

// =====================================================================
__global__ void k4_reduce(float* __restrict__ out) {
    int i = blockIdx.x * 256 + threadIdx.x;   // half2 index
    if (i < BATCH * N_CLASS / 2) {
        float s0 = 0.f, s1 = 0.f;
#pragma unroll 4
        for (int f = 0; f < N_FOREST; f++) {
            __half2 v = *((const __half2*)(g_Yh + (size_t)f * (BATCH * N_CLASS)) + i);
            float2 fv = __half22float2(v);
            s0 += fv.x; s1 += fv.y;
        }
        out[2 * i]     = s0 * (1.f / N_FOREST);
        out[2 * i + 1] = s1 * (1.f / N_FOREST);
    }
}

// =====================================================================
extern "C" void kernel_launch(void* const* d_in, const int* in_sizes, int n_in,
                              void* d_out, int out_size) {
    const float* x     = (const float*)d_in[0];
    const float* w1    = (const float*)d_in[1];
    const float* b1    = (const float*)d_in[2];
    const int*   perm  = (const int*)  d_in[3];
    const float* gn1w  = (const float*)d_in[4];
    const float* gn1b  = (const float*)d_in[5];
    const float* c2w   = (const float*)d_in[6];
    const float* c2b   = (const float*)d_in[7];
    const float* gn2w  = (const float*)d_in[8];
    const float* gn2b  = (const float*)d_in[9];
    const float* c3w   = (const float*)d_in[10];
    const float* c3b   = (const float*)d_in[11];
    const int*   swr   = (const int*)  d_in[12];
    const float* E     = (const float*)d_in[13];
    const float* ln1w  = (const float*)d_in[14];
    const float* ln1b  = (const float*)d_in[15];
    const float* fc1w  = (const float*)d_in[16];
    const float* fc1b  = (const float*)d_in[17];
    const float* ln2w  = (const float*)d_in[18];
    const float* ln2b  = (const float*)d_in[19];
    const float* fc2w  = (const float*)d_in[20];
    const float* fc2b  = (const float*)d_in[21];
    float* out = (float*)d_out;

    cudaFuncSetAttribute(k23_forest_mlp, cudaFuncAttributeMaxDynamicSharedMemorySize, K23_SMEM);

    k0_transpose<<<(N_COL * BATCH) / 256, 256>>>(x);
    k_pre<<<(N_RODT * N_HID + 255) / 256, 256>>>(E, fc1w, ln1w, fc2w, ln2w);
    k_pre2<<<1, 128>>>(fc1w, fc1b, ln1b, fc2w, fc2b, ln2b);
    k1_rodt<<<dim3(N_RODT, BATCH / 1024), 256>>>(w1, b1, perm, gn1w, gn1b,
                                                 c2w, c2b, gn2w, gn2b, c3w, c3b);
    k23_forest_mlp<<<dim3(BATCH / 128, N_FOREST), 512, K23_SMEM>>>(swr);
    k4_reduce<<<(BATCH * N_CLASS / 2 + 255) / 256, 256>>>(out);
}

// round 14
// speedup vs baseline: 2.1883x; 1.0308x over previous
#include <cuda_runtime.h>
#include <cuda_fp16.h>
#include <cstdint>

// ---------------- problem constants ----------------
#define BATCH    4096
#define N_COL    100
#define N_COND   64
#define TOTAL    6400
#define N_RODT   1600
#define N_EST    160
#define N_FOREST 100
#define N_HID    128
#define N_CLASS  10
#define EPSV     1e-5f
#define SDH      136      // half stride per row (272B, 16B-aligned)

// ---------------- device scratch ----------------
__device__ float  g_xT  [N_COL * BATCH];
__device__ __half g_wTh [N_RODT * BATCH];     // fp16(exp(w)) — exp hoisted into k1
__device__ __half g_Ehf [N_RODT * N_HID];     // fp16(E)
__device__ __half g_W1hf[N_HID * N_HID];      // fp16(fc1w * ln1w) [d][o]
__device__ __half g_wc2h[N_HID * 16];         // fp16(fc2w * ln2w) [o][16] (10 used)
__device__ float  g_s1[N_HID], g_d1[N_HID];
__device__ float  g_s2[16],    g_d2[16];
__device__ __half g_Yh [(size_t)N_FOREST * BATCH * N_CLASS];   // per-forest logits fp16

__device__ __forceinline__ void cpasync16(uint32_t dst, const void* src) {
    asm volatile("cp.async.cg.shared.global [%0], [%1], 16;" :: "r"(dst), "l"(src));
}
#define CP_COMMIT asm volatile("cp.async.commit_group;")
#define CP_WAIT0  asm volatile("cp.async.wait_group 0;")

__device__ __forceinline__ float fast_sigmoid(float z) {
    float t;
    asm("tanh.approx.f32 %0, %1;" : "=f"(t) : "f"(z * 0.5f));
    return fmaf(0.5f, t, 0.5f);
}

// =====================================================================
__global__ void k0_transpose(const float* __restrict__ x) {
    int i = blockIdx.x * 256 + threadIdx.x;
    int c = i >> 12;
    int b = i & 4095;
    g_xT[i] = x[b * N_COL + c];
}

// =====================================================================
__global__ void k_pre(const float* __restrict__ E, const float* __restrict__ fc1w,
                      const float* __restrict__ ln1w, const float* __restrict__ fc2w,
                      const float* __restrict__ ln2w) {
    int i = blockIdx.x * 256 + threadIdx.x;
    if (i < N_RODT * N_HID) g_Ehf[i] = __float2half_rn(E[i]);
    if (i < N_HID * N_HID) {
        int d = i >> 7;
        g_W1hf[i] = __float2half_rn(fc1w[i] * ln1w[d]);
    }
    if (i < N_HID * 16) {
        int o = i >> 4, c = i & 15;
        g_wc2h[i] = __float2half_rn((c < 10) ? fc2w[o * 10 + c] * ln2w[o] : 0.f);
    }
}
__global__ void k_pre2(const float* __restrict__ fc1w, const float* __restrict__ fc1b,
                       const float* __restrict__ ln1b, const float* __restrict__ fc2w,
                       const float* __restrict__ fc2b, const float* __restrict__ ln2b) {
    int o = threadIdx.x;
    float ssum = 0.f, dsum = 0.f;
    for (int k = 0; k < 128; k++) {
        ssum += __half2float(g_W1hf[k * 128 + o]);
        dsum += fc1w[k * 128 + o] * ln1b[k];
    }
    g_s1[o] = ssum;
    g_d1[o] = dsum + fc1b[o];
    if (o < 10) {
        float s2 = 0.f, d2 = 0.f;
        for (int k = 0; k < 128; k++) {
            s2 += __half2float(g_wc2h[k * 16 + o]);
            d2 += ln2b[k] * fc2w[k * 10 + o];
        }
        g_s2[o] = s2;
        g_d2[o] = d2 + fc2b[o];
    } else if (o < 16) {
        g_s2[o] = 0.f; g_d2[o] = 0.f;
    }
}

// =====================================================================
// Kernel 1: condition gen + rODT scoring — 4 b's/thread; exp folded in,
// output fp16(exp(w)).
// =====================================================================
__global__ void __launch_bounds__(256, 4)
k1_rodt(const float* __restrict__ w1, const float* __restrict__ b1,
        const int*   __restrict__ perm,
        const float* __restrict__ gn1w, const float* __restrict__ gn1b,
        const float* __restrict__ c2w,  const float* __restrict__ c2b,
        const float* __restrict__ gn2w, const float* __restrict__ gn2b,
        const float* __restrict__ c3w,  const float* __restrict__ c3b) {
    int g   = blockIdx.x;
    int tid = threadIdx.x;
    __shared__ int   sc[4];
    __shared__ float sw1[4], sb1[4], sg1w[4], sg1b[4];
    __shared__ float sw2[16], sb2[4], sg2w[4], sg2b[4], sw3[4], sb3;
    if (tid < 4) {
        int t = 4 * g + tid;
        int p = perm[t];
        int c = p % N_COL;
        int j = p / N_COL;
        sc [tid] = c;
        sw1[tid] = w1[c * N_COND + j];
        sb1[tid] = b1[c * N_COND + j];
        sg1w[tid] = gn1w[t];  sg1b[tid] = gn1b[t];
        sb2 [tid] = c2b[t];
        sg2w[tid] = gn2w[t];  sg2b[tid] = gn2b[t];
        sw3 [tid] = c3w[g * 4 + tid];
    }
    if (tid < 16) sw2[tid] = c2w[g * 16 + tid];
    if (tid == 31) sb3 = c3b[g];
    __syncthreads();

    const int b = blockIdx.y * 1024 + tid * 4;
    float4 xv[4];
#pragma unroll
    for (int k = 0; k < 4; k++)
        xv[k] = *(const float4*)&g_xT[sc[k] * BATCH + b];

    float out[4];
#pragma unroll
    for (int j = 0; j < 4; j++) {
        float v[4];
#pragma unroll
        for (int k = 0; k < 4; k++) {
            float xval = (&xv[k].x)[j];
            float z = fmaf(xval, sw1[k], sb1[k]);
            v[k] = fast_sigmoid(z);
        }
        float mu = 0.25f * (v[0] + v[1] + v[2] + v[3]);
        float var = 0.f;
#pragma unroll
        for (int k = 0; k < 4; k++) { float d = v[k] - mu; var += d * d; }
        var *= 0.25f;
        float rs = rsqrtf(var + EPSV);
        float n[4];
#pragma unroll
        for (int k = 0; k < 4; k++) n[k] = fmaf((v[k] - mu) * rs, sg1w[k], sg1b[k]);
        float h[4];
#pragma unroll
        for (int o = 0; o < 4; o++) {
            float a = sb2[o];
#pragma unroll
            for (int k = 0; k < 4; k++) a = fmaf(n[k], sw2[k * 4 + o], a);
            h[o] = fmaxf(a, 0.f);
        }
        float mu2 = 0.25f * (h[0] + h[1] + h[2] + h[3]);
        float var2 = 0.f;
#pragma unroll
        for (int k = 0; k < 4; k++) { float d = h[k] - mu2; var2 += d * d; }
        var2 *= 0.25f;
        float rs2 = rsqrtf(var2 + EPSV);
        float wo = sb3;
#pragma unroll
        for (int k = 0; k < 4; k++)
            wo = fmaf(fmaf((h[k] - mu2) * rs2, sg2w[k], sg2b[k]), sw3[k], wo);
        out[j] = wo;
    }
    // store fp16(exp(w)) — identical value to what k23 used to compute
    __half2 e01 = __floats2half2_rn(__expf(out[0]), __expf(out[1]));
    __half2 e23 = __floats2half2_rn(__expf(out[2]), __expf(out[3]));
    uint2 pk;
    pk.x = *(uint32_t*)&e01;
    pk.y = *(uint32_t*)&e23;
    *(uint2*)&g_wTh[(size_t)g * BATCH + b] = pk;
}

// =====================================================================
// fp16 m16n8k16 mma + ldmatrix
// =====================================================================
__device__ __forceinline__ uint32_t smaddr(const void* p) {
    return (uint32_t)__cvta_generic_to_shared(p);
}
__device__ __forceinline__ void ldsm4t(uint32_t& r0, uint32_t& r1, uint32_t& r2, uint32_t& r3,
                                       uint32_t addr) {
    asm volatile("ldmatrix.sync.aligned.m8n8.x4.trans.shared.b16 {%0,%1,%2,%3}, [%4];"
                 : "=r"(r0), "=r"(r1), "=r"(r2), "=r"(r3) : "r"(addr));
}
__device__ __forceinline__ void ldsm2t(uint32_t& r0, uint32_t& r1, uint32_t addr) {
    asm volatile("ldmatrix.sync.aligned.m8n8.x2.trans.shared.b16 {%0,%1}, [%2];"
                 : "=r"(r0), "=r"(r1) : "r"(addr));
}
__device__ __forceinline__ void mma_f16(float* c, const uint32_t* a, const uint32_t* b) {
    asm volatile("mma.sync.aligned.m16n8k16.row.col.f32.f16.f16.f32 "
                 "{%0,%1,%2,%3}, {%4,%5,%6,%7}, {%8,%9}, {%0,%1,%2,%3};"
                 : "+f"(c[0]), "+f"(c[1]), "+f"(c[2]), "+f"(c[3])
                 : "r"(a[0]), "r"(a[1]), "r"(a[2]), "r"(a[3]), "r"(b[0]), "r"(b[1]));
}

template<int KSTEPS>
__device__ __forceinline__ void gemm_h(const __half* __restrict__ Asm,
                                       const __half* __restrict__ Bsm,
                                       int warp, int lane, float acc[2][4][4]) {
    const int M0 = (warp & 3) * 32, N0 = (warp >> 2) * 32;
    const int a_k = ((lane >> 4) << 3) + (lane & 7);
    const int a_m = ((lane >> 3) & 1) << 3;
    const int b_k = (((lane >> 3) & 1) << 3) + (lane & 7);
    const int b_n = (lane >> 4) << 3;
#pragma unroll
    for (int ks = 0; ks < KSTEPS; ks++) {
        const int K0 = ks * 16;
        uint32_t afr[2][4];
#pragma unroll
        for (int mt = 0; mt < 2; mt++) {
            uint32_t addr = smaddr(Asm + (K0 + a_k) * SDH + (M0 + mt * 16 + a_m));
            ldsm4t(afr[mt][0], afr[mt][1], afr[mt][2], afr[mt][3], addr);
        }
        uint32_t bfr[4][2];
#pragma unroll
        for (int np = 0; np < 2; np++) {
            uint32_t addr = smaddr(Bsm + (K0 + b_k) * SDH + (N0 + np * 16 + b_n));
            uint32_t r0, r1, r2, r3;
            ldsm4t(r0, r1, r2, r3, addr);
            bfr[np * 2][0] = r0;     bfr[np * 2][1] = r1;
            bfr[np * 2 + 1][0] = r2; bfr[np * 2 + 1][1] = r3;
        }
#pragma unroll
        for (int mt = 0; mt < 2; mt++)
#pragma unroll
            for (int nt = 0; nt < 4; nt++) mma_f16(acc[mt][nt], afr[mt], bfr[nt]);
    }
}

// =====================================================================
// k23: fused forest GEMM + MLP, fp16 everywhere; fc2 via mma. 2 blocks/SM.
// stage-P is now a pure gather (exp precomputed in k1).
// =====================================================================
#define OFF_WH0 (160 * SDH * 2)            // 43520
#define OFF_WH1 (OFF_WH0 + 80 * SDH * 2)   // 65280
#define K23_SMEM (OFF_WH1 + 80 * SDH * 2)  // 87040
__global__ void __launch_bounds__(512, 2) k23_forest_mlp(const int* __restrict__ swr) {
    extern __shared__ char sh[];
    __half* Ph  = (__half*)sh;
    __half* Wh0 = (__half*)(sh + OFF_WH0);
    __half* Wh1 = (__half*)(sh + OFF_WH1);

    __shared__ int   s_idx[160];
    __shared__ float s_invS[128];
    __shared__ float s_scratch[2048];          // s_part(16x128) OR redA(8x128)+redB(8x128)
    __shared__ float s_mu[128], s_rs[128];
    __shared__ float s_s1[128], s_d1[128];
    __shared__ __align__(16) __half s_wc2h[128 * 16];
    __shared__ float s_s2[16], s_d2[16];

    float* s_part = s_scratch;
    float* s_redA = s_scratch;
    float* s_redB = s_scratch + 1024;

    const int tid = threadIdx.x, lane = tid & 31, warp = tid >> 5;
    const int f = blockIdx.y;
    const int b0 = blockIdx.x * 128;

    if (tid < 160) s_idx[tid] = swr[f * N_EST + tid];
    __syncthreads();

    // ---- issue E half0 via cp.async ----
    {
        uint32_t wb0 = (uint32_t)__cvta_generic_to_shared(Wh0);
#pragma unroll
        for (int i = tid; i < 80 * 16; i += 512) {
            int e = i >> 4, q = i & 15;
            cpasync16(wb0 + e * (SDH * 2) + q * 16, g_Ehf + (size_t)s_idx[e] * N_HID + q * 8);
        }
        CP_COMMIT;
    }

    // ---- stage P: pure gather of fp16(exp(w)) + fused invS partials ----
    {
        float p0 = 0.f, p1 = 0.f, p2 = 0.f, p3 = 0.f;
        const int b4 = tid & 31;
#pragma unroll
        for (int j = 0; j < 10; j++) {
            int e = (tid >> 5) + 16 * j;
            uint2 pk = *(const uint2*)(g_wTh + (size_t)s_idx[e] * BATCH + b0 + b4 * 4);
            *(uint2*)(Ph + e * SDH + b4 * 4) = pk;
            float2 f01 = __half22float2(*(__half2*)&pk.x);
            float2 f23 = __half22float2(*(__half2*)&pk.y);
            p0 += f01.x; p1 += f01.y; p2 += f23.x; p3 += f23.y;
        }
        float* pp = s_part + warp * 128 + b4 * 4;
        pp[0] = p0; pp[1] = p1; pp[2] = p2; pp[3] = p3;
    }
    if (tid < 128) { s_s1[tid] = g_s1[tid]; s_d1[tid] = g_d1[tid]; }
    if (tid < 256) ((uint4*)s_wc2h)[tid] = ((const uint4*)g_wc2h)[tid];
    if (tid < 16) { s_s2[tid] = g_s2[tid]; s_d2[tid] = g_d2[tid]; }
    CP_WAIT0;
    __syncthreads();

    // ---- issue E half1 -> Wh1 ----
    {
        uint32_t wb1 = (uint32_t)__cvta_generic_to_shared(Wh1);
#pragma unroll
        for (int i = tid; i < 80 * 16; i += 512) {
            int e = i >> 4, q = i & 15;
            cpasync16(wb1 + e * (SDH * 2) + q * 16, g_Ehf + (size_t)s_idx[80 + e] * N_HID + q * 8);
        }
        CP_COMMIT;
    }

    // ---- invS finalize ----
    if (tid < 128) {
        float s = 0.f;
#pragma unroll
        for (int w = 0; w < 16; w++) s += s_part[w * 128 + tid];
        s_invS[tid] = 1.f / s;
    }

    // ---- GEMM A: K=160, two halves ----
    float acc[2][4][4];
#pragma unroll
    for (int mt = 0; mt < 2; mt++)
#pragma unroll
        for (int nt = 0; nt < 4; nt++)
#pragma unroll
            for (int r = 0; r < 4; r++) acc[mt][nt][r] = 0.f;
    gemm_h<5>(Wh0, Ph, warp, lane, acc);
    CP_WAIT0;
    __syncthreads();
    // prefetch W1' half0 into Wh0
    {
        uint32_t wb0 = (uint32_t)__cvta_generic_to_shared(Wh0);
#pragma unroll
        for (int i = tid; i < 64 * 16; i += 512) {
            int k = i >> 4, q = i & 15;
            cpasync16(wb0 + k * (SDH * 2) + q * 16, g_W1hf + k * N_HID + q * 8);
        }
        CP_COMMIT;
    }
    gemm_h<5>(Wh1, Ph + 80 * SDH, warp, lane, acc);
    __syncthreads();   // all P reads done before overwrite
    // prefetch W1' half1 into Wh1
    {
        uint32_t wb1 = (uint32_t)__cvta_generic_to_shared(Wh1);
#pragma unroll
        for (int i = tid; i < 64 * 16; i += 512) {
            int k = i >> 4, q = i & 15;
            cpasync16(wb1 + k * (SDH * 2) + q * 16, g_W1hf + (64 + k) * N_HID + q * 8);
        }
        CP_COMMIT;
    }
    // epilogue A: C~ = fp16(acc * invS) -> Ph rows 0..127
    {
        const int M0 = (warp & 3) * 32, N0 = (warp >> 2) * 32;
        const int g = lane >> 2, q2 = (lane & 3) * 2;
#pragma unroll
        for (int mt = 0; mt < 2; mt++)
#pragma unroll
            for (int nt = 0; nt < 4; nt++) {
                int row = M0 + mt * 16 + g, col = N0 + nt * 8 + q2;
                float i0 = s_invS[col], i1 = s_invS[col + 1];
                *(__half2*)(Ph + row * SDH + col) =
                    __floats2half2_rn(acc[mt][nt][0] * i0, acc[mt][nt][1] * i1);
                *(__half2*)(Ph + (row + 8) * SDH + col) =
                    __floats2half2_rn(acc[mt][nt][2] * i0, acc[mt][nt][3] * i1);
            }
    }
    CP_WAIT0;
    __syncthreads();

    // ---- stats1 (half2, 8-way row split) ----
    {
        const int c2 = (tid & 63) * 2, q = tid >> 6;
        float s0 = 0.f, s1v = 0.f, q0 = 0.f, q1 = 0.f;
#pragma unroll 4
        for (int r = 0; r < 16; r++) {
            float2 fv = __half22float2(*(__half2*)(Ph + (q * 16 + r) * SDH + c2));
            s0 += fv.x; s1v += fv.y;
            q0 = fmaf(fv.x, fv.x, q0); q1 = fmaf(fv.y, fv.y, q1);
        }
        s_redA[q * 128 + c2] = s0;  s_redA[q * 128 + c2 + 1] = s1v;
        s_redB[q * 128 + c2] = q0;  s_redB[q * 128 + c2 + 1] = q1;
    }
    __syncthreads();
    if (tid < 128) {
        float s = 0.f, s2 = 0.f;
#pragma unroll
        for (int w = 0; w < 8; w++) { s += s_redA[w * 128 + tid]; s2 += s_redB[w * 128 + tid]; }
        float mu = s * (1.f / 128.f);
        float var = fmaxf(s2 * (1.f / 128.f) - mu * mu, 0.f);
        s_mu[tid] = mu;
        s_rs[tid] = rsqrtf(var + EPSV);
    }
    __syncthreads();

    // ---- GEMM B: K=128, two halves ----
#pragma unroll
    for (int mt = 0; mt < 2; mt++)
#pragma unroll
        for (int nt = 0; nt < 4; nt++)
#pragma unroll
            for (int r = 0; r < 4; r++) acc[mt][nt][r] = 0.f;
    gemm_h<4>(Wh0, Ph, warp, lane, acc);
    gemm_h<4>(Wh1, Ph + 64 * SDH, warp, lane, acc);
    __syncthreads();   // all C~ reads done before overwrite

    // epilogue B: H = fp16(relu(rs*(G - mu*s1) + d1)) -> Ph rows 0..127
    {
        const int M0 = (warp & 3) * 32, N0 = (warp >> 2) * 32;
        const int g = lane >> 2, q2 = (lane & 3) * 2;
#pragma unroll
        for (int mt = 0; mt < 2; mt++)
#pragma unroll
            for (int nt = 0; nt < 4; nt++) {
                int row = M0 + mt * 16 + g, col = N0 + nt * 8 + q2;
                float s1a = s_s1[row], d1a = s_d1[row];
                float s1b = s_s1[row + 8], d1b = s_d1[row + 8];
                float mu0 = s_mu[col], rs0 = s_rs[col];
                float mu1 = s_mu[col + 1], rs1 = s_rs[col + 1];
                *(__half2*)(Ph + row * SDH + col) = __floats2half2_rn(
                    fmaxf(fmaf(rs0, acc[mt][nt][0] - mu0 * s1a, d1a), 0.f),
                    fmaxf(fmaf(rs1, acc[mt][nt][1] - mu1 * s1a, d1a), 0.f));
                *(__half2*)(Ph + (row + 8) * SDH + col) = __floats2half2_rn(
                    fmaxf(fmaf(rs0, acc[mt][nt][2] - mu0 * s1b, d1b), 0.f),
                    fmaxf(fmaf(rs1, acc[mt][nt][3] - mu1 * s1b, d1b), 0.f));
            }
    }
    __syncthreads();

    // ---- stats2 on fp16 H (half2) ----
    {
        const int c2 = (tid & 63) * 2, q = tid >> 6;
        float s0 = 0.f, s1v = 0.f, q0 = 0.f, q1 = 0.f;
#pragma unroll 4
        for (int r = 0; r < 16; r++) {
            float2 fv = __half22float2(*(__half2*)(Ph + (q * 16 + r) * SDH + c2));
            s0 += fv.x; s1v += fv.y;
            q0 = fmaf(fv.x, fv.x, q0); q1 = fmaf(fv.y, fv.y, q1);
        }
        s_redA[q * 128 + c2] = s0;  s_redA[q * 128 + c2 + 1] = s1v;
        s_redB[q * 128 + c2] = q0;  s_redB[q * 128 + c2 + 1] = q1;
    }
    __syncthreads();
    if (tid < 128) {
        float s = 0.f, s2 = 0.f;
#pragma unroll
        for (int w = 0; w < 8; w++) { s += s_redA[w * 128 + tid]; s2 += s_redB[w * 128 + tid]; }
        float mu = s * (1.f / 128.f);
        float var = fmaxf(s2 * (1.f / 128.f) - mu * mu, 0.f);
        s_mu[tid] = mu;
        s_rs[tid] = rsqrtf(var + EPSV);
    }
    __syncthreads();

    // ---- fc2 via mma: S^T[c=16][b=128] = wc2h^T H; LN2 folded epilogue ----
    {
        float a2[4] = {0.f, 0.f, 0.f, 0.f};
        const int N0 = warp * 8;
        const int a_k = ((lane >> 4) << 3) + (lane & 7);
        const int a_m = ((lane >> 3) & 1) << 3;
        const int b_k = lane & 15;
#pragma unroll
        for (int ks = 0; ks < 8; ks++) {
            const int K0 = ks * 16;
            uint32_t af[4];
            ldsm4t(af[0], af[1], af[2], af[3], smaddr(s_wc2h + (K0 + a_k) * 16 + a_m));
            uint32_t bf[2];
            ldsm2t(bf[0], bf[1], smaddr(Ph + (K0 + b_k) * SDH + N0));
            mma_f16(a2, af, bf);
        }
        const int g = lane >> 2, q2 = (lane & 3) * 2;
        const int bb = N0 + q2;
        float rs2a = s_rs[bb],     mu2a = s_mu[bb];
        float rs2b = s_rs[bb + 1], mu2b = s_mu[bb + 1];
        size_t Rb = ((size_t)f * BATCH + b0 + bb) * N_CLASS;
        {
            int c = g;
            g_Yh[Rb + c]           = __float2half_rn(fmaf(rs2a, a2[0] - mu2a * s_s2[c], s_d2[c]));
            g_Yh[Rb + N_CLASS + c] = __float2half_rn(fmaf(rs2b, a2[1] - mu2b * s_s2[c], s_d2[c]));
        }
        if (g < 2) {
            int c = g + 8;
            g_Yh[Rb + c]           = __float2half_rn(fmaf(rs2a, a2[2] - mu2a * s_s2[c], s_d2[c]));
            g_Yh[Rb + N_CLASS + c] = __float2half_rn(fmaf(rs2b, a2[3] - mu2b * s_s2[c], s_d2[c]));
        }
    }
}

// =====================================================================
__global__ void k4_reduce(float* __restrict__ out) {
    int i = blockIdx.x * 256 + threadIdx.x;   // half2 index
    if (i < BATCH * N_CLASS / 2) {
        float s0 = 0.f, s1 = 0.f;
#pragma unroll 4
        for (int f = 0; f < N_FOREST; f++) {
            __half2 v = *((const __half2*)(g_Yh + (size_t)f * (BATCH * N_CLASS)) + i);
            float2 fv = __half22float2(v);
            s0 += fv.x; s1 += fv.y;
        }
        out[2 * i]     = s0 * (1.f / N_FOREST);
        out[2 * i + 1] = s1 * (1.f / N_FOREST);
    }
}

// =====================================================================
extern "C" void kernel_launch(void* const* d_in, const int* in_sizes, int n_in,
                              void* d_out, int out_size) {
    const float* x     = (const float*)d_in[0];
    const float* w1    = (const float*)d_in[1];
    const float* b1    = (const float*)d_in[2];
    const int*   perm  = (const int*)  d_in[3];
    const float* gn1w  = (const float*)d_in[4];
    const float* gn1b  = (const float*)d_in[5];
    const float* c2w   = (const float*)d_in[6];
    const float* c2b   = (const float*)d_in[7];
    const float* gn2w  = (const float*)d_in[8];
    const float* gn2b  = (const float*)d_in[9];
    const float* c3w   = (const float*)d_in[10];
    const float* c3b   = (const float*)d_in[11];
    const int*   swr   = (const int*)  d_in[12];
    const float* E     = (const float*)d_in[13];
    const float* ln1w  = (const float*)d_in[14];
    const float* ln1b  = (const float*)d_in[15];
    const float* fc1w  = (const float*)d_in[16];
    const float* fc1b  = (const float*)d_in[17];
    const float* ln2w  = (const float*)d_in[18];
    const float* ln2b  = (const float*)d_in[19];
    const float* fc2w  = (const float*)d_in[20];
    const float* fc2b  = (const float*)d_in[21];
    float* out = (float*)d_out;

    cudaFuncSetAttribute(k23_forest_mlp, cudaFuncAttributeMaxDynamicSharedMemorySize, K23_SMEM);

    k0_transpose<<<(N_COL * BATCH) / 256, 256>>>(x);
    k_pre<<<(N_RODT * N_HID + 255) / 256, 256>>>(E, fc1w, ln1w, fc2w, ln2w);
    k_pre2<<<1, 128>>>(fc1w, fc1b, ln1b, fc2w, fc2b, ln2b);
    k1_rodt<<<dim3(N_RODT, BATCH / 1024), 256>>>(w1, b1, perm, gn1w, gn1b,
                                                 c2w, c2b, gn2w, gn2b, c3w, c3b);
    k23_forest_mlp<<<dim3(BATCH / 128, N_FOREST), 512, K23_SMEM>>>(swr);
    k4_reduce<<<(BATCH * N_CLASS / 2 + 255) / 256, 256>>>(out);
}

// round 15
// speedup vs baseline: 2.3352x; 1.0671x over previous
#include <cuda_runtime.h>
#include <cuda_fp16.h>
#include <cstdint>

// ---------------- problem constants ----------------
#define BATCH    4096
#define N_COL    100
#define N_COND   64
#define TOTAL    6400
#define N_RODT   1600
#define N_EST    160
#define N_FOREST 100
#define N_HID    128
#define N_CLASS  10
#define EPSV     1e-5f
#define SDH      136      // half stride per row (272B, 16B-aligned)

// ---------------- device scratch ----------------
__device__ float  g_xT  [N_COL * BATCH];
__device__ __half g_wTh [N_RODT * BATCH];     // fp16(exp(w)) — exp hoisted into k1
__device__ __half g_Ehf [N_RODT * N_HID];     // fp16(E)
__device__ __half g_W1hf[N_HID * N_HID];      // fp16(fc1w * ln1w) [d][o]
__device__ __half g_wc2h[N_HID * 16];         // fp16(fc2w * ln2w) [o][16] (10 used)
__device__ float  g_s1[N_HID], g_d1[N_HID];
__device__ float  g_s2[16],    g_d2[16];
__device__ __half g_Yh [(size_t)N_FOREST * BATCH * N_CLASS];   // per-forest logits fp16
__device__ float2 g_part[10 * (BATCH * N_CLASS / 2)];          // k4 stage-1 partials

__device__ __forceinline__ void cpasync16(uint32_t dst, const void* src) {
    asm volatile("cp.async.cg.shared.global [%0], [%1], 16;" :: "r"(dst), "l"(src));
}
#define CP_COMMIT asm volatile("cp.async.commit_group;")
#define CP_WAIT0  asm volatile("cp.async.wait_group 0;")

__device__ __forceinline__ float fast_sigmoid(float z) {
    float t;
    asm("tanh.approx.f32 %0, %1;" : "=f"(t) : "f"(z * 0.5f));
    return fmaf(0.5f, t, 0.5f);
}

// =====================================================================
__global__ void k0_transpose(const float* __restrict__ x) {
    int i = blockIdx.x * 256 + threadIdx.x;
    int c = i >> 12;
    int b = i & 4095;
    g_xT[i] = x[b * N_COL + c];
}

// =====================================================================
// k_pre: conversions + (extra block) bias/sum folds, all from raw inputs
// =====================================================================
__global__ void k_pre(const float* __restrict__ E, const float* __restrict__ fc1w,
                      const float* __restrict__ ln1w, const float* __restrict__ fc2w,
                      const float* __restrict__ ln2w,
                      const float* __restrict__ fc1b, const float* __restrict__ ln1b,
                      const float* __restrict__ fc2b, const float* __restrict__ ln2b) {
    if (blockIdx.x < 800) {
        int i = blockIdx.x * 256 + threadIdx.x;
        if (i < N_RODT * N_HID) g_Ehf[i] = __float2half_rn(E[i]);
        if (i < N_HID * N_HID) {
            int d = i >> 7;
            g_W1hf[i] = __float2half_rn(fc1w[i] * ln1w[d]);
        }
        if (i < N_HID * 16) {
            int o = i >> 4, c = i & 15;
            g_wc2h[i] = __float2half_rn((c < 10) ? fc2w[o * 10 + c] * ln2w[o] : 0.f);
        }
    } else {
        int o = threadIdx.x;
        if (o < 128) {
            float ssum = 0.f, dsum = 0.f;
            for (int k = 0; k < 128; k++) {
                ssum += __half2float(__float2half_rn(fc1w[k * 128 + o] * ln1w[k]));
                dsum += fc1w[k * 128 + o] * ln1b[k];
            }
            g_s1[o] = ssum;
            g_d1[o] = dsum + fc1b[o];
            if (o < 10) {
                float s2 = 0.f, d2 = 0.f;
                for (int k = 0; k < 128; k++) {
                    s2 += __half2float(__float2half_rn(fc2w[k * 10 + o] * ln2w[k]));
                    d2 += ln2b[k] * fc2w[k * 10 + o];
                }
                g_s2[o] = s2;
                g_d2[o] = d2 + fc2b[o];
            } else if (o < 16) {
                g_s2[o] = 0.f; g_d2[o] = 0.f;
            }
        }
    }
}

// =====================================================================
// Kernel 1: condition gen + rODT scoring — 4 b's/thread; exp folded in.
// =====================================================================
__global__ void __launch_bounds__(256, 4)
k1_rodt(const float* __restrict__ w1, const float* __restrict__ b1,
        const int*   __restrict__ perm,
        const float* __restrict__ gn1w, const float* __restrict__ gn1b,
        const float* __restrict__ c2w,  const float* __restrict__ c2b,
        const float* __restrict__ gn2w, const float* __restrict__ gn2b,
        const float* __restrict__ c3w,  const float* __restrict__ c3b) {
    int g   = blockIdx.x;
    int tid = threadIdx.x;
    __shared__ int   sc[4];
    __shared__ float sw1[4], sb1[4], sg1w[4], sg1b[4];
    __shared__ float sw2[16], sb2[4], sg2w[4], sg2b[4], sw3[4], sb3;
    if (tid < 4) {
        int t = 4 * g + tid;
        int p = perm[t];
        int c = p % N_COL;
        int j = p / N_COL;
        sc [tid] = c;
        sw1[tid] = w1[c * N_COND + j];
        sb1[tid] = b1[c * N_COND + j];
        sg1w[tid] = gn1w[t];  sg1b[tid] = gn1b[t];
        sb2 [tid] = c2b[t];
        sg2w[tid] = gn2w[t];  sg2b[tid] = gn2b[t];
        sw3 [tid] = c3w[g * 4 + tid];
    }
    if (tid < 16) sw2[tid] = c2w[g * 16 + tid];
    if (tid == 31) sb3 = c3b[g];
    __syncthreads();

    const int b = blockIdx.y * 1024 + tid * 4;
    float4 xv[4];
#pragma unroll
    for (int k = 0; k < 4; k++)
        xv[k] = *(const float4*)&g_xT[sc[k] * BATCH + b];

    float out[4];
#pragma unroll
    for (int j = 0; j < 4; j++) {
        float v[4];
#pragma unroll
        for (int k = 0; k < 4; k++) {
            float xval = (&xv[k].x)[j];
            float z = fmaf(xval, sw1[k], sb1[k]);
            v[k] = fast_sigmoid(z);
        }
        float mu = 0.25f * (v[0] + v[1] + v[2] + v[3]);
        float var = 0.f;
#pragma unroll
        for (int k = 0; k < 4; k++) { float d = v[k] - mu; var += d * d; }
        var *= 0.25f;
        float rs = rsqrtf(var + EPSV);
        float n[4];
#pragma unroll
        for (int k = 0; k < 4; k++) n[k] = fmaf((v[k] - mu) * rs, sg1w[k], sg1b[k]);
        float h[4];
#pragma unroll
        for (int o = 0; o < 4; o++) {
            float a = sb2[o];
#pragma unroll
            for (int k = 0; k < 4; k++) a = fmaf(n[k], sw2[k * 4 + o], a);
            h[o] = fmaxf(a, 0.f);
        }
        float mu2 = 0.25f * (h[0] + h[1] + h[2] + h[3]);
        float var2 = 0.f;
#pragma unroll
        for (int k = 0; k < 4; k++) { float d = h[k] - mu2; var2 += d * d; }
        var2 *= 0.25f;
        float rs2 = rsqrtf(var2 + EPSV);
        float wo = sb3;
#pragma unroll
        for (int k = 0; k < 4; k++)
            wo = fmaf(fmaf((h[k] - mu2) * rs2, sg2w[k], sg2b[k]), sw3[k], wo);
        out[j] = wo;
    }
    __half2 e01 = __floats2half2_rn(__expf(out[0]), __expf(out[1]));
    __half2 e23 = __floats2half2_rn(__expf(out[2]), __expf(out[3]));
    uint2 pk;
    pk.x = *(uint32_t*)&e01;
    pk.y = *(uint32_t*)&e23;
    *(uint2*)&g_wTh[(size_t)g * BATCH + b] = pk;
}

// =====================================================================
// fp16 m16n8k16 mma + ldmatrix
// =====================================================================
__device__ __forceinline__ uint32_t smaddr(const void* p) {
    return (uint32_t)__cvta_generic_to_shared(p);
}
__device__ __forceinline__ void ldsm4t(uint32_t& r0, uint32_t& r1, uint32_t& r2, uint32_t& r3,
                                       uint32_t addr) {
    asm volatile("ldmatrix.sync.aligned.m8n8.x4.trans.shared.b16 {%0,%1,%2,%3}, [%4];"
                 : "=r"(r0), "=r"(r1), "=r"(r2), "=r"(r3) : "r"(addr));
}
__device__ __forceinline__ void ldsm2t(uint32_t& r0, uint32_t& r1, uint32_t addr) {
    asm volatile("ldmatrix.sync.aligned.m8n8.x2.trans.shared.b16 {%0,%1}, [%2];"
                 : "=r"(r0), "=r"(r1) : "r"(addr));
}
__device__ __forceinline__ void mma_f16(float* c, const uint32_t* a, const uint32_t* b) {
    asm volatile("mma.sync.aligned.m16n8k16.row.col.f32.f16.f16.f32 "
                 "{%0,%1,%2,%3}, {%4,%5,%6,%7}, {%8,%9}, {%0,%1,%2,%3};"
                 : "+f"(c[0]), "+f"(c[1]), "+f"(c[2]), "+f"(c[3])
                 : "r"(a[0]), "r"(a[1]), "r"(a[2]), "r"(a[3]), "r"(b[0]), "r"(b[1]));
}

template<int KSTEPS>
__device__ __forceinline__ void gemm_h(const __half* __restrict__ Asm,
                                       const __half* __restrict__ Bsm,
                                       int warp, int lane, float acc[2][4][4]) {
    const int M0 = (warp & 3) * 32, N0 = (warp >> 2) * 32;
    const int a_k = ((lane >> 4) << 3) + (lane & 7);
    const int a_m = ((lane >> 3) & 1) << 3;
    const int b_k = (((lane >> 3) & 1) << 3) + (lane & 7);
    const int b_n = (lane >> 4) << 3;
#pragma unroll
    for (int ks = 0; ks < KSTEPS; ks++) {
        const int K0 = ks * 16;
        uint32_t afr[2][4];
#pragma unroll
        for (int mt = 0; mt < 2; mt++) {
            uint32_t addr = smaddr(Asm + (K0 + a_k) * SDH + (M0 + mt * 16 + a_m));
            ldsm4t(afr[mt][0], afr[mt][1], afr[mt][2], afr[mt][3], addr);
        }
        uint32_t bfr[4][2];
#pragma unroll
        for (int np = 0; np < 2; np++) {
            uint32_t addr = smaddr(Bsm + (K0 + b_k) * SDH + (N0 + np * 16 + b_n));
            uint32_t r0, r1, r2, r3;
            ldsm4t(r0, r1, r2, r3, addr);
            bfr[np * 2][0] = r0;     bfr[np * 2][1] = r1;
            bfr[np * 2 + 1][0] = r2; bfr[np * 2 + 1][1] = r3;
        }
#pragma unroll
        for (int mt = 0; mt < 2; mt++)
#pragma unroll
            for (int nt = 0; nt < 4; nt++) mma_f16(acc[mt][nt], afr[mt], bfr[nt]);
    }
}

// =====================================================================
// k23: fused forest GEMM + MLP; barrier-trimmed. 2 blocks/SM.
// =====================================================================
#define OFF_WH0 (160 * SDH * 2)            // 43520
#define OFF_WH1 (OFF_WH0 + 80 * SDH * 2)   // 65280
#define K23_SMEM (OFF_WH1 + 80 * SDH * 2)  // 87040
__global__ void __launch_bounds__(512, 2) k23_forest_mlp(const int* __restrict__ swr) {
    extern __shared__ char sh[];
    __half* Ph  = (__half*)sh;
    __half* Wh0 = (__half*)(sh + OFF_WH0);
    __half* Wh1 = (__half*)(sh + OFF_WH1);

    __shared__ int   s_idx[160];
    __shared__ float s_invS[128];
    __shared__ float s_scratch[2048];
    __shared__ float s_mu[128], s_rs[128];
    __shared__ float s_s1[128], s_d1[128];
    __shared__ __align__(16) __half s_wc2h[128 * 16];
    __shared__ float s_s2[16], s_d2[16];

    float* s_part = s_scratch;
    float* s_redA = s_scratch;
    float* s_redB = s_scratch + 1024;

    const int tid = threadIdx.x, lane = tid & 31, warp = tid >> 5;
    const int f = blockIdx.y;
    const int b0 = blockIdx.x * 128;

    if (tid < 160) s_idx[tid] = swr[f * N_EST + tid];
    __syncthreads();

    // ---- issue E half0 via cp.async ----
    {
        uint32_t wb0 = (uint32_t)__cvta_generic_to_shared(Wh0);
#pragma unroll
        for (int i = tid; i < 80 * 16; i += 512) {
            int e = i >> 4, q = i & 15;
            cpasync16(wb0 + e * (SDH * 2) + q * 16, g_Ehf + (size_t)s_idx[e] * N_HID + q * 8);
        }
        CP_COMMIT;
    }

    // ---- stage P: pure gather of fp16(exp(w)) + fused invS partials ----
    {
        float p0 = 0.f, p1 = 0.f, p2 = 0.f, p3 = 0.f;
        const int b4 = tid & 31;
#pragma unroll
        for (int j = 0; j < 10; j++) {
            int e = (tid >> 5) + 16 * j;
            uint2 pk = *(const uint2*)(g_wTh + (size_t)s_idx[e] * BATCH + b0 + b4 * 4);
            *(uint2*)(Ph + e * SDH + b4 * 4) = pk;
            float2 f01 = __half22float2(*(__half2*)&pk.x);
            float2 f23 = __half22float2(*(__half2*)&pk.y);
            p0 += f01.x; p1 += f01.y; p2 += f23.x; p3 += f23.y;
        }
        float* pp = s_part + warp * 128 + b4 * 4;
        pp[0] = p0; pp[1] = p1; pp[2] = p2; pp[3] = p3;
    }
    if (tid < 128) { s_s1[tid] = g_s1[tid]; s_d1[tid] = g_d1[tid]; }
    if (tid < 256) ((uint4*)s_wc2h)[tid] = ((const uint4*)g_wc2h)[tid];
    if (tid < 16) { s_s2[tid] = g_s2[tid]; s_d2[tid] = g_d2[tid]; }
    CP_WAIT0;
    __syncthreads();

    // ---- issue E half1 -> Wh1 ----
    {
        uint32_t wb1 = (uint32_t)__cvta_generic_to_shared(Wh1);
#pragma unroll
        for (int i = tid; i < 80 * 16; i += 512) {
            int e = i >> 4, q = i & 15;
            cpasync16(wb1 + e * (SDH * 2) + q * 16, g_Ehf + (size_t)s_idx[80 + e] * N_HID + q * 8);
        }
        CP_COMMIT;
    }

    // ---- invS finalize ----
    if (tid < 128) {
        float s = 0.f;
#pragma unroll
        for (int w = 0; w < 16; w++) s += s_part[w * 128 + tid];
        s_invS[tid] = 1.f / s;
    }

    // ---- GEMM A: K=160, two halves ----
    float acc[2][4][4];
#pragma unroll
    for (int mt = 0; mt < 2; mt++)
#pragma unroll
        for (int nt = 0; nt < 4; nt++)
#pragma unroll
            for (int r = 0; r < 4; r++) acc[mt][nt][r] = 0.f;
    gemm_h<5>(Wh0, Ph, warp, lane, acc);
    CP_WAIT0;
    __syncthreads();
    // prefetch W1' half0 into Wh0
    {
        uint32_t wb0 = (uint32_t)__cvta_generic_to_shared(Wh0);
#pragma unroll
        for (int i = tid; i < 64 * 16; i += 512) {
            int k = i >> 4, q = i & 15;
            cpasync16(wb0 + k * (SDH * 2) + q * 16, g_W1hf + k * N_HID + q * 8);
        }
        CP_COMMIT;
    }
    gemm_h<5>(Wh1, Ph + 80 * SDH, warp, lane, acc);
    __syncthreads();   // all P reads done before overwrite
    // prefetch W1' half1 into Wh1
    {
        uint32_t wb1 = (uint32_t)__cvta_generic_to_shared(Wh1);
#pragma unroll
        for (int i = tid; i < 64 * 16; i += 512) {
            int k = i >> 4, q = i & 15;
            cpasync16(wb1 + k * (SDH * 2) + q * 16, g_W1hf + (64 + k) * N_HID + q * 8);
        }
        CP_COMMIT;
    }
    // epilogue A: C~ = fp16(acc * invS) -> Ph rows 0..127
    {
        const int M0 = (warp & 3) * 32, N0 = (warp >> 2) * 32;
        const int g = lane >> 2, q2 = (lane & 3) * 2;
#pragma unroll
        for (int mt = 0; mt < 2; mt++)
#pragma unroll
            for (int nt = 0; nt < 4; nt++) {
                int row = M0 + mt * 16 + g, col = N0 + nt * 8 + q2;
                float i0 = s_invS[col], i1 = s_invS[col + 1];
                *(__half2*)(Ph + row * SDH + col) =
                    __floats2half2_rn(acc[mt][nt][0] * i0, acc[mt][nt][1] * i1);
                *(__half2*)(Ph + (row + 8) * SDH + col) =
                    __floats2half2_rn(acc[mt][nt][2] * i0, acc[mt][nt][3] * i1);
            }
    }
    CP_WAIT0;
    __syncthreads();

    // ---- stats1 pass (half2, 8-way row split) ----
    {
        const int c2 = (tid & 63) * 2, q = tid >> 6;
        float s0 = 0.f, s1v = 0.f, q0 = 0.f, q1 = 0.f;
#pragma unroll 4
        for (int r = 0; r < 16; r++) {
            float2 fv = __half22float2(*(__half2*)(Ph + (q * 16 + r) * SDH + c2));
            s0 += fv.x; s1v += fv.y;
            q0 = fmaf(fv.x, fv.x, q0); q1 = fmaf(fv.y, fv.y, q1);
        }
        s_redA[q * 128 + c2] = s0;  s_redA[q * 128 + c2 + 1] = s1v;
        s_redB[q * 128 + c2] = q0;  s_redB[q * 128 + c2 + 1] = q1;
    }
    __syncthreads();
    // finalize (tid<128) overlapped with GEMM B — GEMM B touches neither
    // s_mu/s_rs nor s_redA/B; the post-GEMM-B barrier orders these writes.
    if (tid < 128) {
        float s = 0.f, s2 = 0.f;
#pragma unroll
        for (int w = 0; w < 8; w++) { s += s_redA[w * 128 + tid]; s2 += s_redB[w * 128 + tid]; }
        float mu = s * (1.f / 128.f);
        float var = fmaxf(s2 * (1.f / 128.f) - mu * mu, 0.f);
        s_mu[tid] = mu;
        s_rs[tid] = rsqrtf(var + EPSV);
    }

    // ---- GEMM B: K=128, two halves ----
#pragma unroll
    for (int mt = 0; mt < 2; mt++)
#pragma unroll
        for (int nt = 0; nt < 4; nt++)
#pragma unroll
            for (int r = 0; r < 4; r++) acc[mt][nt][r] = 0.f;
    gemm_h<4>(Wh0, Ph, warp, lane, acc);
    gemm_h<4>(Wh1, Ph + 64 * SDH, warp, lane, acc);
    __syncthreads();   // orders C~ reads before overwrite AND stats1 finalize

    // epilogue B: H = fp16(relu(rs*(G - mu*s1) + d1)) -> Ph rows 0..127
    {
        const int M0 = (warp & 3) * 32, N0 = (warp >> 2) * 32;
        const int g = lane >> 2, q2 = (lane & 3) * 2;
#pragma unroll
        for (int mt = 0; mt < 2; mt++)
#pragma unroll
            for (int nt = 0; nt < 4; nt++) {
                int row = M0 + mt * 16 + g, col = N0 + nt * 8 + q2;
                float s1a = s_s1[row], d1a = s_d1[row];
                float s1b = s_s1[row + 8], d1b = s_d1[row + 8];
                float mu0 = s_mu[col], rs0 = s_rs[col];
                float mu1 = s_mu[col + 1], rs1 = s_rs[col + 1];
                *(__half2*)(Ph + row * SDH + col) = __floats2half2_rn(
                    fmaxf(fmaf(rs0, acc[mt][nt][0] - mu0 * s1a, d1a), 0.f),
                    fmaxf(fmaf(rs1, acc[mt][nt][1] - mu1 * s1a, d1a), 0.f));
                *(__half2*)(Ph + (row + 8) * SDH + col) = __floats2half2_rn(
                    fmaxf(fmaf(rs0, acc[mt][nt][2] - mu0 * s1b, d1b), 0.f),
                    fmaxf(fmaf(rs1, acc[mt][nt][3] - mu1 * s1b, d1b), 0.f));
            }
    }
    __syncthreads();

    // ---- stats2 pass on fp16 H ----
    {
        const int c2 = (tid & 63) * 2, q = tid >> 6;
        float s0 = 0.f, s1v = 0.f, q0 = 0.f, q1 = 0.f;
#pragma unroll 4
        for (int r = 0; r < 16; r++) {
            float2 fv = __half22float2(*(__half2*)(Ph + (q * 16 + r) * SDH + c2));
            s0 += fv.x; s1v += fv.y;
            q0 = fmaf(fv.x, fv.x, q0); q1 = fmaf(fv.y, fv.y, q1);
        }
        s_redA[q * 128 + c2] = s0;  s_redA[q * 128 + c2 + 1] = s1v;
        s_redB[q * 128 + c2] = q0;  s_redB[q * 128 + c2 + 1] = q1;
    }
    __syncthreads();
    // finalize (tid<128) overlapped with the fc2 mma stream below.
    if (tid < 128) {
        float s = 0.f, s2 = 0.f;
#pragma unroll
        for (int w = 0; w < 8; w++) { s += s_redA[w * 128 + tid]; s2 += s_redB[w * 128 + tid]; }
        float mu = s * (1.f / 128.f);
        float var = fmaxf(s2 * (1.f / 128.f) - mu * mu, 0.f);
        s_mu[tid] = mu;
        s_rs[tid] = rsqrtf(var + EPSV);
    }

    // ---- fc2 via mma (H stable since epilogue-B barrier) ----
    {
        float a2[4] = {0.f, 0.f, 0.f, 0.f};
        const int N0 = warp * 8;
        const int a_k = ((lane >> 4) << 3) + (lane & 7);
        const int a_m = ((lane >> 3) & 1) << 3;
        const int b_k = lane & 15;
#pragma unroll
        for (int ks = 0; ks < 8; ks++) {
            const int K0 = ks * 16;
            uint32_t af[4];
            ldsm4t(af[0], af[1], af[2], af[3], smaddr(s_wc2h + (K0 + a_k) * 16 + a_m));
            uint32_t bf[2];
            ldsm2t(bf[0], bf[1], smaddr(Ph + (K0 + b_k) * SDH + N0));
            mma_f16(a2, af, bf);
        }
        __syncthreads();   // stats2 finalize visible before epilogue reads s_mu/s_rs
        const int g = lane >> 2, q2 = (lane & 3) * 2;
        const int bb = N0 + q2;
        float rs2a = s_rs[bb],     mu2a = s_mu[bb];
        float rs2b = s_rs[bb + 1], mu2b = s_mu[bb + 1];
        size_t Rb = ((size_t)f * BATCH + b0 + bb) * N_CLASS;
        {
            int c = g;
            g_Yh[Rb + c]           = __float2half_rn(fmaf(rs2a, a2[0] - mu2a * s_s2[c], s_d2[c]));
            g_Yh[Rb + N_CLASS + c] = __float2half_rn(fmaf(rs2b, a2[1] - mu2b * s_s2[c], s_d2[c]));
        }
        if (g < 2) {
            int c = g + 8;
            g_Yh[Rb + c]           = __float2half_rn(fmaf(rs2a, a2[2] - mu2a * s_s2[c], s_d2[c]));
            g_Yh[Rb + N_CLASS + c] = __float2half_rn(fmaf(rs2b, a2[3] - mu2b * s_s2[c], s_d2[c]));
        }
    }
}

// =====================================================================
// k4 two-stage: stage1 sums 10 forests per chunk; stage2 combines 10 chunks.
// =====================================================================
__global__ void k4a(void) {
    int i = blockIdx.x * 256 + threadIdx.x;   // half2 index, 20480 total
    int c = blockIdx.y;                        // chunk 0..9
    if (i < BATCH * N_CLASS / 2) {
        float s0 = 0.f, s1 = 0.f;
#pragma unroll
        for (int j = 0; j < 10; j++) {
            int fidx = c * 10 + j;
            __half2 v = *((const __half2*)(g_Yh + (size_t)fidx * (BATCH * N_CLASS)) + i);
            float2 fv = __half22float2(v);
            s0 += fv.x; s1 += fv.y;
        }
        g_part[(size_t)c * (BATCH * N_CLASS / 2) + i] = make_float2(s0, s1);
    }
}
__global__ void k4b(float* __restrict__ out) {
    int i = blockIdx.x * 256 + threadIdx.x;
    if (i < BATCH * N_CLASS / 2) {
        float s0 = 0.f, s1 = 0.f;
#pragma unroll
        for (int c = 0; c < 10; c++) {
            float2 p = g_part[(size_t)c * (BATCH * N_CLASS / 2) + i];
            s0 += p.x; s1 += p.y;
        }
        out[2 * i]     = s0 * (1.f / N_FOREST);
        out[2 * i + 1] = s1 * (1.f / N_FOREST);
    }
}

// =====================================================================
extern "C" void kernel_launch(void* const* d_in, const int* in_sizes, int n_in,
                              void* d_out, int out_size) {
    const float* x     = (const float*)d_in[0];
    const float* w1    = (const float*)d_in[1];
    const float* b1    = (const float*)d_in[2];
    const int*   perm  = (const int*)  d_in[3];
    const float* gn1w  = (const float*)d_in[4];
    const float* gn1b  = (const float*)d_in[5];
    const float* c2w   = (const float*)d_in[6];
    const float* c2b   = (const float*)d_in[7];
    const float* gn2w  = (const float*)d_in[8];
    const float* gn2b  = (const float*)d_in[9];
    const float* c3w   = (const float*)d_in[10];
    const float* c3b   = (const float*)d_in[11];
    const int*   swr   = (const int*)  d_in[12];
    const float* E     = (const float*)d_in[13];
    const float* ln1w  = (const float*)d_in[14];
    const float* ln1b  = (const float*)d_in[15];
    const float* fc1w  = (const float*)d_in[16];
    const float* fc1b  = (const float*)d_in[17];
    const float* ln2w  = (const float*)d_in[18];
    const float* ln2b  = (const float*)d_in[19];
    const float* fc2w  = (const float*)d_in[20];
    const float* fc2b  = (const float*)d_in[21];
    float* out = (float*)d_out;

    cudaFuncSetAttribute(k23_forest_mlp, cudaFuncAttributeMaxDynamicSharedMemorySize, K23_SMEM);

    k0_transpose<<<(N_COL * BATCH) / 256, 256>>>(x);
    k_pre<<<801, 256>>>(E, fc1w, ln1w, fc2w, ln2w, fc1b, ln1b, fc2b, ln2b);
    k1_rodt<<<dim3(N_RODT, BATCH / 1024), 256>>>(w1, b1, perm, gn1w, gn1b,
                                                 c2w, c2b, gn2w, gn2b, c3w, c3b);
    k23_forest_mlp<<<dim3(BATCH / 128, N_FOREST), 512, K23_SMEM>>>(swr);
    k4a<<<dim3(BATCH * N_CLASS / 2 / 256, 10), 256>>>();
    k4b<<<BATCH * N_CLASS / 2 / 256, 256>>>(out);
}

// round 16
// speedup vs baseline: 2.3392x; 1.0017x over previous
#include <cuda_runtime.h>
#include <cuda_fp16.h>
#include <cstdint>

// ---------------- problem constants ----------------
#define BATCH    4096
#define N_COL    100
#define N_COND   64
#define TOTAL    6400
#define N_RODT   1600
#define N_EST    160
#define N_FOREST 100
#define N_HID    128
#define N_CLASS  10
#define EPSV     1e-5f
#define SDH      136      // half stride per row (272B, 16B-aligned)

// ---------------- device scratch ----------------
__device__ float  g_xT  [N_COL * BATCH];
__device__ __half g_wTh [N_RODT * BATCH];     // fp16(exp(w))
__device__ __half g_Ehf [N_RODT * N_HID];     // fp16(E)
__device__ __half g_W1hf[N_HID * N_HID];      // fp16(fc1w * ln1w) [d][o]
__device__ __half g_wc2h[N_HID * 16];         // fp16(fc2w * ln2w) [o][16]
__device__ float  g_s1[N_HID], g_d1[N_HID];
__device__ float  g_s2[16],    g_d2[16];
__device__ __half g_Yh [(size_t)N_FOREST * BATCH * N_CLASS];
__device__ float2 g_part[10 * (BATCH * N_CLASS / 2)];

__device__ __forceinline__ void cpasync16(uint32_t dst, const void* src) {
    asm volatile("cp.async.cg.shared.global [%0], [%1], 16;" :: "r"(dst), "l"(src));
}
#define CP_COMMIT asm volatile("cp.async.commit_group;")
#define CP_WAIT0  asm volatile("cp.async.wait_group 0;")

__device__ __forceinline__ float fast_sigmoid(float z) {
    float t;
    asm("tanh.approx.f32 %0, %1;" : "=f"(t) : "f"(z * 0.5f));
    return fmaf(0.5f, t, 0.5f);
}

// =====================================================================
__global__ void k0_transpose(const float* __restrict__ x) {
    int i = blockIdx.x * 256 + threadIdx.x;
    int c = i >> 12;
    int b = i & 4095;
    g_xT[i] = x[b * N_COL + c];
}

// =====================================================================
__global__ void k_pre(const float* __restrict__ E, const float* __restrict__ fc1w,
                      const float* __restrict__ ln1w, const float* __restrict__ fc2w,
                      const float* __restrict__ ln2w,
                      const float* __restrict__ fc1b, const float* __restrict__ ln1b,
                      const float* __restrict__ fc2b, const float* __restrict__ ln2b) {
    if (blockIdx.x < 800) {
        int i = blockIdx.x * 256 + threadIdx.x;
        if (i < N_RODT * N_HID) g_Ehf[i] = __float2half_rn(E[i]);
        if (i < N_HID * N_HID) {
            int d = i >> 7;
            g_W1hf[i] = __float2half_rn(fc1w[i] * ln1w[d]);
        }
        if (i < N_HID * 16) {
            int o = i >> 4, c = i & 15;
            g_wc2h[i] = __float2half_rn((c < 10) ? fc2w[o * 10 + c] * ln2w[o] : 0.f);
        }
    } else {
        int o = threadIdx.x;
        if (o < 128) {
            float ssum = 0.f, dsum = 0.f;
            for (int k = 0; k < 128; k++) {
                ssum += __half2float(__float2half_rn(fc1w[k * 128 + o] * ln1w[k]));
                dsum += fc1w[k * 128 + o] * ln1b[k];
            }
            g_s1[o] = ssum;
            g_d1[o] = dsum + fc1b[o];
            if (o < 10) {
                float s2 = 0.f, d2 = 0.f;
                for (int k = 0; k < 128; k++) {
                    s2 += __half2float(__float2half_rn(fc2w[k * 10 + o] * ln2w[k]));
                    d2 += ln2b[k] * fc2w[k * 10 + o];
                }
                g_s2[o] = s2;
                g_d2[o] = d2 + fc2b[o];
            } else if (o < 16) {
                g_s2[o] = 0.f; g_d2[o] = 0.f;
            }
        }
    }
}

// =====================================================================
// Kernel 1
// =====================================================================
__global__ void __launch_bounds__(256, 4)
k1_rodt(const float* __restrict__ w1, const float* __restrict__ b1,
        const int*   __restrict__ perm,
        const float* __restrict__ gn1w, const float* __restrict__ gn1b,
        const float* __restrict__ c2w,  const float* __restrict__ c2b,
        const float* __restrict__ gn2w, const float* __restrict__ gn2b,
        const float* __restrict__ c3w,  const float* __restrict__ c3b) {
    int g   = blockIdx.x;
    int tid = threadIdx.x;
    __shared__ int   sc[4];
    __shared__ float sw1[4], sb1[4], sg1w[4], sg1b[4];
    __shared__ float sw2[16], sb2[4], sg2w[4], sg2b[4], sw3[4], sb3;
    if (tid < 4) {
        int t = 4 * g + tid;
        int p = perm[t];
        int c = p % N_COL;
        int j = p / N_COL;
        sc [tid] = c;
        sw1[tid] = w1[c * N_COND + j];
        sb1[tid] = b1[c * N_COND + j];
        sg1w[tid] = gn1w[t];  sg1b[tid] = gn1b[t];
        sb2 [tid] = c2b[t];
        sg2w[tid] = gn2w[t];  sg2b[tid] = gn2b[t];
        sw3 [tid] = c3w[g * 4 + tid];
    }
    if (tid < 16) sw2[tid] = c2w[g * 16 + tid];
    if (tid == 31) sb3 = c3b[g];
    __syncthreads();

    const int b = blockIdx.y * 1024 + tid * 4;
    float4 xv[4];
#pragma unroll
    for (int k = 0; k < 4; k++)
        xv[k] = *(const float4*)&g_xT[sc[k] * BATCH + b];

    float out[4];
#pragma unroll
    for (int j = 0; j < 4; j++) {
        float v[4];
#pragma unroll
        for (int k = 0; k < 4; k++) {
            float xval = (&xv[k].x)[j];
            float z = fmaf(xval, sw1[k], sb1[k]);
            v[k] = fast_sigmoid(z);
        }
        float mu = 0.25f * (v[0] + v[1] + v[2] + v[3]);
        float var = 0.f;
#pragma unroll
        for (int k = 0; k < 4; k++) { float d = v[k] - mu; var += d * d; }
        var *= 0.25f;
        float rs = rsqrtf(var + EPSV);
        float n[4];
#pragma unroll
        for (int k = 0; k < 4; k++) n[k] = fmaf((v[k] - mu) * rs, sg1w[k], sg1b[k]);
        float h[4];
#pragma unroll
        for (int o = 0; o < 4; o++) {
            float a = sb2[o];
#pragma unroll
            for (int k = 0; k < 4; k++) a = fmaf(n[k], sw2[k * 4 + o], a);
            h[o] = fmaxf(a, 0.f);
        }
        float mu2 = 0.25f * (h[0] + h[1] + h[2] + h[3]);
        float var2 = 0.f;
#pragma unroll
        for (int k = 0; k < 4; k++) { float d = h[k] - mu2; var2 += d * d; }
        var2 *= 0.25f;
        float rs2 = rsqrtf(var2 + EPSV);
        float wo = sb3;
#pragma unroll
        for (int k = 0; k < 4; k++)
            wo = fmaf(fmaf((h[k] - mu2) * rs2, sg2w[k], sg2b[k]), sw3[k], wo);
        out[j] = wo;
    }
    __half2 e01 = __floats2half2_rn(__expf(out[0]), __expf(out[1]));
    __half2 e23 = __floats2half2_rn(__expf(out[2]), __expf(out[3]));
    uint2 pk;
    pk.x = *(uint32_t*)&e01;
    pk.y = *(uint32_t*)&e23;
    *(uint2*)&g_wTh[(size_t)g * BATCH + b] = pk;
}

// =====================================================================
// fp16 m16n8k16 mma + ldmatrix
// =====================================================================
__device__ __forceinline__ uint32_t smaddr(const void* p) {
    return (uint32_t)__cvta_generic_to_shared(p);
}
__device__ __forceinline__ void ldsm4t(uint32_t& r0, uint32_t& r1, uint32_t& r2, uint32_t& r3,
                                       uint32_t addr) {
    asm volatile("ldmatrix.sync.aligned.m8n8.x4.trans.shared.b16 {%0,%1,%2,%3}, [%4];"
                 : "=r"(r0), "=r"(r1), "=r"(r2), "=r"(r3) : "r"(addr));
}
__device__ __forceinline__ void mma_f16(float* c, const uint32_t* a, const uint32_t* b) {
    asm volatile("mma.sync.aligned.m16n8k16.row.col.f32.f16.f16.f32 "
                 "{%0,%1,%2,%3}, {%4,%5,%6,%7}, {%8,%9}, {%0,%1,%2,%3};"
                 : "+f"(c[0]), "+f"(c[1]), "+f"(c[2]), "+f"(c[3])
                 : "r"(a[0]), "r"(a[1]), "r"(a[2]), "r"(a[3]), "r"(b[0]), "r"(b[1]));
}

// 8 warps, 32x64 warp tiles over 128x128 (wm=warp&3, wn=warp>>2).
template<int KSTEPS>
__device__ __forceinline__ void gemm_h(const __half* __restrict__ Asm,
                                       const __half* __restrict__ Bsm,
                                       int warp, int lane, float acc[2][8][4]) {
    const int M0 = (warp & 3) * 32, N0 = (warp >> 2) * 64;
    const int a_k = ((lane >> 4) << 3) + (lane & 7);
    const int a_m = ((lane >> 3) & 1) << 3;
    const int b_k = lane & 15;
    const int b_n = (lane >> 4) << 3;
#pragma unroll
    for (int ks = 0; ks < KSTEPS; ks++) {
        const int K0 = ks * 16;
        uint32_t afr[2][4];
#pragma unroll
        for (int mt = 0; mt < 2; mt++) {
            uint32_t addr = smaddr(Asm + (K0 + a_k) * SDH + (M0 + mt * 16 + a_m));
            ldsm4t(afr[mt][0], afr[mt][1], afr[mt][2], afr[mt][3], addr);
        }
        uint32_t bfr[8][2];
#pragma unroll
        for (int np = 0; np < 4; np++) {
            uint32_t addr = smaddr(Bsm + (K0 + b_k) * SDH + (N0 + np * 16 + b_n));
            uint32_t r0, r1, r2, r3;
            ldsm4t(r0, r1, r2, r3, addr);
            bfr[np * 2][0] = r0;     bfr[np * 2][1] = r1;
            bfr[np * 2 + 1][0] = r2; bfr[np * 2 + 1][1] = r3;
        }
#pragma unroll
        for (int mt = 0; mt < 2; mt++)
#pragma unroll
            for (int nt = 0; nt < 8; nt++) mma_f16(acc[mt][nt], afr[mt], bfr[nt]);
    }
}

// =====================================================================
// k23: 256 threads, 8 warps with 32x64 tiles (25% less ldsm traffic).
// =====================================================================
#define OFF_WH0 (160 * SDH * 2)            // 43520
#define OFF_WH1 (OFF_WH0 + 80 * SDH * 2)   // 65280
#define K23_SMEM (OFF_WH1 + 80 * SDH * 2)  // 87040
__global__ void __launch_bounds__(256, 2) k23_forest_mlp(const int* __restrict__ swr) {
    extern __shared__ char sh[];
    __half* Ph  = (__half*)sh;
    __half* Wh0 = (__half*)(sh + OFF_WH0);
    __half* Wh1 = (__half*)(sh + OFF_WH1);

    __shared__ int   s_idx[160];
    __shared__ float s_invS[128];
    __shared__ float s_scratch[1024];          // s_part[8][128] OR redA[4][128]+redB[4][128]
    __shared__ float s_mu[128], s_rs[128];
    __shared__ float s_s1[128], s_d1[128];
    __shared__ __align__(16) __half s_wc2h[128 * 16];
    __shared__ float s_s2[16], s_d2[16];

    float* s_part = s_scratch;
    float* s_redA = s_scratch;
    float* s_redB = s_scratch + 512;

    const int tid = threadIdx.x, lane = tid & 31, warp = tid >> 5;
    const int f = blockIdx.y;
    const int b0 = blockIdx.x * 128;

    if (tid < 160) s_idx[tid] = swr[f * N_EST + tid];
    __syncthreads();

    // ---- issue E half0 via cp.async ----
    {
        uint32_t wb0 = (uint32_t)__cvta_generic_to_shared(Wh0);
#pragma unroll
        for (int i = tid; i < 80 * 16; i += 256) {
            int e = i >> 4, q = i & 15;
            cpasync16(wb0 + e * (SDH * 2) + q * 16, g_Ehf + (size_t)s_idx[e] * N_HID + q * 8);
        }
        CP_COMMIT;
    }

    // ---- stage P: gather fp16(exp(w)) + fused invS partials ----
    {
        float p0 = 0.f, p1 = 0.f, p2 = 0.f, p3 = 0.f;
        const int b4 = tid & 31;
#pragma unroll
        for (int j = 0; j < 20; j++) {
            int e = (tid >> 5) + 8 * j;
            uint2 pk = *(const uint2*)(g_wTh + (size_t)s_idx[e] * BATCH + b0 + b4 * 4);
            *(uint2*)(Ph + e * SDH + b4 * 4) = pk;
            float2 f01 = __half22float2(*(__half2*)&pk.x);
            float2 f23 = __half22float2(*(__half2*)&pk.y);
            p0 += f01.x; p1 += f01.y; p2 += f23.x; p3 += f23.y;
        }
        float* pp = s_part + warp * 128 + b4 * 4;
        pp[0] = p0; pp[1] = p1; pp[2] = p2; pp[3] = p3;
    }
    if (tid < 128) { s_s1[tid] = g_s1[tid]; s_d1[tid] = g_d1[tid]; }
    ((uint4*)s_wc2h)[tid] = ((const uint4*)g_wc2h)[tid];
    if (tid < 16) { s_s2[tid] = g_s2[tid]; s_d2[tid] = g_d2[tid]; }
    CP_WAIT0;
    __syncthreads();

    // ---- issue E half1 -> Wh1 ----
    {
        uint32_t wb1 = (uint32_t)__cvta_generic_to_shared(Wh1);
#pragma unroll
        for (int i = tid; i < 80 * 16; i += 256) {
            int e = i >> 4, q = i & 15;
            cpasync16(wb1 + e * (SDH * 2) + q * 16, g_Ehf + (size_t)s_idx[80 + e] * N_HID + q * 8);
        }
        CP_COMMIT;
    }

    // ---- invS finalize ----
    if (tid < 128) {
        float s = 0.f;
#pragma unroll
        for (int w = 0; w < 8; w++) s += s_part[w * 128 + tid];
        s_invS[tid] = 1.f / s;
    }

    // ---- GEMM A: K=160, two halves ----
    float acc[2][8][4];
#pragma unroll
    for (int mt = 0; mt < 2; mt++)
#pragma unroll
        for (int nt = 0; nt < 8; nt++)
#pragma unroll
            for (int r = 0; r < 4; r++) acc[mt][nt][r] = 0.f;
    gemm_h<5>(Wh0, Ph, warp, lane, acc);
    CP_WAIT0;
    __syncthreads();
    // prefetch W1' half0 into Wh0
    {
        uint32_t wb0 = (uint32_t)__cvta_generic_to_shared(Wh0);
#pragma unroll
        for (int i = tid; i < 64 * 16; i += 256) {
            int k = i >> 4, q = i & 15;
            cpasync16(wb0 + k * (SDH * 2) + q * 16, g_W1hf + k * N_HID + q * 8);
        }
        CP_COMMIT;
    }
    gemm_h<5>(Wh1, Ph + 80 * SDH, warp, lane, acc);
    __syncthreads();   // all P reads done before overwrite
    // prefetch W1' half1 into Wh1
    {
        uint32_t wb1 = (uint32_t)__cvta_generic_to_shared(Wh1);
#pragma unroll
        for (int i = tid; i < 64 * 16; i += 256) {
            int k = i >> 4, q = i & 15;
            cpasync16(wb1 + k * (SDH * 2) + q * 16, g_W1hf + (64 + k) * N_HID + q * 8);
        }
        CP_COMMIT;
    }
    // epilogue A: C~ = fp16(acc * invS) -> Ph rows 0..127
    {
        const int M0 = (warp & 3) * 32, N0 = (warp >> 2) * 64;
        const int g = lane >> 2, q2 = (lane & 3) * 2;
#pragma unroll
        for (int mt = 0; mt < 2; mt++)
#pragma unroll
            for (int nt = 0; nt < 8; nt++) {
                int row = M0 + mt * 16 + g, col = N0 + nt * 8 + q2;
                float i0 = s_invS[col], i1 = s_invS[col + 1];
                *(__half2*)(Ph + row * SDH + col) =
                    __floats2half2_rn(acc[mt][nt][0] * i0, acc[mt][nt][1] * i1);
                *(__half2*)(Ph + (row + 8) * SDH + col) =
                    __floats2half2_rn(acc[mt][nt][2] * i0, acc[mt][nt][3] * i1);
            }
    }
    CP_WAIT0;
    __syncthreads();

    // ---- stats1 pass (half2, 4-way row split) ----
    {
        const int c2 = (tid & 63) * 2, q = tid >> 6;
        float s0 = 0.f, s1v = 0.f, q0 = 0.f, q1 = 0.f;
#pragma unroll 4
        for (int r = 0; r < 32; r++) {
            float2 fv = __half22float2(*(__half2*)(Ph + (q * 32 + r) * SDH + c2));
            s0 += fv.x; s1v += fv.y;
            q0 = fmaf(fv.x, fv.x, q0); q1 = fmaf(fv.y, fv.y, q1);
        }
        s_redA[q * 128 + c2] = s0;  s_redA[q * 128 + c2 + 1] = s1v;
        s_redB[q * 128 + c2] = q0;  s_redB[q * 128 + c2 + 1] = q1;
    }
    __syncthreads();
    // finalize overlapped with GEMM B (post-GEMM-B barrier orders it)
    if (tid < 128) {
        float s = 0.f, s2 = 0.f;
#pragma unroll
        for (int w = 0; w < 4; w++) { s += s_redA[w * 128 + tid]; s2 += s_redB[w * 128 + tid]; }
        float mu = s * (1.f / 128.f);
        float var = fmaxf(s2 * (1.f / 128.f) - mu * mu, 0.f);
        s_mu[tid] = mu;
        s_rs[tid] = rsqrtf(var + EPSV);
    }

    // ---- GEMM B: K=128, two halves ----
#pragma unroll
    for (int mt = 0; mt < 2; mt++)
#pragma unroll
        for (int nt = 0; nt < 8; nt++)
#pragma unroll
            for (int r = 0; r < 4; r++) acc[mt][nt][r] = 0.f;
    gemm_h<4>(Wh0, Ph, warp, lane, acc);
    gemm_h<4>(Wh1, Ph + 64 * SDH, warp, lane, acc);
    __syncthreads();

    // epilogue B: H = fp16(relu(rs*(G - mu*s1) + d1)) -> Ph rows 0..127
    {
        const int M0 = (warp & 3) * 32, N0 = (warp >> 2) * 64;
        const int g = lane >> 2, q2 = (lane & 3) * 2;
#pragma unroll
        for (int mt = 0; mt < 2; mt++)
#pragma unroll
            for (int nt = 0; nt < 8; nt++) {
                int row = M0 + mt * 16 + g, col = N0 + nt * 8 + q2;
                float s1a = s_s1[row], d1a = s_d1[row];
                float s1b = s_s1[row + 8], d1b = s_d1[row + 8];
                float mu0 = s_mu[col], rs0 = s_rs[col];
                float mu1 = s_mu[col + 1], rs1 = s_rs[col + 1];
                *(__half2*)(Ph + row * SDH + col) = __floats2half2_rn(
                    fmaxf(fmaf(rs0, acc[mt][nt][0] - mu0 * s1a, d1a), 0.f),
                    fmaxf(fmaf(rs1, acc[mt][nt][1] - mu1 * s1a, d1a), 0.f));
                *(__half2*)(Ph + (row + 8) * SDH + col) = __floats2half2_rn(
                    fmaxf(fmaf(rs0, acc[mt][nt][2] - mu0 * s1b, d1b), 0.f),
                    fmaxf(fmaf(rs1, acc[mt][nt][3] - mu1 * s1b, d1b), 0.f));
            }
    }
    __syncthreads();

    // ---- stats2 pass on fp16 H ----
    {
        const int c2 = (tid & 63) * 2, q = tid >> 6;
        float s0 = 0.f, s1v = 0.f, q0 = 0.f, q1 = 0.f;
#pragma unroll 4
        for (int r = 0; r < 32; r++) {
            float2 fv = __half22float2(*(__half2*)(Ph + (q * 32 + r) * SDH + c2));
            s0 += fv.x; s1v += fv.y;
            q0 = fmaf(fv.x, fv.x, q0); q1 = fmaf(fv.y, fv.y, q1);
        }
        s_redA[q * 128 + c2] = s0;  s_redA[q * 128 + c2 + 1] = s1v;
        s_redB[q * 128 + c2] = q0;  s_redB[q * 128 + c2 + 1] = q1;
    }
    __syncthreads();
    // finalize overlapped with the fc2 mma stream
    if (tid < 128) {
        float s = 0.f, s2 = 0.f;
#pragma unroll
        for (int w = 0; w < 4; w++) { s += s_redA[w * 128 + tid]; s2 += s_redB[w * 128 + tid]; }
        float mu = s * (1.f / 128.f);
        float var = fmaxf(s2 * (1.f / 128.f) - mu * mu, 0.f);
        s_mu[tid] = mu;
        s_rs[tid] = rsqrtf(var + EPSV);
    }

    // ---- fc2 via mma: warp covers 16 b-cols; LN2 folded ----
    {
        float a2[2][4];
#pragma unroll
        for (int n = 0; n < 2; n++)
#pragma unroll
            for (int r = 0; r < 4; r++) a2[n][r] = 0.f;
        const int N0 = warp * 16;
        const int a_k = ((lane >> 4) << 3) + (lane & 7);
        const int a_m = ((lane >> 3) & 1) << 3;
        const int b_k = lane & 15;
        const int b_n = (lane >> 4) << 3;
#pragma unroll
        for (int ks = 0; ks < 8; ks++) {
            const int K0 = ks * 16;
            uint32_t af[4];
            ldsm4t(af[0], af[1], af[2], af[3], smaddr(s_wc2h + (K0 + a_k) * 16 + a_m));
            uint32_t r0, r1, r2, r3;
            ldsm4t(r0, r1, r2, r3, smaddr(Ph + (K0 + b_k) * SDH + N0 + b_n));
            uint32_t bf0[2] = {r0, r1}, bf1[2] = {r2, r3};
            mma_f16(a2[0], af, bf0);
            mma_f16(a2[1], af, bf1);
        }
        __syncthreads();   // stats2 finalize visible
        const int g = lane >> 2, q2 = (lane & 3) * 2;
#pragma unroll
        for (int n = 0; n < 2; n++) {
            const int bb = N0 + n * 8 + q2;
            float rs2a = s_rs[bb],     mu2a = s_mu[bb];
            float rs2b = s_rs[bb + 1], mu2b = s_mu[bb + 1];
            size_t Rb = ((size_t)f * BATCH + b0 + bb) * N_CLASS;
            {
                int c = g;
                g_Yh[Rb + c]           = __float2half_rn(fmaf(rs2a, a2[n][0] - mu2a * s_s2[c], s_d2[c]));
                g_Yh[Rb + N_CLASS + c] = __float2half_rn(fmaf(rs2b, a2[n][1] - mu2b * s_s2[c], s_d2[c]));
            }
            if (g < 2) {
                int c = g + 8;
                g_Yh[Rb + c]           = __float2half_rn(fmaf(rs2a, a2[n][2] - mu2a * s_s2[c], s_d2[c]));
                g_Yh[Rb + N_CLASS + c] = __float2half_rn(fmaf(rs2b, a2[n][3] - mu2b * s_s2[c], s_d2[c]));
            }
        }
    }
}

// =====================================================================
// k4 two-stage
// =====================================================================
__global__ void k4a(void) {
    int i = blockIdx.x * 256 + threadIdx.x;
    int c = blockIdx.y;
    if (i < BATCH * N_CLASS / 2) {
        float s0 = 0.f, s1 = 0.f;
#pragma unroll
        for (int j = 0; j < 10; j++) {
            int fidx = c * 10 + j;
            __half2 v = *((const __half2*)(g_Yh + (size_t)fidx * (BATCH * N_CLASS)) + i);
            float2 fv = __half22float2(v);
            s0 += fv.x; s1 += fv.y;
        }
        g_part[(size_t)c * (BATCH * N_CLASS / 2) + i] = make_float2(s0, s1);
    }
}
__global__ void k4b(float* __restrict__ out) {
    int i = blockIdx.x * 256 + threadIdx.x;
    if (i < BATCH * N_CLASS / 2) {
        float s0 = 0.f, s1 = 0.f;
#pragma unroll
        for (int c = 0; c < 10; c++) {
            float2 p = g_part[(size_t)c * (BATCH * N_CLASS / 2) + i];
            s0 += p.x; s1 += p.y;
        }
        out[2 * i]     = s0 * (1.f / N_FOREST);
        out[2 * i + 1] = s1 * (1.f / N_FOREST);
    }
}

// =====================================================================
extern "C" void kernel_launch(void* const* d_in, const int* in_sizes, int n_in,
                              void* d_out, int out_size) {
    const float* x     = (const float*)d_in[0];
    const float* w1    = (const float*)d_in[1];
    const float* b1    = (const float*)d_in[2];
    const int*   perm  = (const int*)  d_in[3];
    const float* gn1w  = (const float*)d_in[4];
    const float* gn1b  = (const float*)d_in[5];
    const float* c2w   = (const float*)d_in[6];
    const float* c2b   = (const float*)d_in[7];
    const float* gn2w  = (const float*)d_in[8];
    const float* gn2b  = (const float*)d_in[9];
    const float* c3w   = (const float*)d_in[10];
    const float* c3b   = (const float*)d_in[11];
    const int*   swr   = (const int*)  d_in[12];
    const float* E     = (const float*)d_in[13];
    const float* ln1w  = (const float*)d_in[14];
    const float* ln1b  = (const float*)d_in[15];
    const float* fc1w  = (const float*)d_in[16];
    const float* fc1b  = (const float*)d_in[17];
    const float* ln2w  = (const float*)d_in[18];
    const float* ln2b  = (const float*)d_in[19];
    const float* fc2w  = (const float*)d_in[20];
    const float* fc2b  = (const float*)d_in[21];
    float* out = (float*)d_out;

    cudaFuncSetAttribute(k23_forest_mlp, cudaFuncAttributeMaxDynamicSharedMemorySize, K23_SMEM);

    k0_transpose<<<(N_COL * BATCH) / 256, 256>>>(x);
    k_pre<<<801, 256>>>(E, fc1w, ln1w, fc2w, ln2w, fc1b, ln1b, fc2b, ln2b);
    k1_rodt<<<dim3(N_RODT, BATCH / 1024), 256>>>(w1, b1, perm, gn1w, gn1b,
                                                 c2w, c2b, gn2w, gn2b, c3w, c3b);
    k23_forest_mlp<<<dim3(BATCH / 128, N_FOREST), 256, K23_SMEM>>>(swr);
    k4a<<<dim3(BATCH * N_CLASS / 2 / 256, 10), 256>>>();
    k4b<<<BATCH * N_CLASS / 2 / 256, 256>>>(out);
}